// round 12
// baseline (speedup 1.0000x reference)
#include <cuda_runtime.h>
#include <cuda_bf16.h>
#include <cstdint>

// Problem constants (fixed shapes)
#define B_  4
#define T_  2048
#define D_  1024
#define H_  4
#define DK_ 256
#define DV_ 512
#define M_  (B_ * T_)        // 8192 rows
#define NKV (H_ * DK_)       // 1024
#define NV  (H_ * DV_)       // 2048
#define C_   64              // chunk length
#define NC_  32              // chunks per sequence
#define NCH  (B_ * H_ * NC_) // 512 chunk instances

typedef unsigned long long ull;

// ---------------------------------------------------------------------------
// Scratch (device globals; no dynamic allocation allowed)
// ---------------------------------------------------------------------------
__device__ float g_q[(size_t)M_ * NKV];
__device__ float g_k[(size_t)M_ * NKV];
__device__ float g_v[(size_t)M_ * NV];
__device__ float g_beta[(size_t)M_ * H_];
__device__ float g_o[(size_t)M_ * NV];
// chunked-scan intermediates
__device__ float g_mlt[(size_t)NCH * C_ * C_];   // [cIdx][i][j]  strict tril
__device__ float g_Uv [(size_t)NCH * C_ * DV_];  // [cIdx][i][dv] fp32
// split-bf16 chunkscan operands (written by prep1)
__device__ __nv_bfloat16 g_cWh [(size_t)NCH * C_ * DK_];  // [cIdx][i][kk]
__device__ __nv_bfloat16 g_cWl [(size_t)NCH * C_ * DK_];
__device__ __nv_bfloat16 g_cQh [(size_t)NCH * C_ * DK_];  // [cIdx][i][kk]
__device__ __nv_bfloat16 g_cQl [(size_t)NCH * C_ * DK_];
__device__ __nv_bfloat16 g_cKth[(size_t)NCH * DK_ * C_];  // [cIdx][kk][i]
__device__ __nv_bfloat16 g_cKtl[(size_t)NCH * DK_ * C_];
__device__ __nv_bfloat16 g_cPh [(size_t)NCH * C_ * C_];   // [cIdx][i][j]
__device__ __nv_bfloat16 g_cPl [(size_t)NCH * C_ * C_];
// bf16 split operands for projection GEMMs
__device__ __nv_bfloat16 g_nh[(size_t)M_ * D_];
__device__ __nv_bfloat16 g_nl[(size_t)M_ * D_];
__device__ __nv_bfloat16 g_oh[(size_t)M_ * NV];
__device__ __nv_bfloat16 g_ol[(size_t)M_ * NV];
__device__ __nv_bfloat16 g_Wqt_h[(size_t)NKV * D_];
__device__ __nv_bfloat16 g_Wqt_l[(size_t)NKV * D_];
__device__ __nv_bfloat16 g_Wkt_h[(size_t)NKV * D_];
__device__ __nv_bfloat16 g_Wkt_l[(size_t)NKV * D_];
__device__ __nv_bfloat16 g_Wvt_h[(size_t)NV * D_];
__device__ __nv_bfloat16 g_Wvt_l[(size_t)NV * D_];
__device__ __nv_bfloat16 g_Wot_h[(size_t)D_ * NV];
__device__ __nv_bfloat16 g_Wot_l[(size_t)D_ * NV];

// ---------------------------------------------------------------------------
// f32x2 packed-FMA helpers (prep kernels)
// ---------------------------------------------------------------------------
__device__ __forceinline__ ull pack2(float x, float y) {
    ull r; asm("mov.b64 %0, {%1, %2};" : "=l"(r) : "f"(x), "f"(y)); return r;
}
__device__ __forceinline__ void unpack2(ull v, float& x, float& y) {
    asm("mov.b64 {%0, %1}, %2;" : "=f"(x), "=f"(y) : "l"(v));
}
__device__ __forceinline__ void ffma2(ull& d, ull a, ull b) {
    asm("fma.rn.f32x2 %0, %1, %2, %0;" : "+l"(d) : "l"(a), "l"(b));
}
__device__ __forceinline__ void mma4x4p(ull (&acc)[4][2], const float4 a4,
                                        const ull b0, const ull b1) {
    ull a;
    a = pack2(a4.x, a4.x); ffma2(acc[0][0], a, b0); ffma2(acc[0][1], a, b1);
    a = pack2(a4.y, a4.y); ffma2(acc[1][0], a, b0); ffma2(acc[1][1], a, b1);
    a = pack2(a4.z, a4.z); ffma2(acc[2][0], a, b0); ffma2(acc[2][1], a, b1);
    a = pack2(a4.w, a4.w); ffma2(acc[3][0], a, b0); ffma2(acc[3][1], a, b1);
}
__device__ __forceinline__ void unp4x4(const ull (&acc)[4][2], float (&o)[4][4]) {
    #pragma unroll
    for (int r = 0; r < 4; ++r) {
        unpack2(acc[r][0], o[r][0], o[r][1]);
        unpack2(acc[r][1], o[r][2], o[r][3]);
    }
}

__device__ __forceinline__ float sigmoidf_(float x) { return 1.0f / (1.0f + __expf(-x)); }
__device__ __forceinline__ float siluf_(float x)    { return x * sigmoidf_(x); }

// split pair (a,b) fp32 -> hi bf16x2 (as u32) + lo bf16x2 (as u32)
__device__ __forceinline__ void split2(float a, float b, uint32_t& hi, uint32_t& lo) {
    __nv_bfloat162 h, l;
    h.x = __float2bfloat16(a); h.y = __float2bfloat16(b);
    l.x = __float2bfloat16(a - __bfloat162float(h.x));
    l.y = __float2bfloat16(b - __bfloat162float(h.y));
    hi = *(uint32_t*)&h; lo = *(uint32_t*)&l;
}

__device__ __forceinline__ void split_store4(const float4 v,
                                             __nv_bfloat16* __restrict__ hp,
                                             __nv_bfloat16* __restrict__ lp,
                                             size_t idx) {
    uint32_t h0, l0, h1, l1;
    split2(v.x, v.y, h0, l0);
    split2(v.z, v.w, h1, l1);
    *(uint32_t*)(hp + idx)     = h0;
    *(uint32_t*)(hp + idx + 2) = h1;
    *(uint32_t*)(lp + idx)     = l0;
    *(uint32_t*)(lp + idx + 2) = l1;
}

// ---------------------------------------------------------------------------
// mma.sync helpers (arch-portable HMMA)
// ---------------------------------------------------------------------------
__device__ __forceinline__ uint32_t smem_u32(const void* p) {
    uint32_t a;
    asm("{ .reg .u64 t; cvta.to.shared.u64 t, %1; cvt.u32.u64 %0, t; }" : "=r"(a) : "l"(p));
    return a;
}
__device__ __forceinline__ void ldsm4(uint32_t* r, uint32_t addr) {
    asm volatile("ldmatrix.sync.aligned.m8n8.x4.shared.b16 {%0,%1,%2,%3}, [%4];"
        : "=r"(r[0]), "=r"(r[1]), "=r"(r[2]), "=r"(r[3]) : "r"(addr));
}
__device__ __forceinline__ void ldsm4t(uint32_t* r, uint32_t addr) {
    asm volatile("ldmatrix.sync.aligned.m8n8.x4.trans.shared.b16 {%0,%1,%2,%3}, [%4];"
        : "=r"(r[0]), "=r"(r[1]), "=r"(r[2]), "=r"(r[3]) : "r"(addr));
}
__device__ __forceinline__ void mma16816(float* c, const uint32_t* a, const uint32_t* b) {
    asm volatile(
        "mma.sync.aligned.m16n8k16.row.col.f32.bf16.bf16.f32 "
        "{%0,%1,%2,%3}, {%4,%5,%6,%7}, {%8,%9}, {%0,%1,%2,%3};"
        : "+f"(c[0]), "+f"(c[1]), "+f"(c[2]), "+f"(c[3])
        : "r"(a[0]), "r"(a[1]), "r"(a[2]), "r"(a[3]), "r"(b[0]), "r"(b[1]));
}

// 64-col bf16 tile swizzle: rows of 128B, 8 chunks of 16B, chunk ^ (row&7)
__device__ __forceinline__ uint32_t swz(int row, int ch) {
    return (uint32_t)((row << 7) + ((ch ^ (row & 7)) << 4));
}
// byte offset of bf16 element (row, col), col even
__device__ __forceinline__ uint32_t swzb(int row, int col) {
    return (uint32_t)((row << 7) + ((((col >> 3) ^ (row & 7))) << 4) + ((col & 7) << 1));
}
// 32-col bf16 tile swizzle: rows of 64B, 4 chunks of 16B
__device__ __forceinline__ int xr32(int row) { return (row & 3) ^ ((row >> 2) & 3); }
__device__ __forceinline__ uint32_t swz32(int row, int ch) {
    return (uint32_t)((row << 6) + ((ch ^ xr32(row)) << 4));
}
__device__ __forceinline__ uint32_t swzb32(int row, int col) {
    return (uint32_t)((row << 6) + (((col >> 3) ^ xr32(row)) << 4) + ((col & 7) << 1));
}

// ---------------------------------------------------------------------------
// 1) LayerNorm -> g_nh/g_nl (bf16 split) + fused beta = sigmoid(normed @ Wb)
// ---------------------------------------------------------------------------
__global__ void __launch_bounds__(256) ln_kernel(const float* __restrict__ x,
                                                 const float* __restrict__ w,
                                                 const float* __restrict__ b,
                                                 const float* __restrict__ Wb) {
    const int row = blockIdx.x;
    const int tid = threadIdx.x;
    const float4 v = ((const float4*)(x + (size_t)row * D_))[tid];

    float s  = v.x + v.y + v.z + v.w;
    float s2 = v.x * v.x + v.y * v.y + v.z * v.z + v.w * v.w;
    #pragma unroll
    for (int off = 16; off > 0; off >>= 1) {
        s  += __shfl_xor_sync(0xffffffffu, s,  off);
        s2 += __shfl_xor_sync(0xffffffffu, s2, off);
    }
    __shared__ float sh[16];
    __shared__ float bsh[32];
    const int wid = tid >> 5, lane = tid & 31;
    if (lane == 0) { sh[wid] = s; sh[8 + wid] = s2; }
    __syncthreads();
    float ts = 0.f, ts2 = 0.f;
    #pragma unroll
    for (int i = 0; i < 8; ++i) { ts += sh[i]; ts2 += sh[8 + i]; }

    const float mean = ts * (1.0f / D_);
    const float var  = ts2 * (1.0f / D_) - mean * mean;
    const float rstd = rsqrtf(var + 1e-5f);

    const float4 wv = ((const float4*)w)[tid];
    const float4 bv = ((const float4*)b)[tid];
    float4 o;
    o.x = (v.x - mean) * rstd * wv.x + bv.x;
    o.y = (v.y - mean) * rstd * wv.y + bv.y;
    o.z = (v.z - mean) * rstd * wv.z + bv.z;
    o.w = (v.w - mean) * rstd * wv.w + bv.w;
    const size_t base = (size_t)row * D_;
    split_store4(o, g_nh, g_nl, base + (size_t)tid * 4);

    // fused beta: partial dot of normed row with Wb[:,0..3]
    float a0, a1, a2, a3;
    {
        const float4 w0 = ((const float4*)Wb)[tid * 4 + 0];
        const float4 w1 = ((const float4*)Wb)[tid * 4 + 1];
        const float4 w2 = ((const float4*)Wb)[tid * 4 + 2];
        const float4 w3 = ((const float4*)Wb)[tid * 4 + 3];
        a0 = o.x * w0.x + o.y * w1.x + o.z * w2.x + o.w * w3.x;
        a1 = o.x * w0.y + o.y * w1.y + o.z * w2.y + o.w * w3.y;
        a2 = o.x * w0.z + o.y * w1.z + o.z * w2.z + o.w * w3.z;
        a3 = o.x * w0.w + o.y * w1.w + o.z * w2.w + o.w * w3.w;
    }
    #pragma unroll
    for (int off = 16; off > 0; off >>= 1) {
        a0 += __shfl_xor_sync(0xffffffffu, a0, off);
        a1 += __shfl_xor_sync(0xffffffffu, a1, off);
        a2 += __shfl_xor_sync(0xffffffffu, a2, off);
        a3 += __shfl_xor_sync(0xffffffffu, a3, off);
    }
    if (lane == 0) {
        bsh[wid * 4 + 0] = a0; bsh[wid * 4 + 1] = a1;
        bsh[wid * 4 + 2] = a2; bsh[wid * 4 + 3] = a3;
    }
    __syncthreads();
    if (tid == 0) {
        float t0 = 0, t1 = 0, t2 = 0, t3 = 0;
        #pragma unroll
        for (int wq = 0; wq < 8; ++wq) {
            t0 += bsh[wq * 4 + 0]; t1 += bsh[wq * 4 + 1];
            t2 += bsh[wq * 4 + 2]; t3 += bsh[wq * 4 + 3];
        }
        *(float4*)&g_beta[(size_t)row * 4] =
            make_float4(sigmoidf_(t0), sigmoidf_(t1), sigmoidf_(t2), sigmoidf_(t3));
    }
}

// ---------------------------------------------------------------------------
// 1b) weight transpose + bf16 split
// ---------------------------------------------------------------------------
__global__ void __launch_bounds__(256) wtrans_kernel(const float* __restrict__ W,
                                                     __nv_bfloat16* __restrict__ Th,
                                                     __nv_bfloat16* __restrict__ Tl,
                                                     int K, int N) {
    __shared__ float tile[32][33];
    const int tx = threadIdx.x & 31, ty = threadIdx.x >> 5;
    const int k0 = blockIdx.y * 32, n0 = blockIdx.x * 32;
    #pragma unroll
    for (int i = 0; i < 32; i += 8)
        tile[ty + i][tx] = W[(size_t)(k0 + ty + i) * N + n0 + tx];
    __syncthreads();
    #pragma unroll
    for (int i = 0; i < 32; i += 8) {
        const float v = tile[tx][ty + i];
        const size_t oi = (size_t)(n0 + ty + i) * K + k0 + tx;
        const __nv_bfloat16 h = __float2bfloat16(v);
        Th[oi] = h;
        Tl[oi] = __float2bfloat16(v - __bfloat162float(h));
    }
}

// ---------------------------------------------------------------------------
// 2) HMMA GEMM (R6 proven: register-prefetch double-buffer)
// ---------------------------------------------------------------------------
#define MG_STAGE 65536
#define MG_SMEM  (2 * MG_STAGE)

__global__ void __launch_bounds__(256, 1)
mma_gemm(const __nv_bfloat16* __restrict__ Ah, const __nv_bfloat16* __restrict__ Al,
         const __nv_bfloat16* __restrict__ Bh, const __nv_bfloat16* __restrict__ Bl,
         float* __restrict__ C, const float* __restrict__ resid,
         int N, int K, int do_silu) {
    extern __shared__ char smx[];
    const uint32_t sbase = smem_u32(smx);
    const int tid = threadIdx.x;
    const int lane = tid & 31;
    const int wid = tid >> 5;
    const int wm = wid >> 2;
    const int wn = wid & 3;
    const int m0w = wm * 64, n0w = wn * 32;

    const size_t bm = (size_t)blockIdx.y * 128;
    const size_t bn = (size_t)blockIdx.x * 128;
    const __nv_bfloat16* pAh = Ah + bm * K;
    const __nv_bfloat16* pAl = Al + bm * K;
    const __nv_bfloat16* pBh = Bh + bn * K;
    const __nv_bfloat16* pBl = Bl + bn * K;

    {
        char* stg = smx;
        #pragma unroll
        for (int p = 0; p < 4; ++p) {
            const int c = tid + (p << 8);
            const int row = c >> 3, ch = c & 7;
            const size_t gi = (size_t)row * K + (ch << 3);
            const int off = (row << 7) + (((ch ^ (row & 7))) << 4);
            *(uint4*)(stg + off)         = *(const uint4*)(pAh + gi);
            *(uint4*)(stg + 16384 + off) = *(const uint4*)(pAl + gi);
            *(uint4*)(stg + 32768 + off) = *(const uint4*)(pBh + gi);
            *(uint4*)(stg + 49152 + off) = *(const uint4*)(pBl + gi);
        }
    }
    __syncthreads();

    float acc[4][4][4];
    #pragma unroll
    for (int i = 0; i < 4; ++i)
        #pragma unroll
        for (int j = 0; j < 4; ++j)
            #pragma unroll
            for (int q = 0; q < 4; ++q) acc[i][j][q] = 0.f;

    const int a_row = m0w + (lane & 15);
    const int a_chs = lane >> 4;
    const int b_row = n0w + ((lane >> 3) & 2) * 4 + (lane & 7);
    const int b_chs = (lane >> 3) & 1;

    const int KB = K >> 6;
    for (int kb = 0; kb < KB; ++kb) {
        const uint32_t stg = sbase + (uint32_t)(kb & 1) * MG_STAGE;
        const bool hasNext = (kb + 1) < KB;

        uint4 vAh[4], vAl[4], vBh[4], vBl[4];
        if (hasNext) {
            const int k0 = (kb + 1) << 6;
            #pragma unroll
            for (int p = 0; p < 4; ++p) {
                const int c = tid + (p << 8);
                const int row = c >> 3, ch = c & 7;
                const size_t gi = (size_t)row * K + k0 + (ch << 3);
                vAh[p] = *(const uint4*)(pAh + gi);
                vAl[p] = *(const uint4*)(pAl + gi);
                vBh[p] = *(const uint4*)(pBh + gi);
                vBl[p] = *(const uint4*)(pBl + gi);
            }
        }

        #pragma unroll
        for (int ks = 0; ks < 4; ++ks) {
            uint32_t afh[4][4], afl[4][4];
            #pragma unroll
            for (int mt = 0; mt < 4; ++mt) {
                const int row = a_row + mt * 16;
                const int ch  = ks * 2 + a_chs;
                const uint32_t off = (uint32_t)((row << 7) + ((ch ^ (row & 7)) << 4));
                ldsm4(afh[mt], stg + off);
                ldsm4(afl[mt], stg + 16384u + off);
            }
            uint32_t bfh[2][4], bfl[2][4];
            #pragma unroll
            for (int np = 0; np < 2; ++np) {
                const int row = b_row + np * 16;
                const int ch  = ks * 2 + b_chs;
                const uint32_t off = (uint32_t)((row << 7) + ((ch ^ (row & 7)) << 4));
                ldsm4(bfh[np], stg + 32768u + off);
                ldsm4(bfl[np], stg + 49152u + off);
            }
            #pragma unroll
            for (int mt = 0; mt < 4; ++mt) {
                #pragma unroll
                for (int nt = 0; nt < 4; ++nt) {
                    const uint32_t* bh = &bfh[nt >> 1][(nt & 1) * 2];
                    const uint32_t* bl = &bfl[nt >> 1][(nt & 1) * 2];
                    mma16816(acc[mt][nt], afh[mt], bh);
                    mma16816(acc[mt][nt], afh[mt], bl);
                    mma16816(acc[mt][nt], afl[mt], bh);
                }
            }
        }

        if (hasNext) {
            char* nst = smx + ((kb + 1) & 1) * MG_STAGE;
            #pragma unroll
            for (int p = 0; p < 4; ++p) {
                const int c = tid + (p << 8);
                const int row = c >> 3, ch = c & 7;
                const int off = (row << 7) + ((ch ^ (row & 7)) << 4);
                *(uint4*)(nst + off)         = vAh[p];
                *(uint4*)(nst + 16384 + off) = vAl[p];
                *(uint4*)(nst + 32768 + off) = vBh[p];
                *(uint4*)(nst + 49152 + off) = vBl[p];
            }
        }
        __syncthreads();
    }

    const int erow = lane >> 2;
    const int ecol = (lane & 3) * 2;
    #pragma unroll
    for (int mt = 0; mt < 4; ++mt) {
        #pragma unroll
        for (int nt = 0; nt < 4; ++nt) {
            const size_t gr0 = bm + m0w + mt * 16 + erow;
            const size_t gc  = bn + n0w + nt * 8 + ecol;
            float v0 = acc[mt][nt][0], v1 = acc[mt][nt][1];
            float v2 = acc[mt][nt][2], v3 = acc[mt][nt][3];
            if (do_silu) { v0 = siluf_(v0); v1 = siluf_(v1); v2 = siluf_(v2); v3 = siluf_(v3); }
            if (resid != nullptr) {
                const float2 r0 = *(const float2*)&resid[gr0 * N + gc];
                const float2 r1 = *(const float2*)&resid[(gr0 + 8) * N + gc];
                v0 += r0.x; v1 += r0.y; v2 += r1.x; v3 += r1.y;
            }
            float2 w0; w0.x = v0; w0.y = v1;
            float2 w1; w1.x = v2; w1.y = v3;
            *(float2*)&C[gr0 * N + gc]       = w0;
            *(float2*)&C[(gr0 + 8) * N + gc] = w1;
        }
    }
}

// ---------------------------------------------------------------------------
// 5a) prep1 (includes l2norm of k and q, q additionally * DK^-0.5)
// ---------------------------------------------------------------------------
#define P1_FLOATS (17408 + 17408 + 4352 + 64 + 64 + 272)
#define P1_BYTES  (P1_FLOATS * 4)

__global__ void __launch_bounds__(256, 1) prep1_kernel() {
    extern __shared__ float sm1[];
    float* Kt  = sm1;            // [256][68]
    float* wb  = sm1 + 17408;    // [64][260]
    float* Qts = sm1 + 17408;    // [256][68]  (aliases wb)
    float* Ms  = sm1 + 34816;    // [64][68]
    float* bsm = sm1 + 39168;    // [64]
    float* rsk = sm1 + 39232;    // [64]
    float* nrm = sm1 + 39296;    // [4][68]

    const int tid  = threadIdx.x;
    const int cIdx = blockIdx.x;
    const int n = cIdx & 31, h = (cIdx >> 5) & 3, b = cIdx >> 7;
    const size_t m0 = (size_t)b * T_ + n * C_;
    const int hK = h * DK_;

    if (tid < 64) bsm[tid] = g_beta[(m0 + tid) * H_ + h];

    #pragma unroll 4
    for (int p = 0; p < 16; ++p) {
        const int idx = tid + p * 256;
        const int i = idx >> 6, c4 = idx & 63;
        const float4 v = *(const float4*)&g_k[(m0 + i) * NKV + hK + c4 * 4];
        Kt[(c4 * 4 + 0) * 68 + i] = v.x;
        Kt[(c4 * 4 + 1) * 68 + i] = v.y;
        Kt[(c4 * 4 + 2) * 68 + i] = v.z;
        Kt[(c4 * 4 + 3) * 68 + i] = v.w;
    }
    __syncthreads();

    {
        const int i = tid & 63, part = tid >> 6;
        float ss = 0.f;
        #pragma unroll 4
        for (int kk = part * 64; kk < part * 64 + 64; ++kk) {
            const float vv = Kt[kk * 68 + i];
            ss += vv * vv;
        }
        nrm[part * 68 + i] = ss;
    }
    __syncthreads();
    if (tid < 64)
        rsk[tid] = rsqrtf(nrm[tid] + nrm[68 + tid] + nrm[136 + tid] + nrm[204 + tid] + 1e-6f);
    __syncthreads();
    for (int idx = tid; idx < 4352; idx += 256) {
        const int kk = idx / 17, f4 = idx % 17;
        if (f4 < 16) {
            float4 v = *(float4*)&Kt[kk * 68 + f4 * 4];
            const float4 r = *(const float4*)&rsk[f4 * 4];
            v.x *= r.x; v.y *= r.y; v.z *= r.z; v.w *= r.w;
            *(float4*)&Kt[kk * 68 + f4 * 4] = v;
        }
    }
    __syncthreads();

    const int ty = tid >> 4, tx = tid & 15;
    const int ti4 = ty * 4, tj4 = tx * 4;

    #pragma unroll 4
    for (int p = 0; p < 16; ++p) {
        const int idx = tid + p * 256;
        const int i = idx >> 6, c4 = idx & 63;
        const float bb = bsm[i];
        float4 v;
        v.x = bb * Kt[(c4 * 4 + 0) * 68 + i];
        v.y = bb * Kt[(c4 * 4 + 1) * 68 + i];
        v.z = bb * Kt[(c4 * 4 + 2) * 68 + i];
        v.w = bb * Kt[(c4 * 4 + 3) * 68 + i];
        *(float4*)&wb[i * 260 + c4 * 4] = v;
    }

    {
        ull acc[4][2] = {};
        #pragma unroll 4
        for (int kk = 0; kk < 256; ++kk) {
            const float4 a4 = *(const float4*)&Kt[kk * 68 + ti4];
            const float4 b4 = *(const float4*)&Kt[kk * 68 + tj4];
            mma4x4p(acc, a4, pack2(b4.x, b4.y), pack2(b4.z, b4.w));
        }
        float mo[4][4]; unp4x4(acc, mo);
        #pragma unroll
        for (int r = 0; r < 4; ++r) {
            const int i = ti4 + r;
            const float bi = bsm[i];
            #pragma unroll
            for (int cc = 0; cc < 4; ++cc) {
                const int j = tj4 + cc;
                Ms[i * 68 + j] = (j < i) ? bi * mo[r][cc] : 0.f;
            }
        }
    }

    {
        __nv_bfloat16* kth = g_cKth + (size_t)cIdx * 16384;
        __nv_bfloat16* ktl = g_cKtl + (size_t)cIdx * 16384;
        for (int idx = tid; idx < 8192; idx += 256) {
            const int kk = idx >> 5, i2 = (idx & 31) * 2;
            uint32_t hi, lo;
            split2(Kt[kk * 68 + i2], Kt[kk * 68 + i2 + 1], hi, lo);
            *(uint32_t*)(kth + kk * 64 + i2) = hi;
            *(uint32_t*)(ktl + kk * 64 + i2) = lo;
        }
    }
    __syncthreads();

    for (int i = 1; i < 64; ++i) {
        const float* mr = Ms + i * 68;
        float a0 = 0.f, a1 = 0.f, a2 = 0.f, a3 = 0.f;
        int j = 0;
        for (; j + 4 <= i; j += 4) {
            a0 += mr[j + 0] * wb[(j + 0) * 260 + tid];
            a1 += mr[j + 1] * wb[(j + 1) * 260 + tid];
            a2 += mr[j + 2] * wb[(j + 2) * 260 + tid];
            a3 += mr[j + 3] * wb[(j + 3) * 260 + tid];
        }
        for (; j < i; ++j) a0 += mr[j] * wb[j * 260 + tid];
        wb[i * 260 + tid] -= (a0 + a1) + (a2 + a3);
        __syncthreads();
    }

    {
        __nv_bfloat16* wh = g_cWh + (size_t)cIdx * 16384;
        __nv_bfloat16* wl = g_cWl + (size_t)cIdx * 16384;
        for (int idx = tid; idx < 8192; idx += 256) {
            const int i = idx >> 7, kk2 = (idx & 127) * 2;
            uint32_t hi, lo;
            split2(wb[i * 260 + kk2], wb[i * 260 + kk2 + 1], hi, lo);
            *(uint32_t*)(wh + i * 256 + kk2) = hi;
            *(uint32_t*)(wl + i * 256 + kk2) = lo;
        }
        float* mo = g_mlt + (size_t)cIdx * (C_ * C_);
        for (int idx = tid; idx < C_ * C_; idx += 256)
            mo[idx] = Ms[(idx >> 6) * 68 + (idx & 63)];
    }
    __syncthreads();   // wb dead; Qts may now overwrite

    #pragma unroll 4
    for (int p = 0; p < 16; ++p) {
        const int idx = tid + p * 256;
        const int i = idx >> 6, c4 = idx & 63;
        const float4 v = *(const float4*)&g_q[(m0 + i) * NKV + hK + c4 * 4];
        Qts[(c4 * 4 + 0) * 68 + i] = v.x;
        Qts[(c4 * 4 + 1) * 68 + i] = v.y;
        Qts[(c4 * 4 + 2) * 68 + i] = v.z;
        Qts[(c4 * 4 + 3) * 68 + i] = v.w;
    }
    __syncthreads();

    {
        const int i = tid & 63, part = tid >> 6;
        float ss = 0.f;
        #pragma unroll 4
        for (int kk = part * 64; kk < part * 64 + 64; ++kk) {
            const float vv = Qts[kk * 68 + i];
            ss += vv * vv;
        }
        nrm[part * 68 + i] = ss;
    }
    __syncthreads();
    if (tid < 64)
        rsk[tid] = rsqrtf(nrm[tid] + nrm[68 + tid] + nrm[136 + tid] + nrm[204 + tid] + 1e-6f) * 0.0625f;
    __syncthreads();
    for (int idx = tid; idx < 4352; idx += 256) {
        const int kk = idx / 17, f4 = idx % 17;
        if (f4 < 16) {
            float4 v = *(float4*)&Qts[kk * 68 + f4 * 4];
            const float4 r = *(const float4*)&rsk[f4 * 4];
            v.x *= r.x; v.y *= r.y; v.z *= r.z; v.w *= r.w;
            *(float4*)&Qts[kk * 68 + f4 * 4] = v;
        }
    }
    __syncthreads();

    {
        __nv_bfloat16* qh = g_cQh + (size_t)cIdx * 16384;
        __nv_bfloat16* ql = g_cQl + (size_t)cIdx * 16384;
        for (int idx = tid; idx < 8192; idx += 256) {
            const int i = idx >> 7, kk2 = (idx & 127) * 2;
            uint32_t hi, lo;
            split2(Qts[kk2 * 68 + i], Qts[(kk2 + 1) * 68 + i], hi, lo);
            *(uint32_t*)(qh + i * 256 + kk2) = hi;
            *(uint32_t*)(ql + i * 256 + kk2) = lo;
        }
    }

    {
        ull acc[4][2] = {};
        #pragma unroll 4
        for (int kk = 0; kk < 256; ++kk) {
            const float4 a4 = *(const float4*)&Qts[kk * 68 + ti4];
            const float4 b4 = *(const float4*)&Kt[kk * 68 + tj4];
            mma4x4p(acc, a4, pack2(b4.x, b4.y), pack2(b4.z, b4.w));
        }
        float po[4][4]; unp4x4(acc, po);
        __nv_bfloat16* ph = g_cPh + (size_t)cIdx * 4096;
        __nv_bfloat16* pl = g_cPl + (size_t)cIdx * 4096;
        #pragma unroll
        for (int r = 0; r < 4; ++r) {
            const int i = ti4 + r;
            const float v0 = (tj4 + 0 <= i) ? po[r][0] : 0.f;
            const float v1 = (tj4 + 1 <= i) ? po[r][1] : 0.f;
            const float v2 = (tj4 + 2 <= i) ? po[r][2] : 0.f;
            const float v3 = (tj4 + 3 <= i) ? po[r][3] : 0.f;
            uint32_t hi, lo;
            split2(v0, v1, hi, lo);
            *(uint32_t*)(ph + i * 64 + tj4)     = hi;
            *(uint32_t*)(pl + i * 64 + tj4)     = lo;
            split2(v2, v3, hi, lo);
            *(uint32_t*)(ph + i * 64 + tj4 + 2) = hi;
            *(uint32_t*)(pl + i * 64 + tj4 + 2) = lo;
        }
    }
}

// ---------------------------------------------------------------------------
// 5b) prep2: Uv = (I+M)^{-1} (beta V)  -> g_Uv (unchanged)
// ---------------------------------------------------------------------------
#define P2_FLOATS (33280 + 4352 + 64)
#define P2_BYTES  (P2_FLOATS * 4)

__global__ void __launch_bounds__(256, 1) prep2_kernel() {
    extern __shared__ float sm2[];
    float* vb  = sm2;            // [64][520]
    float* Ms  = sm2 + 33280;    // [64][68]
    float* bsm = sm2 + 33280 + 4352;

    const int tid  = threadIdx.x;
    const int cIdx = blockIdx.x;
    const int n = cIdx & 31, h = (cIdx >> 5) & 3, b = cIdx >> 7;
    const size_t m0 = (size_t)b * T_ + n * C_;
    const int hV = h * DV_;

    if (tid < 64) bsm[tid] = g_beta[(m0 + tid) * H_ + h];
    {
        const float* mg = g_mlt + (size_t)cIdx * (C_ * C_);
        for (int idx = tid; idx < C_ * C_; idx += 256)
            Ms[(idx >> 6) * 68 + (idx & 63)] = mg[idx];
    }
    __syncthreads();

    #pragma unroll 4
    for (int p = 0; p < 32; ++p) {
        const int idx = tid + p * 256;
        const int i = idx >> 7, c4 = idx & 127;
        float4 v = *(const float4*)&g_v[(m0 + i) * NV + hV + c4 * 4];
        const float bb = bsm[i];
        v.x *= bb; v.y *= bb; v.z *= bb; v.w *= bb;
        *(float4*)&vb[i * 520 + c4 * 4] = v;
    }
    __syncthreads();

    const int col2 = 2 * tid;
    for (int i = 1; i < 64; ++i) {
        const float* mr = Ms + i * 68;
        ull acc = 0ull;
        for (int j = 0; j < i; ++j) {
            const float m = mr[j];
            const ull v = *(const ull*)&vb[j * 520 + col2];
            ffma2(acc, pack2(m, m), v);
        }
        float ax, ay; unpack2(acc, ax, ay);
        vb[i * 520 + col2]     -= ax;
        vb[i * 520 + col2 + 1] -= ay;
        __syncthreads();
    }

    float* uo = g_Uv + (size_t)cIdx * (C_ * DV_);
    #pragma unroll 4
    for (int p = 0; p < 32; ++p) {
        const int idx = tid + p * 256;
        const int i = idx >> 7, c4 = idx & 127;
        *(float4*)&uo[i * DV_ + c4 * 4] = *(const float4*)&vb[i * 520 + c4 * 4];
    }
}

// ---------------------------------------------------------------------------
// 5c) chunkscan v4: dv-slice 32, 256 CTAs -> 2 CTAs/SM.
//     256 thr / 8 warps, warp grid 4m x 2n (16x16 tiles).
//     SMEM 107.5 KB: SF [256][33] fp32 | SH/SL [256][32] | UH/UL [64][32] | STG 32KB
// ---------------------------------------------------------------------------
#define CS3_SF   0
#define CS3_SH   33792
#define CS3_SL   50176
#define CS3_UH   66560
#define CS3_UL   70656
#define CS3_STG  74752
#define CS3_BYTES 107520

__global__ void __launch_bounds__(256, 2) chunkscan_kernel() {
    extern __shared__ char sm3[];
    float* SF  = (float*)(sm3 + CS3_SF);      // [256][33] fp32
    char*  SH  = sm3 + CS3_SH;                // [256][32] bf16 swizzled (64B rows)
    char*  SL  = sm3 + CS3_SL;
    char*  UH  = sm3 + CS3_UH;                // [64][32] bf16 swizzled
    char*  UL  = sm3 + CS3_UL;
    char*  STG = sm3 + CS3_STG;               // 4 x 8192B A-tiles (128B rows)

    const uint32_t stg_u = smem_u32(STG);
    const uint32_t sh_u  = smem_u32(SH);
    const uint32_t sl_u  = smem_u32(SL);
    const uint32_t uh_u  = smem_u32(UH);
    const uint32_t ul_u  = smem_u32(UL);

    const int tid  = threadIdx.x;
    const int lane = tid & 31, wid = tid >> 5;
    const int wm = wid >> 1, wn = wid & 1;      // 4m x 2n
    const int erow = lane >> 2, ecol = (lane & 3) * 2;
    const int lrow = lane & 15, lhi = lane >> 4;
    const int c = blockIdx.x & 15, h = (blockIdx.x >> 4) & 3, b = blockIdx.x >> 6;
    const int dv0 = c * 32;

    for (int i = tid; i < 8448; i += 256) SF[i] = 0.f;
    for (int i = tid; i < 4096; i += 256) { ((uint32_t*)SH)[i] = 0u; ((uint32_t*)SL)[i] = 0u; }
    __syncthreads();

    for (int n = 0; n < NC_; ++n) {
        const int cIdx = b * 128 + h * 32 + n;
        const __nv_bfloat16* Wh  = g_cWh  + (size_t)cIdx * 16384;
        const __nv_bfloat16* Wl  = g_cWl  + (size_t)cIdx * 16384;
        const __nv_bfloat16* Qh  = g_cQh  + (size_t)cIdx * 16384;
        const __nv_bfloat16* Ql  = g_cQl  + (size_t)cIdx * 16384;
        const __nv_bfloat16* Kth = g_cKth + (size_t)cIdx * 16384;
        const __nv_bfloat16* Ktl = g_cKtl + (size_t)cIdx * 16384;
        const __nv_bfloat16* Ph  = g_cPh  + (size_t)cIdx * 4096;
        const __nv_bfloat16* Pl  = g_cPl  + (size_t)cIdx * 4096;
        const float* Uvg = g_Uv + (size_t)cIdx * 32768 + dv0;
        const size_t m0  = (size_t)b * T_ + n * 64;

        // stage W/Q block 0
        #pragma unroll
        for (int j = 0; j < 2; ++j) {
            const int idx = tid + j * 256;
            const int r = idx >> 3, ch = idx & 7;
            const uint32_t so = swz(r, ch);
            const size_t gi = (size_t)r * 256 + ch * 8;
            *(uint4*)(STG + so)         = *(const uint4*)(Wh + gi);
            *(uint4*)(STG + 8192 + so)  = *(const uint4*)(Wl + gi);
            *(uint4*)(STG + 16384 + so) = *(const uint4*)(Qh + gi);
            *(uint4*)(STG + 24576 + so) = *(const uint4*)(Ql + gi);
        }
        __syncthreads();

        float accU[2][4] = {}, accO[2][4] = {};

        // GEMM1+2a: accU = W·S, accO = Q·S over 4 kk-blocks
        for (int kb = 0; kb < 4; ++kb) {
            uint4 pf[8];
            if (kb < 3) {
                #pragma unroll
                for (int j = 0; j < 2; ++j) {
                    const int idx = tid + j * 256;
                    const int r = idx >> 3, ch = idx & 7;
                    const size_t gi = (size_t)r * 256 + (kb + 1) * 64 + ch * 8;
                    pf[j]     = *(const uint4*)(Wh + gi);
                    pf[2 + j] = *(const uint4*)(Wl + gi);
                    pf[4 + j] = *(const uint4*)(Qh + gi);
                    pf[6 + j] = *(const uint4*)(Ql + gi);
                }
            }
            #pragma unroll
            for (int ks = 0; ks < 4; ++ks) {
                uint32_t wfh[4], wfl[4], qfh[4], qfl[4];
                const int ar = wm * 16 + lrow;
                const uint32_t ao = swz(ar, ks * 2 + lhi);
                ldsm4(wfh, stg_u + ao);
                ldsm4(wfl, stg_u + 8192u + ao);
                ldsm4(qfh, stg_u + 16384u + ao);
                ldsm4(qfl, stg_u + 24576u + ao);
                uint32_t sfh[4], sfl[4];
                const int br = kb * 64 + ks * 16 + lrow;
                const uint32_t bo = swz32(br, wn * 2 + lhi);
                ldsm4t(sfh, sh_u + bo);
                ldsm4t(sfl, sl_u + bo);
                #pragma unroll
                for (int nt = 0; nt < 2; ++nt) {
                    mma16816(accU[nt], wfh, sfh + nt * 2);
                    mma16816(accU[nt], wfh, sfl + nt * 2);
                    mma16816(accU[nt], wfl, sfh + nt * 2);
                    mma16816(accO[nt], qfh, sfh + nt * 2);
                    mma16816(accO[nt], qfh, sfl + nt * 2);
                    mma16816(accO[nt], qfl, sfh + nt * 2);
                }
            }
            __syncthreads();
            if (kb < 3) {
                #pragma unroll
                for (int j = 0; j < 2; ++j) {
                    const int idx = tid + j * 256;
                    const int r = idx >> 3, ch = idx & 7;
                    const uint32_t so = swz(r, ch);
                    *(uint4*)(STG + so)         = pf[j];
                    *(uint4*)(STG + 8192 + so)  = pf[2 + j];
                    *(uint4*)(STG + 16384 + so) = pf[4 + j];
                    *(uint4*)(STG + 24576 + so) = pf[6 + j];
                }
                __syncthreads();
            }
        }

        // U finalize (u = Uv - accU) -> UH/UL (Uv read direct from global)
        #pragma unroll
        for (int nt = 0; nt < 2; ++nt) {
            const int r0 = wm * 16 + erow;
            const int cc = wn * 16 + nt * 8 + ecol;
            const float2 uva = *(const float2*)&Uvg[(size_t)r0 * DV_ + cc];
            const float2 uvb = *(const float2*)&Uvg[(size_t)(r0 + 8) * DV_ + cc];
            const float u0 = uva.x - accU[nt][0];
            const float u1 = uva.y - accU[nt][1];
            const float u2 = uvb.x - accU[nt][2];
            const float u3 = uvb.y - accU[nt][3];
            uint32_t hi, lo;
            split2(u0, u1, hi, lo);
            *(uint32_t*)(UH + swzb32(r0, cc)) = hi;
            *(uint32_t*)(UL + swzb32(r0, cc)) = lo;
            split2(u2, u3, hi, lo);
            *(uint32_t*)(UH + swzb32(r0 + 8, cc)) = hi;
            *(uint32_t*)(UL + swzb32(r0 + 8, cc)) = lo;
        }
        // stage P -> T0/T1, Kt block0 -> T2/T3
        #pragma unroll
        for (int j = 0; j < 2; ++j) {
            const int idx = tid + j * 256;
            const int r = idx >> 3, ch = idx & 7;
            const uint32_t so = swz(r, ch);
            const size_t gp = (size_t)r * 64 + ch * 8;
            *(uint4*)(STG + so)         = *(const uint4*)(Ph + gp);
            *(uint4*)(STG + 8192 + so)  = *(const uint4*)(Pl + gp);
            *(uint4*)(STG + 16384 + so) = *(const uint4*)(Kth + gp);
            *(uint4*)(STG + 24576 + so) = *(const uint4*)(Ktl + gp);
        }
        __syncthreads();

        // hoist U B-fragments for all 4 k-steps (shared by GEMM2b and GEMM3)
        uint32_t ufh[4][4], ufl[4][4];
        #pragma unroll
        for (int ks = 0; ks < 4; ++ks) {
            const int br = ks * 16 + lrow;
            const uint32_t bo = swz32(br, wn * 2 + lhi);
            ldsm4t(ufh[ks], uh_u + bo);
            ldsm4t(ufl[ks], ul_u + bo);
        }

        // GEMM2b: accO += P·U
        #pragma unroll
        for (int ks = 0; ks < 4; ++ks) {
            uint32_t pfh[4], pfl[4];
            const int ar = wm * 16 + lrow;
            const uint32_t ao = swz(ar, ks * 2 + lhi);
            ldsm4(pfh, stg_u + ao);
            ldsm4(pfl, stg_u + 8192u + ao);
            #pragma unroll
            for (int nt = 0; nt < 2; ++nt) {
                mma16816(accO[nt], pfh, ufh[ks] + nt * 2);
                mma16816(accO[nt], pfh, ufl[ks] + nt * 2);
                mma16816(accO[nt], pfl, ufh[ks] + nt * 2);
            }
        }

        // O epilogue -> global
        #pragma unroll
        for (int nt = 0; nt < 2; ++nt) {
            const int r0 = wm * 16 + erow;
            const int cc = wn * 16 + nt * 8 + ecol;
            float2 w0; w0.x = accO[nt][0]; w0.y = accO[nt][1];
            float2 w1; w1.x = accO[nt][2]; w1.y = accO[nt][3];
            *(float2*)&g_o[(m0 + r0) * NV + h * DV_ + dv0 + cc]     = w0;
            *(float2*)&g_o[(m0 + r0 + 8) * NV + h * DV_ + dv0 + cc] = w1;
        }
        __syncthreads();   // retire P reads (T0/T1) before GEMM3 stores there

        // GEMM3: S += K^T · U, 4 kk-blocks, double-buffered halves
        for (int kkb = 0; kkb < 4; ++kkb) {
            float accS[2][4] = {};
            uint4 kf[4];
            if (kkb < 3) {
                #pragma unroll
                for (int j = 0; j < 2; ++j) {
                    const int idx = tid + j * 256;
                    const int r = idx >> 3, ch = idx & 7;
                    const size_t gi = (size_t)((kkb + 1) * 64 + r) * 64 + ch * 8;
                    kf[j]     = *(const uint4*)(Kth + gi);
                    kf[2 + j] = *(const uint4*)(Ktl + gi);
                }
            }
            const uint32_t curH = stg_u + ((kkb & 1) ? 0u : 16384u);
            const uint32_t curL = stg_u + ((kkb & 1) ? 8192u : 24576u);
            #pragma unroll
            for (int ks = 0; ks < 4; ++ks) {
                uint32_t kfh[4], kfl[4];
                const int ar = wm * 16 + lrow;
                const uint32_t ao = swz(ar, ks * 2 + lhi);
                ldsm4(kfh, curH + ao);
                ldsm4(kfl, curL + ao);
                #pragma unroll
                for (int nt = 0; nt < 2; ++nt) {
                    mma16816(accS[nt], kfh, ufh[ks] + nt * 2);
                    mma16816(accS[nt], kfh, ufl[ks] + nt * 2);
                    mma16816(accS[nt], kfl, ufh[ks] + nt * 2);
                }
            }
            // S finalize: fp32 RMW + bf16 re-split for this 64-row block
            #pragma unroll
            for (int nt = 0; nt < 2; ++nt) {
                const int sr = kkb * 64 + wm * 16 + erow;
                const int sc = wn * 16 + nt * 8 + ecol;
                const float s0 = SF[sr * 33 + sc]           + accS[nt][0];
                const float s1 = SF[sr * 33 + sc + 1]       + accS[nt][1];
                const float s2 = SF[(sr + 8) * 33 + sc]     + accS[nt][2];
                const float s3 = SF[(sr + 8) * 33 + sc + 1] + accS[nt][3];
                SF[sr * 33 + sc]           = s0;
                SF[sr * 33 + sc + 1]       = s1;
                SF[(sr + 8) * 33 + sc]     = s2;
                SF[(sr + 8) * 33 + sc + 1] = s3;
                uint32_t hi, lo;
                split2(s0, s1, hi, lo);
                *(uint32_t*)(SH + swzb32(sr, sc)) = hi;
                *(uint32_t*)(SL + swzb32(sr, sc)) = lo;
                split2(s2, s3, hi, lo);
                *(uint32_t*)(SH + swzb32(sr + 8, sc)) = hi;
                *(uint32_t*)(SL + swzb32(sr + 8, sc)) = lo;
            }
            __syncthreads();
            if (kkb < 3) {
                char* oH = STG + ((kkb & 1) ? 16384 : 0);
                char* oL = STG + ((kkb & 1) ? 24576 : 8192);
                #pragma unroll
                for (int j = 0; j < 2; ++j) {
                    const int idx = tid + j * 256;
                    const int r = idx >> 3, ch = idx & 7;
                    const uint32_t so = swz(r, ch);
                    *(uint4*)(oH + so) = kf[j];
                    *(uint4*)(oL + so) = kf[2 + j];
                }
                __syncthreads();
            }
        }
    }
}

// ---------------------------------------------------------------------------
// 6) per-head RMSNorm on g_o -> bf16 split g_oh/g_ol
// ---------------------------------------------------------------------------
__global__ void __launch_bounds__(256) rmsnorm_kernel(const float* __restrict__ w) {
    const int grp  = blockIdx.x * 8 + (threadIdx.x >> 5);
    const int lane = threadIdx.x & 31;
    const float* base = g_o + (size_t)grp * DV_;
    float4 v[4];
    float ss = 0.f;
    #pragma unroll
    for (int i = 0; i < 4; ++i) {
        v[i] = ((const float4*)base)[lane + 32 * i];
        ss += v[i].x * v[i].x + v[i].y * v[i].y + v[i].z * v[i].z + v[i].w * v[i].w;
    }
    #pragma unroll
    for (int off = 16; off > 0; off >>= 1) ss += __shfl_xor_sync(0xffffffffu, ss, off);
    const float rs = rsqrtf(ss * (1.0f / DV_) + 1e-5f);
    #pragma unroll
    for (int i = 0; i < 4; ++i) {
        const int idx = lane + 32 * i;
        const float4 wv = ((const float4*)w)[idx];
        const float4 o = make_float4(v[i].x * rs * wv.x, v[i].y * rs * wv.y,
                                     v[i].z * rs * wv.z, v[i].w * rs * wv.w);
        split_store4(o, g_oh, g_ol, (size_t)grp * DV_ + (size_t)idx * 4);
    }
}

// ---------------------------------------------------------------------------
// Launch
// ---------------------------------------------------------------------------
extern "C" void kernel_launch(void* const* d_in, const int* in_sizes, int n_in,
                              void* d_out, int out_size) {
    const float* x        = (const float*)d_in[0];
    const float* ln_w     = (const float*)d_in[1];
    const float* ln_b     = (const float*)d_in[2];
    const float* Wq       = (const float*)d_in[3];
    const float* Wk       = (const float*)d_in[4];
    const float* Wv       = (const float*)d_in[5];
    const float* Wb       = (const float*)d_in[6];
    const float* o_norm_w = (const float*)d_in[7];
    const float* Wo       = (const float*)d_in[8];
    float* out = (float*)d_out;

    cudaFuncSetAttribute(mma_gemm, cudaFuncAttributeMaxDynamicSharedMemorySize, MG_SMEM);
    cudaFuncSetAttribute(prep1_kernel, cudaFuncAttributeMaxDynamicSharedMemorySize, P1_BYTES);
    cudaFuncSetAttribute(prep2_kernel, cudaFuncAttributeMaxDynamicSharedMemorySize, P2_BYTES);
    cudaFuncSetAttribute(chunkscan_kernel, cudaFuncAttributeMaxDynamicSharedMemorySize, CS3_BYTES);

    __nv_bfloat16 *nh, *nl, *oh, *ol, *wqh, *wql, *wkh, *wkl, *wvh, *wvl, *woh, *wol;
    cudaGetSymbolAddress((void**)&nh,  g_nh);
    cudaGetSymbolAddress((void**)&nl,  g_nl);
    cudaGetSymbolAddress((void**)&oh,  g_oh);
    cudaGetSymbolAddress((void**)&ol,  g_ol);
    cudaGetSymbolAddress((void**)&wqh, g_Wqt_h);
    cudaGetSymbolAddress((void**)&wql, g_Wqt_l);
    cudaGetSymbolAddress((void**)&wkh, g_Wkt_h);
    cudaGetSymbolAddress((void**)&wkl, g_Wkt_l);
    cudaGetSymbolAddress((void**)&wvh, g_Wvt_h);
    cudaGetSymbolAddress((void**)&wvl, g_Wvt_l);
    cudaGetSymbolAddress((void**)&woh, g_Wot_h);
    cudaGetSymbolAddress((void**)&wol, g_Wot_l);
    float *gq, *gk, *gv;
    cudaGetSymbolAddress((void**)&gq, g_q);
    cudaGetSymbolAddress((void**)&gk, g_k);
    cudaGetSymbolAddress((void**)&gv, g_v);

    // 1) LayerNorm (+ bf16 split of normed, + fused beta)
    ln_kernel<<<M_, 256>>>(x, ln_w, ln_b, Wb);

    // 1b) weight transpose+split
    wtrans_kernel<<<dim3(NKV / 32, D_ / 32), 256>>>(Wq, wqh, wql, D_, NKV);
    wtrans_kernel<<<dim3(NKV / 32, D_ / 32), 256>>>(Wk, wkh, wkl, D_, NKV);
    wtrans_kernel<<<dim3(NV  / 32, D_ / 32), 256>>>(Wv, wvh, wvl, D_, NV);
    wtrans_kernel<<<dim3(D_  / 32, NV / 32), 256>>>(Wo, woh, wol, NV, D_);

    // 2) projections (HMMA, silu fused)
    mma_gemm<<<dim3(NKV / 128, M_ / 128), 256, MG_SMEM>>>(nh, nl, wqh, wql, gq, nullptr, NKV, D_, 1);
    mma_gemm<<<dim3(NKV / 128, M_ / 128), 256, MG_SMEM>>>(nh, nl, wkh, wkl, gk, nullptr, NKV, D_, 1);
    mma_gemm<<<dim3(NV  / 128, M_ / 128), 256, MG_SMEM>>>(nh, nl, wvh, wvl, gv, nullptr, NV,  D_, 1);

    // 5) chunked delta-rule (prep1 includes l2norm of q/k)
    prep1_kernel<<<NCH, 256, P1_BYTES>>>();
    prep2_kernel<<<NCH, 256, P2_BYTES>>>();
    chunkscan_kernel<<<B_ * H_ * 16, 256, CS3_BYTES>>>();

    // 6) RMSNorm (+ bf16 split of o)
    rmsnorm_kernel<<<(M_ * H_) / 8, 256>>>(o_norm_w);

    // 7) output projection + residual (HMMA)
    mma_gemm<<<dim3(D_ / 128, M_ / 128), 256, MG_SMEM>>>(oh, ol, woh, wol, out, x, D_, NV, 0);
}

// round 13
// speedup vs baseline: 1.0487x; 1.0487x over previous
#include <cuda_runtime.h>
#include <cuda_bf16.h>
#include <cstdint>

// Problem constants (fixed shapes)
#define B_  4
#define T_  2048
#define D_  1024
#define H_  4
#define DK_ 256
#define DV_ 512
#define M_  (B_ * T_)        // 8192 rows
#define NKV (H_ * DK_)       // 1024
#define NV  (H_ * DV_)       // 2048
#define C_   64              // chunk length
#define NC_  32              // chunks per sequence
#define NCH  (B_ * H_ * NC_) // 512 chunk instances

typedef unsigned long long ull;

// ---------------------------------------------------------------------------
// Scratch (device globals; no dynamic allocation allowed)
// ---------------------------------------------------------------------------
__device__ float g_q[(size_t)M_ * NKV];
__device__ float g_k[(size_t)M_ * NKV];
__device__ float g_v[(size_t)M_ * NV];
__device__ float g_beta[(size_t)M_ * H_];
__device__ float g_o[(size_t)M_ * NV];
// chunked-scan intermediates
__device__ float g_mlt[(size_t)NCH * C_ * C_];   // [cIdx][i][j]  strict tril
__device__ float g_Uv [(size_t)NCH * C_ * DV_];  // [cIdx][i][dv] fp32
// split-bf16 chunkscan operands (written by prep1)
__device__ __nv_bfloat16 g_cWh [(size_t)NCH * C_ * DK_];  // [cIdx][i][kk]
__device__ __nv_bfloat16 g_cWl [(size_t)NCH * C_ * DK_];
__device__ __nv_bfloat16 g_cQh [(size_t)NCH * C_ * DK_];  // [cIdx][i][kk]
__device__ __nv_bfloat16 g_cQl [(size_t)NCH * C_ * DK_];
__device__ __nv_bfloat16 g_cKth[(size_t)NCH * DK_ * C_];  // [cIdx][kk][i]
__device__ __nv_bfloat16 g_cKtl[(size_t)NCH * DK_ * C_];
__device__ __nv_bfloat16 g_cPh [(size_t)NCH * C_ * C_];   // [cIdx][i][j]
__device__ __nv_bfloat16 g_cPl [(size_t)NCH * C_ * C_];
// bf16 split operands for projection GEMMs
__device__ __nv_bfloat16 g_nh[(size_t)M_ * D_];
__device__ __nv_bfloat16 g_nl[(size_t)M_ * D_];
__device__ __nv_bfloat16 g_oh[(size_t)M_ * NV];
__device__ __nv_bfloat16 g_ol[(size_t)M_ * NV];
__device__ __nv_bfloat16 g_Wqt_h[(size_t)NKV * D_];
__device__ __nv_bfloat16 g_Wqt_l[(size_t)NKV * D_];
__device__ __nv_bfloat16 g_Wkt_h[(size_t)NKV * D_];
__device__ __nv_bfloat16 g_Wkt_l[(size_t)NKV * D_];
__device__ __nv_bfloat16 g_Wvt_h[(size_t)NV * D_];
__device__ __nv_bfloat16 g_Wvt_l[(size_t)NV * D_];
__device__ __nv_bfloat16 g_Wot_h[(size_t)D_ * NV];
__device__ __nv_bfloat16 g_Wot_l[(size_t)D_ * NV];

// ---------------------------------------------------------------------------
// f32x2 packed-FMA helpers (prep kernels)
// ---------------------------------------------------------------------------
__device__ __forceinline__ ull pack2(float x, float y) {
    ull r; asm("mov.b64 %0, {%1, %2};" : "=l"(r) : "f"(x), "f"(y)); return r;
}
__device__ __forceinline__ void unpack2(ull v, float& x, float& y) {
    asm("mov.b64 {%0, %1}, %2;" : "=f"(x), "=f"(y) : "l"(v));
}
__device__ __forceinline__ void ffma2(ull& d, ull a, ull b) {
    asm("fma.rn.f32x2 %0, %1, %2, %0;" : "+l"(d) : "l"(a), "l"(b));
}
__device__ __forceinline__ void mma4x4p(ull (&acc)[4][2], const float4 a4,
                                        const ull b0, const ull b1) {
    ull a;
    a = pack2(a4.x, a4.x); ffma2(acc[0][0], a, b0); ffma2(acc[0][1], a, b1);
    a = pack2(a4.y, a4.y); ffma2(acc[1][0], a, b0); ffma2(acc[1][1], a, b1);
    a = pack2(a4.z, a4.z); ffma2(acc[2][0], a, b0); ffma2(acc[2][1], a, b1);
    a = pack2(a4.w, a4.w); ffma2(acc[3][0], a, b0); ffma2(acc[3][1], a, b1);
}
__device__ __forceinline__ void unp4x4(const ull (&acc)[4][2], float (&o)[4][4]) {
    #pragma unroll
    for (int r = 0; r < 4; ++r) {
        unpack2(acc[r][0], o[r][0], o[r][1]);
        unpack2(acc[r][1], o[r][2], o[r][3]);
    }
}

__device__ __forceinline__ float sigmoidf_(float x) { return 1.0f / (1.0f + __expf(-x)); }
__device__ __forceinline__ float siluf_(float x)    { return x * sigmoidf_(x); }

// split pair (a,b) fp32 -> hi bf16x2 (as u32) + lo bf16x2 (as u32)
__device__ __forceinline__ void split2(float a, float b, uint32_t& hi, uint32_t& lo) {
    __nv_bfloat162 h, l;
    h.x = __float2bfloat16(a); h.y = __float2bfloat16(b);
    l.x = __float2bfloat16(a - __bfloat162float(h.x));
    l.y = __float2bfloat16(b - __bfloat162float(h.y));
    hi = *(uint32_t*)&h; lo = *(uint32_t*)&l;
}

__device__ __forceinline__ void split_store4(const float4 v,
                                             __nv_bfloat16* __restrict__ hp,
                                             __nv_bfloat16* __restrict__ lp,
                                             size_t idx) {
    uint32_t h0, l0, h1, l1;
    split2(v.x, v.y, h0, l0);
    split2(v.z, v.w, h1, l1);
    *(uint32_t*)(hp + idx)     = h0;
    *(uint32_t*)(hp + idx + 2) = h1;
    *(uint32_t*)(lp + idx)     = l0;
    *(uint32_t*)(lp + idx + 2) = l1;
}

// ---------------------------------------------------------------------------
// mma.sync helpers (arch-portable HMMA)
// ---------------------------------------------------------------------------
__device__ __forceinline__ uint32_t smem_u32(const void* p) {
    uint32_t a;
    asm("{ .reg .u64 t; cvta.to.shared.u64 t, %1; cvt.u32.u64 %0, t; }" : "=r"(a) : "l"(p));
    return a;
}
__device__ __forceinline__ void ldsm4(uint32_t* r, uint32_t addr) {
    asm volatile("ldmatrix.sync.aligned.m8n8.x4.shared.b16 {%0,%1,%2,%3}, [%4];"
        : "=r"(r[0]), "=r"(r[1]), "=r"(r[2]), "=r"(r[3]) : "r"(addr));
}
__device__ __forceinline__ void ldsm4t(uint32_t* r, uint32_t addr) {
    asm volatile("ldmatrix.sync.aligned.m8n8.x4.trans.shared.b16 {%0,%1,%2,%3}, [%4];"
        : "=r"(r[0]), "=r"(r[1]), "=r"(r[2]), "=r"(r[3]) : "r"(addr));
}
__device__ __forceinline__ void mma16816(float* c, const uint32_t* a, const uint32_t* b) {
    asm volatile(
        "mma.sync.aligned.m16n8k16.row.col.f32.bf16.bf16.f32 "
        "{%0,%1,%2,%3}, {%4,%5,%6,%7}, {%8,%9}, {%0,%1,%2,%3};"
        : "+f"(c[0]), "+f"(c[1]), "+f"(c[2]), "+f"(c[3])
        : "r"(a[0]), "r"(a[1]), "r"(a[2]), "r"(a[3]), "r"(b[0]), "r"(b[1]));
}

// 64-col bf16 tile swizzle: rows of 128B, 8 chunks of 16B, chunk ^ (row&7)
__device__ __forceinline__ uint32_t swz(int row, int ch) {
    return (uint32_t)((row << 7) + ((ch ^ (row & 7)) << 4));
}
// byte offset of bf16 element (row, col), col even
__device__ __forceinline__ uint32_t swzb(int row, int col) {
    return (uint32_t)((row << 7) + ((((col >> 3) ^ (row & 7))) << 4) + ((col & 7) << 1));
}

// ---------------------------------------------------------------------------
// 1) LayerNorm -> g_nh/g_nl (bf16 split) + fused beta = sigmoid(normed @ Wb)
// ---------------------------------------------------------------------------
__global__ void __launch_bounds__(256) ln_kernel(const float* __restrict__ x,
                                                 const float* __restrict__ w,
                                                 const float* __restrict__ b,
                                                 const float* __restrict__ Wb) {
    const int row = blockIdx.x;
    const int tid = threadIdx.x;
    const float4 v = ((const float4*)(x + (size_t)row * D_))[tid];

    float s  = v.x + v.y + v.z + v.w;
    float s2 = v.x * v.x + v.y * v.y + v.z * v.z + v.w * v.w;
    #pragma unroll
    for (int off = 16; off > 0; off >>= 1) {
        s  += __shfl_xor_sync(0xffffffffu, s,  off);
        s2 += __shfl_xor_sync(0xffffffffu, s2, off);
    }
    __shared__ float sh[16];
    __shared__ float bsh[32];
    const int wid = tid >> 5, lane = tid & 31;
    if (lane == 0) { sh[wid] = s; sh[8 + wid] = s2; }
    __syncthreads();
    float ts = 0.f, ts2 = 0.f;
    #pragma unroll
    for (int i = 0; i < 8; ++i) { ts += sh[i]; ts2 += sh[8 + i]; }

    const float mean = ts * (1.0f / D_);
    const float var  = ts2 * (1.0f / D_) - mean * mean;
    const float rstd = rsqrtf(var + 1e-5f);

    const float4 wv = ((const float4*)w)[tid];
    const float4 bv = ((const float4*)b)[tid];
    float4 o;
    o.x = (v.x - mean) * rstd * wv.x + bv.x;
    o.y = (v.y - mean) * rstd * wv.y + bv.y;
    o.z = (v.z - mean) * rstd * wv.z + bv.z;
    o.w = (v.w - mean) * rstd * wv.w + bv.w;
    const size_t base = (size_t)row * D_;
    split_store4(o, g_nh, g_nl, base + (size_t)tid * 4);

    // fused beta: partial dot of normed row with Wb[:,0..3]
    float a0, a1, a2, a3;
    {
        const float4 w0 = ((const float4*)Wb)[tid * 4 + 0];
        const float4 w1 = ((const float4*)Wb)[tid * 4 + 1];
        const float4 w2 = ((const float4*)Wb)[tid * 4 + 2];
        const float4 w3 = ((const float4*)Wb)[tid * 4 + 3];
        a0 = o.x * w0.x + o.y * w1.x + o.z * w2.x + o.w * w3.x;
        a1 = o.x * w0.y + o.y * w1.y + o.z * w2.y + o.w * w3.y;
        a2 = o.x * w0.z + o.y * w1.z + o.z * w2.z + o.w * w3.z;
        a3 = o.x * w0.w + o.y * w1.w + o.z * w2.w + o.w * w3.w;
    }
    #pragma unroll
    for (int off = 16; off > 0; off >>= 1) {
        a0 += __shfl_xor_sync(0xffffffffu, a0, off);
        a1 += __shfl_xor_sync(0xffffffffu, a1, off);
        a2 += __shfl_xor_sync(0xffffffffu, a2, off);
        a3 += __shfl_xor_sync(0xffffffffu, a3, off);
    }
    if (lane == 0) {
        bsh[wid * 4 + 0] = a0; bsh[wid * 4 + 1] = a1;
        bsh[wid * 4 + 2] = a2; bsh[wid * 4 + 3] = a3;
    }
    __syncthreads();
    if (tid == 0) {
        float t0 = 0, t1 = 0, t2 = 0, t3 = 0;
        #pragma unroll
        for (int wq = 0; wq < 8; ++wq) {
            t0 += bsh[wq * 4 + 0]; t1 += bsh[wq * 4 + 1];
            t2 += bsh[wq * 4 + 2]; t3 += bsh[wq * 4 + 3];
        }
        *(float4*)&g_beta[(size_t)row * 4] =
            make_float4(sigmoidf_(t0), sigmoidf_(t1), sigmoidf_(t2), sigmoidf_(t3));
    }
}

// ---------------------------------------------------------------------------
// 1b) weight transpose + bf16 split
// ---------------------------------------------------------------------------
__global__ void __launch_bounds__(256) wtrans_kernel(const float* __restrict__ W,
                                                     __nv_bfloat16* __restrict__ Th,
                                                     __nv_bfloat16* __restrict__ Tl,
                                                     int K, int N) {
    __shared__ float tile[32][33];
    const int tx = threadIdx.x & 31, ty = threadIdx.x >> 5;
    const int k0 = blockIdx.y * 32, n0 = blockIdx.x * 32;
    #pragma unroll
    for (int i = 0; i < 32; i += 8)
        tile[ty + i][tx] = W[(size_t)(k0 + ty + i) * N + n0 + tx];
    __syncthreads();
    #pragma unroll
    for (int i = 0; i < 32; i += 8) {
        const float v = tile[tx][ty + i];
        const size_t oi = (size_t)(n0 + ty + i) * K + k0 + tx;
        const __nv_bfloat16 h = __float2bfloat16(v);
        Th[oi] = h;
        Tl[oi] = __float2bfloat16(v - __bfloat162float(h));
    }
}

// ---------------------------------------------------------------------------
// 2) HMMA GEMM (R6 proven: register-prefetch double-buffer)
// ---------------------------------------------------------------------------
#define MG_STAGE 65536
#define MG_SMEM  (2 * MG_STAGE)

__global__ void __launch_bounds__(256, 1)
mma_gemm(const __nv_bfloat16* __restrict__ Ah, const __nv_bfloat16* __restrict__ Al,
         const __nv_bfloat16* __restrict__ Bh, const __nv_bfloat16* __restrict__ Bl,
         float* __restrict__ C, const float* __restrict__ resid,
         int N, int K, int do_silu) {
    extern __shared__ char smx[];
    const uint32_t sbase = smem_u32(smx);
    const int tid = threadIdx.x;
    const int lane = tid & 31;
    const int wid = tid >> 5;
    const int wm = wid >> 2;
    const int wn = wid & 3;
    const int m0w = wm * 64, n0w = wn * 32;

    const size_t bm = (size_t)blockIdx.y * 128;
    const size_t bn = (size_t)blockIdx.x * 128;
    const __nv_bfloat16* pAh = Ah + bm * K;
    const __nv_bfloat16* pAl = Al + bm * K;
    const __nv_bfloat16* pBh = Bh + bn * K;
    const __nv_bfloat16* pBl = Bl + bn * K;

    {
        char* stg = smx;
        #pragma unroll
        for (int p = 0; p < 4; ++p) {
            const int c = tid + (p << 8);
            const int row = c >> 3, ch = c & 7;
            const size_t gi = (size_t)row * K + (ch << 3);
            const int off = (row << 7) + (((ch ^ (row & 7))) << 4);
            *(uint4*)(stg + off)         = *(const uint4*)(pAh + gi);
            *(uint4*)(stg + 16384 + off) = *(const uint4*)(pAl + gi);
            *(uint4*)(stg + 32768 + off) = *(const uint4*)(pBh + gi);
            *(uint4*)(stg + 49152 + off) = *(const uint4*)(pBl + gi);
        }
    }
    __syncthreads();

    float acc[4][4][4];
    #pragma unroll
    for (int i = 0; i < 4; ++i)
        #pragma unroll
        for (int j = 0; j < 4; ++j)
            #pragma unroll
            for (int q = 0; q < 4; ++q) acc[i][j][q] = 0.f;

    const int a_row = m0w + (lane & 15);
    const int a_chs = lane >> 4;
    const int b_row = n0w + ((lane >> 3) & 2) * 4 + (lane & 7);
    const int b_chs = (lane >> 3) & 1;

    const int KB = K >> 6;
    for (int kb = 0; kb < KB; ++kb) {
        const uint32_t stg = sbase + (uint32_t)(kb & 1) * MG_STAGE;
        const bool hasNext = (kb + 1) < KB;

        uint4 vAh[4], vAl[4], vBh[4], vBl[4];
        if (hasNext) {
            const int k0 = (kb + 1) << 6;
            #pragma unroll
            for (int p = 0; p < 4; ++p) {
                const int c = tid + (p << 8);
                const int row = c >> 3, ch = c & 7;
                const size_t gi = (size_t)row * K + k0 + (ch << 3);
                vAh[p] = *(const uint4*)(pAh + gi);
                vAl[p] = *(const uint4*)(pAl + gi);
                vBh[p] = *(const uint4*)(pBh + gi);
                vBl[p] = *(const uint4*)(pBl + gi);
            }
        }

        #pragma unroll
        for (int ks = 0; ks < 4; ++ks) {
            uint32_t afh[4][4], afl[4][4];
            #pragma unroll
            for (int mt = 0; mt < 4; ++mt) {
                const int row = a_row + mt * 16;
                const int ch  = ks * 2 + a_chs;
                const uint32_t off = (uint32_t)((row << 7) + ((ch ^ (row & 7)) << 4));
                ldsm4(afh[mt], stg + off);
                ldsm4(afl[mt], stg + 16384u + off);
            }
            uint32_t bfh[2][4], bfl[2][4];
            #pragma unroll
            for (int np = 0; np < 2; ++np) {
                const int row = b_row + np * 16;
                const int ch  = ks * 2 + b_chs;
                const uint32_t off = (uint32_t)((row << 7) + ((ch ^ (row & 7)) << 4));
                ldsm4(bfh[np], stg + 32768u + off);
                ldsm4(bfl[np], stg + 49152u + off);
            }
            #pragma unroll
            for (int mt = 0; mt < 4; ++mt) {
                #pragma unroll
                for (int nt = 0; nt < 4; ++nt) {
                    const uint32_t* bh = &bfh[nt >> 1][(nt & 1) * 2];
                    const uint32_t* bl = &bfl[nt >> 1][(nt & 1) * 2];
                    mma16816(acc[mt][nt], afh[mt], bh);
                    mma16816(acc[mt][nt], afh[mt], bl);
                    mma16816(acc[mt][nt], afl[mt], bh);
                }
            }
        }

        if (hasNext) {
            char* nst = smx + ((kb + 1) & 1) * MG_STAGE;
            #pragma unroll
            for (int p = 0; p < 4; ++p) {
                const int c = tid + (p << 8);
                const int row = c >> 3, ch = c & 7;
                const int off = (row << 7) + ((ch ^ (row & 7)) << 4);
                *(uint4*)(nst + off)         = vAh[p];
                *(uint4*)(nst + 16384 + off) = vAl[p];
                *(uint4*)(nst + 32768 + off) = vBh[p];
                *(uint4*)(nst + 49152 + off) = vBl[p];
            }
        }
        __syncthreads();
    }

    const int erow = lane >> 2;
    const int ecol = (lane & 3) * 2;
    #pragma unroll
    for (int mt = 0; mt < 4; ++mt) {
        #pragma unroll
        for (int nt = 0; nt < 4; ++nt) {
            const size_t gr0 = bm + m0w + mt * 16 + erow;
            const size_t gc  = bn + n0w + nt * 8 + ecol;
            float v0 = acc[mt][nt][0], v1 = acc[mt][nt][1];
            float v2 = acc[mt][nt][2], v3 = acc[mt][nt][3];
            if (do_silu) { v0 = siluf_(v0); v1 = siluf_(v1); v2 = siluf_(v2); v3 = siluf_(v3); }
            if (resid != nullptr) {
                const float2 r0 = *(const float2*)&resid[gr0 * N + gc];
                const float2 r1 = *(const float2*)&resid[(gr0 + 8) * N + gc];
                v0 += r0.x; v1 += r0.y; v2 += r1.x; v3 += r1.y;
            }
            float2 w0; w0.x = v0; w0.y = v1;
            float2 w1; w1.x = v2; w1.y = v3;
            *(float2*)&C[gr0 * N + gc]       = w0;
            *(float2*)&C[(gr0 + 8) * N + gc] = w1;
        }
    }
}

// ---------------------------------------------------------------------------
// 5a) prep1 (includes l2norm of k and q, q additionally * DK^-0.5)
// ---------------------------------------------------------------------------
#define P1_FLOATS (17408 + 17408 + 4352 + 64 + 64 + 272)
#define P1_BYTES  (P1_FLOATS * 4)

__global__ void __launch_bounds__(256, 1) prep1_kernel() {
    extern __shared__ float sm1[];
    float* Kt  = sm1;            // [256][68]
    float* wb  = sm1 + 17408;    // [64][260]
    float* Qts = sm1 + 17408;    // [256][68]  (aliases wb)
    float* Ms  = sm1 + 34816;    // [64][68]
    float* bsm = sm1 + 39168;    // [64]
    float* rsk = sm1 + 39232;    // [64]
    float* nrm = sm1 + 39296;    // [4][68]

    const int tid  = threadIdx.x;
    const int cIdx = blockIdx.x;
    const int n = cIdx & 31, h = (cIdx >> 5) & 3, b = cIdx >> 7;
    const size_t m0 = (size_t)b * T_ + n * C_;
    const int hK = h * DK_;

    if (tid < 64) bsm[tid] = g_beta[(m0 + tid) * H_ + h];

    #pragma unroll 4
    for (int p = 0; p < 16; ++p) {
        const int idx = tid + p * 256;
        const int i = idx >> 6, c4 = idx & 63;
        const float4 v = *(const float4*)&g_k[(m0 + i) * NKV + hK + c4 * 4];
        Kt[(c4 * 4 + 0) * 68 + i] = v.x;
        Kt[(c4 * 4 + 1) * 68 + i] = v.y;
        Kt[(c4 * 4 + 2) * 68 + i] = v.z;
        Kt[(c4 * 4 + 3) * 68 + i] = v.w;
    }
    __syncthreads();

    {
        const int i = tid & 63, part = tid >> 6;
        float ss = 0.f;
        #pragma unroll 4
        for (int kk = part * 64; kk < part * 64 + 64; ++kk) {
            const float vv = Kt[kk * 68 + i];
            ss += vv * vv;
        }
        nrm[part * 68 + i] = ss;
    }
    __syncthreads();
    if (tid < 64)
        rsk[tid] = rsqrtf(nrm[tid] + nrm[68 + tid] + nrm[136 + tid] + nrm[204 + tid] + 1e-6f);
    __syncthreads();
    for (int idx = tid; idx < 4352; idx += 256) {
        const int kk = idx / 17, f4 = idx % 17;
        if (f4 < 16) {
            float4 v = *(float4*)&Kt[kk * 68 + f4 * 4];
            const float4 r = *(const float4*)&rsk[f4 * 4];
            v.x *= r.x; v.y *= r.y; v.z *= r.z; v.w *= r.w;
            *(float4*)&Kt[kk * 68 + f4 * 4] = v;
        }
    }
    __syncthreads();

    const int ty = tid >> 4, tx = tid & 15;
    const int ti4 = ty * 4, tj4 = tx * 4;

    #pragma unroll 4
    for (int p = 0; p < 16; ++p) {
        const int idx = tid + p * 256;
        const int i = idx >> 6, c4 = idx & 63;
        const float bb = bsm[i];
        float4 v;
        v.x = bb * Kt[(c4 * 4 + 0) * 68 + i];
        v.y = bb * Kt[(c4 * 4 + 1) * 68 + i];
        v.z = bb * Kt[(c4 * 4 + 2) * 68 + i];
        v.w = bb * Kt[(c4 * 4 + 3) * 68 + i];
        *(float4*)&wb[i * 260 + c4 * 4] = v;
    }

    {
        ull acc[4][2] = {};
        #pragma unroll 4
        for (int kk = 0; kk < 256; ++kk) {
            const float4 a4 = *(const float4*)&Kt[kk * 68 + ti4];
            const float4 b4 = *(const float4*)&Kt[kk * 68 + tj4];
            mma4x4p(acc, a4, pack2(b4.x, b4.y), pack2(b4.z, b4.w));
        }
        float mo[4][4]; unp4x4(acc, mo);
        #pragma unroll
        for (int r = 0; r < 4; ++r) {
            const int i = ti4 + r;
            const float bi = bsm[i];
            #pragma unroll
            for (int cc = 0; cc < 4; ++cc) {
                const int j = tj4 + cc;
                Ms[i * 68 + j] = (j < i) ? bi * mo[r][cc] : 0.f;
            }
        }
    }

    {
        __nv_bfloat16* kth = g_cKth + (size_t)cIdx * 16384;
        __nv_bfloat16* ktl = g_cKtl + (size_t)cIdx * 16384;
        for (int idx = tid; idx < 8192; idx += 256) {
            const int kk = idx >> 5, i2 = (idx & 31) * 2;
            uint32_t hi, lo;
            split2(Kt[kk * 68 + i2], Kt[kk * 68 + i2 + 1], hi, lo);
            *(uint32_t*)(kth + kk * 64 + i2) = hi;
            *(uint32_t*)(ktl + kk * 64 + i2) = lo;
        }
    }
    __syncthreads();

    for (int i = 1; i < 64; ++i) {
        const float* mr = Ms + i * 68;
        float a0 = 0.f, a1 = 0.f, a2 = 0.f, a3 = 0.f;
        int j = 0;
        for (; j + 4 <= i; j += 4) {
            a0 += mr[j + 0] * wb[(j + 0) * 260 + tid];
            a1 += mr[j + 1] * wb[(j + 1) * 260 + tid];
            a2 += mr[j + 2] * wb[(j + 2) * 260 + tid];
            a3 += mr[j + 3] * wb[(j + 3) * 260 + tid];
        }
        for (; j < i; ++j) a0 += mr[j] * wb[j * 260 + tid];
        wb[i * 260 + tid] -= (a0 + a1) + (a2 + a3);
        __syncthreads();
    }

    {
        __nv_bfloat16* wh = g_cWh + (size_t)cIdx * 16384;
        __nv_bfloat16* wl = g_cWl + (size_t)cIdx * 16384;
        for (int idx = tid; idx < 8192; idx += 256) {
            const int i = idx >> 7, kk2 = (idx & 127) * 2;
            uint32_t hi, lo;
            split2(wb[i * 260 + kk2], wb[i * 260 + kk2 + 1], hi, lo);
            *(uint32_t*)(wh + i * 256 + kk2) = hi;
            *(uint32_t*)(wl + i * 256 + kk2) = lo;
        }
        float* mo = g_mlt + (size_t)cIdx * (C_ * C_);
        for (int idx = tid; idx < C_ * C_; idx += 256)
            mo[idx] = Ms[(idx >> 6) * 68 + (idx & 63)];
    }
    __syncthreads();   // wb dead; Qts may now overwrite

    #pragma unroll 4
    for (int p = 0; p < 16; ++p) {
        const int idx = tid + p * 256;
        const int i = idx >> 6, c4 = idx & 63;
        const float4 v = *(const float4*)&g_q[(m0 + i) * NKV + hK + c4 * 4];
        Qts[(c4 * 4 + 0) * 68 + i] = v.x;
        Qts[(c4 * 4 + 1) * 68 + i] = v.y;
        Qts[(c4 * 4 + 2) * 68 + i] = v.z;
        Qts[(c4 * 4 + 3) * 68 + i] = v.w;
    }
    __syncthreads();

    {
        const int i = tid & 63, part = tid >> 6;
        float ss = 0.f;
        #pragma unroll 4
        for (int kk = part * 64; kk < part * 64 + 64; ++kk) {
            const float vv = Qts[kk * 68 + i];
            ss += vv * vv;
        }
        nrm[part * 68 + i] = ss;
    }
    __syncthreads();
    if (tid < 64)
        rsk[tid] = rsqrtf(nrm[tid] + nrm[68 + tid] + nrm[136 + tid] + nrm[204 + tid] + 1e-6f) * 0.0625f;
    __syncthreads();
    for (int idx = tid; idx < 4352; idx += 256) {
        const int kk = idx / 17, f4 = idx % 17;
        if (f4 < 16) {
            float4 v = *(float4*)&Qts[kk * 68 + f4 * 4];
            const float4 r = *(const float4*)&rsk[f4 * 4];
            v.x *= r.x; v.y *= r.y; v.z *= r.z; v.w *= r.w;
            *(float4*)&Qts[kk * 68 + f4 * 4] = v;
        }
    }
    __syncthreads();

    {
        __nv_bfloat16* qh = g_cQh + (size_t)cIdx * 16384;
        __nv_bfloat16* ql = g_cQl + (size_t)cIdx * 16384;
        for (int idx = tid; idx < 8192; idx += 256) {
            const int i = idx >> 7, kk2 = (idx & 127) * 2;
            uint32_t hi, lo;
            split2(Qts[kk2 * 68 + i], Qts[(kk2 + 1) * 68 + i], hi, lo);
            *(uint32_t*)(qh + i * 256 + kk2) = hi;
            *(uint32_t*)(ql + i * 256 + kk2) = lo;
        }
    }

    {
        ull acc[4][2] = {};
        #pragma unroll 4
        for (int kk = 0; kk < 256; ++kk) {
            const float4 a4 = *(const float4*)&Qts[kk * 68 + ti4];
            const float4 b4 = *(const float4*)&Kt[kk * 68 + tj4];
            mma4x4p(acc, a4, pack2(b4.x, b4.y), pack2(b4.z, b4.w));
        }
        float po[4][4]; unp4x4(acc, po);
        __nv_bfloat16* ph = g_cPh + (size_t)cIdx * 4096;
        __nv_bfloat16* pl = g_cPl + (size_t)cIdx * 4096;
        #pragma unroll
        for (int r = 0; r < 4; ++r) {
            const int i = ti4 + r;
            const float v0 = (tj4 + 0 <= i) ? po[r][0] : 0.f;
            const float v1 = (tj4 + 1 <= i) ? po[r][1] : 0.f;
            const float v2 = (tj4 + 2 <= i) ? po[r][2] : 0.f;
            const float v3 = (tj4 + 3 <= i) ? po[r][3] : 0.f;
            uint32_t hi, lo;
            split2(v0, v1, hi, lo);
            *(uint32_t*)(ph + i * 64 + tj4)     = hi;
            *(uint32_t*)(pl + i * 64 + tj4)     = lo;
            split2(v2, v3, hi, lo);
            *(uint32_t*)(ph + i * 64 + tj4 + 2) = hi;
            *(uint32_t*)(pl + i * 64 + tj4 + 2) = lo;
        }
    }
}

// ---------------------------------------------------------------------------
// 5b) prep2: Uv = (I+M)^{-1} (beta V)  -> g_Uv (unchanged)
// ---------------------------------------------------------------------------
#define P2_FLOATS (33280 + 4352 + 64)
#define P2_BYTES  (P2_FLOATS * 4)

__global__ void __launch_bounds__(256, 1) prep2_kernel() {
    extern __shared__ float sm2[];
    float* vb  = sm2;            // [64][520]
    float* Ms  = sm2 + 33280;    // [64][68]
    float* bsm = sm2 + 33280 + 4352;

    const int tid  = threadIdx.x;
    const int cIdx = blockIdx.x;
    const int n = cIdx & 31, h = (cIdx >> 5) & 3, b = cIdx >> 7;
    const size_t m0 = (size_t)b * T_ + n * C_;
    const int hV = h * DV_;

    if (tid < 64) bsm[tid] = g_beta[(m0 + tid) * H_ + h];
    {
        const float* mg = g_mlt + (size_t)cIdx * (C_ * C_);
        for (int idx = tid; idx < C_ * C_; idx += 256)
            Ms[(idx >> 6) * 68 + (idx & 63)] = mg[idx];
    }
    __syncthreads();

    #pragma unroll 4
    for (int p = 0; p < 32; ++p) {
        const int idx = tid + p * 256;
        const int i = idx >> 7, c4 = idx & 127;
        float4 v = *(const float4*)&g_v[(m0 + i) * NV + hV + c4 * 4];
        const float bb = bsm[i];
        v.x *= bb; v.y *= bb; v.z *= bb; v.w *= bb;
        *(float4*)&vb[i * 520 + c4 * 4] = v;
    }
    __syncthreads();

    const int col2 = 2 * tid;
    for (int i = 1; i < 64; ++i) {
        const float* mr = Ms + i * 68;
        ull acc = 0ull;
        for (int j = 0; j < i; ++j) {
            const float m = mr[j];
            const ull v = *(const ull*)&vb[j * 520 + col2];
            ffma2(acc, pack2(m, m), v);
        }
        float ax, ay; unpack2(acc, ax, ay);
        vb[i * 520 + col2]     -= ax;
        vb[i * 520 + col2 + 1] -= ay;
        __syncthreads();
    }

    float* uo = g_Uv + (size_t)cIdx * (C_ * DV_);
    #pragma unroll 4
    for (int p = 0; p < 32; ++p) {
        const int idx = tid + p * 256;
        const int i = idx >> 7, c4 = idx & 127;
        *(float4*)&uo[i * DV_ + c4 * 4] = *(const float4*)&vb[i * 520 + c4 * 4];
    }
}

// ---------------------------------------------------------------------------
// 5c) chunkscan (HMMA, 512 threads / 16 warps, warp grid 4x4 — R9 best)
// ---------------------------------------------------------------------------
#define CST 512
#define CS2_SH   69632
#define CS2_SL   102400
#define CS2_UH   135168
#define CS2_UL   143360
#define CS2_UVS  151552
#define CS2_STG  168960
#define CS2_BYTES 201728

__global__ void __launch_bounds__(CST, 1) chunkscan_kernel() {
    extern __shared__ char sm3[];
    float* SF  = (float*)sm3;                 // [256][68] fp32
    char*  SH  = sm3 + CS2_SH;                // [256][64] bf16 swizzled
    char*  SL  = sm3 + CS2_SL;
    char*  UH  = sm3 + CS2_UH;                // [64][64] bf16 swizzled
    char*  UL  = sm3 + CS2_UL;
    float* UVS = (float*)(sm3 + CS2_UVS);     // [64][68] fp32
    char*  STG = sm3 + CS2_STG;               // 4 x 8192B tiles

    const uint32_t stg_u = smem_u32(STG);
    const uint32_t sh_u  = smem_u32(SH);
    const uint32_t sl_u  = smem_u32(SL);
    const uint32_t uh_u  = smem_u32(UH);
    const uint32_t ul_u  = smem_u32(UL);

    const int tid  = threadIdx.x;
    const int lane = tid & 31, wid = tid >> 5;      // 16 warps
    const int wm = wid >> 2, wn = wid & 3;          // 4 x 4
    const int erow = lane >> 2, ecol = (lane & 3) * 2;
    const int lrow = lane & 15, lhi = lane >> 4;
    const int c = blockIdx.x & 7, h = (blockIdx.x >> 3) & 3, b = blockIdx.x >> 5;
    const int dv0 = c * 64;
    const int srow = tid >> 3, sch = tid & 7;       // staging role (512 = 64 rows x 8 ch)
    const uint32_t sso = swz(srow, sch);

    for (int i = tid; i < 17408; i += CST) SF[i] = 0.f;
    for (int i = tid; i < 8192; i += CST) { ((uint32_t*)SH)[i] = 0u; ((uint32_t*)SL)[i] = 0u; }
    __syncthreads();

    for (int n = 0; n < NC_; ++n) {
        const int cIdx = b * 128 + h * 32 + n;
        const __nv_bfloat16* Wh  = g_cWh  + (size_t)cIdx * 16384;
        const __nv_bfloat16* Wl  = g_cWl  + (size_t)cIdx * 16384;
        const __nv_bfloat16* Qh  = g_cQh  + (size_t)cIdx * 16384;
        const __nv_bfloat16* Ql  = g_cQl  + (size_t)cIdx * 16384;
        const __nv_bfloat16* Kth = g_cKth + (size_t)cIdx * 16384;
        const __nv_bfloat16* Ktl = g_cKtl + (size_t)cIdx * 16384;
        const __nv_bfloat16* Ph  = g_cPh  + (size_t)cIdx * 4096;
        const __nv_bfloat16* Pl  = g_cPl  + (size_t)cIdx * 4096;
        const float* Uvg = g_Uv + (size_t)cIdx * 32768 + dv0;
        const size_t m0  = (size_t)b * T_ + n * 64;

        // stage W/Q block 0 + Uv
        {
            const size_t gi = (size_t)srow * 256 + sch * 8;
            *(uint4*)(STG + sso)         = *(const uint4*)(Wh + gi);
            *(uint4*)(STG + 8192 + sso)  = *(const uint4*)(Wl + gi);
            *(uint4*)(STG + 16384 + sso) = *(const uint4*)(Qh + gi);
            *(uint4*)(STG + 24576 + sso) = *(const uint4*)(Ql + gi);
        }
        #pragma unroll
        for (int j = 0; j < 2; ++j) {
            const int idx = tid + j * CST;
            const int r = idx >> 4, c4 = idx & 15;
            *(float4*)&UVS[r * 68 + c4 * 4] = *(const float4*)&Uvg[(size_t)r * DV_ + c4 * 4];
        }
        __syncthreads();

        float accU[2][4] = {}, accO[2][4] = {};

        // GEMM1+2a: accU = W·S, accO = Q·S over 4 kk-blocks
        for (int kb = 0; kb < 4; ++kb) {
            uint4 pf[4];
            if (kb < 3) {
                const size_t gi = (size_t)srow * 256 + (kb + 1) * 64 + sch * 8;
                pf[0] = *(const uint4*)(Wh + gi);
                pf[1] = *(const uint4*)(Wl + gi);
                pf[2] = *(const uint4*)(Qh + gi);
                pf[3] = *(const uint4*)(Ql + gi);
            }
            #pragma unroll
            for (int ks = 0; ks < 4; ++ks) {
                uint32_t wfh[4], wfl[4], qfh[4], qfl[4];
                const int ar = wm * 16 + lrow;
                const uint32_t ao = swz(ar, ks * 2 + lhi);
                ldsm4(wfh, stg_u + ao);
                ldsm4(wfl, stg_u + 8192u + ao);
                ldsm4(qfh, stg_u + 16384u + ao);
                ldsm4(qfl, stg_u + 24576u + ao);
                uint32_t sfh[4], sfl[4];
                const int br = kb * 64 + ks * 16 + lrow;
                const uint32_t bo = swz(br, wn * 2 + lhi);
                ldsm4t(sfh, sh_u + bo);
                ldsm4t(sfl, sl_u + bo);
                #pragma unroll
                for (int nt = 0; nt < 2; ++nt) {
                    mma16816(accU[nt], wfh, sfh + nt * 2);
                    mma16816(accU[nt], wfh, sfl + nt * 2);
                    mma16816(accU[nt], wfl, sfh + nt * 2);
                    mma16816(accO[nt], qfh, sfh + nt * 2);
                    mma16816(accO[nt], qfh, sfl + nt * 2);
                    mma16816(accO[nt], qfl, sfh + nt * 2);
                }
            }
            __syncthreads();
            if (kb < 3) {
                *(uint4*)(STG + sso)         = pf[0];
                *(uint4*)(STG + 8192 + sso)  = pf[1];
                *(uint4*)(STG + 16384 + sso) = pf[2];
                *(uint4*)(STG + 24576 + sso) = pf[3];
                __syncthreads();
            }
        }

        // U finalize (u = Uv - accU) -> UH/UL
        #pragma unroll
        for (int nt = 0; nt < 2; ++nt) {
            const int r0 = wm * 16 + erow;
            const int cc = wn * 16 + nt * 8 + ecol;
            const float u0 = UVS[r0 * 68 + cc]           - accU[nt][0];
            const float u1 = UVS[r0 * 68 + cc + 1]       - accU[nt][1];
            const float u2 = UVS[(r0 + 8) * 68 + cc]     - accU[nt][2];
            const float u3 = UVS[(r0 + 8) * 68 + cc + 1] - accU[nt][3];
            uint32_t hi, lo;
            split2(u0, u1, hi, lo);
            *(uint32_t*)(UH + swzb(r0, cc)) = hi;
            *(uint32_t*)(UL + swzb(r0, cc)) = lo;
            split2(u2, u3, hi, lo);
            *(uint32_t*)(UH + swzb(r0 + 8, cc)) = hi;
            *(uint32_t*)(UL + swzb(r0 + 8, cc)) = lo;
        }
        // stage P -> T0/T1, Kt block0 -> T2/T3
        {
            const size_t gp = (size_t)srow * 64 + sch * 8;
            *(uint4*)(STG + sso)         = *(const uint4*)(Ph + gp);
            *(uint4*)(STG + 8192 + sso)  = *(const uint4*)(Pl + gp);
            *(uint4*)(STG + 16384 + sso) = *(const uint4*)(Kth + gp);
            *(uint4*)(STG + 24576 + sso) = *(const uint4*)(Ktl + gp);
        }
        __syncthreads();

        // hoist U B-fragments for all 4 k-steps (shared by GEMM2b and GEMM3)
        uint32_t ufh[4][4], ufl[4][4];
        #pragma unroll
        for (int ks = 0; ks < 4; ++ks) {
            const int br = ks * 16 + lrow;
            const uint32_t bo = swz(br, wn * 2 + lhi);
            ldsm4t(ufh[ks], uh_u + bo);
            ldsm4t(ufl[ks], ul_u + bo);
        }

        // GEMM2b: accO += P·U
        #pragma unroll
        for (int ks = 0; ks < 4; ++ks) {
            uint32_t pfh[4], pfl[4];
            const int ar = wm * 16 + lrow;
            const uint32_t ao = swz(ar, ks * 2 + lhi);
            ldsm4(pfh, stg_u + ao);
            ldsm4(pfl, stg_u + 8192u + ao);
            #pragma unroll
            for (int nt = 0; nt < 2; ++nt) {
                mma16816(accO[nt], pfh, ufh[ks] + nt * 2);
                mma16816(accO[nt], pfh, ufl[ks] + nt * 2);
                mma16816(accO[nt], pfl, ufh[ks] + nt * 2);
            }
        }

        // O epilogue -> global
        #pragma unroll
        for (int nt = 0; nt < 2; ++nt) {
            const int r0 = wm * 16 + erow;
            const int cc = wn * 16 + nt * 8 + ecol;
            float2 w0; w0.x = accO[nt][0]; w0.y = accO[nt][1];
            float2 w1; w1.x = accO[nt][2]; w1.y = accO[nt][3];
            *(float2*)&g_o[(m0 + r0) * NV + h * DV_ + dv0 + cc]     = w0;
            *(float2*)&g_o[(m0 + r0 + 8) * NV + h * DV_ + dv0 + cc] = w1;
        }
        __syncthreads();   // retire P reads (T0/T1) before GEMM3 stores there

        // GEMM3: S += K^T · U, 4 kk-blocks, double-buffered halves
        for (int kkb = 0; kkb < 4; ++kkb) {
            float accS[2][4] = {};
            uint4 kf[2];
            if (kkb < 3) {
                const size_t gi = (size_t)((kkb + 1) * 64 + srow) * 64 + sch * 8;
                kf[0] = *(const uint4*)(Kth + gi);
                kf[1] = *(const uint4*)(Ktl + gi);
            }
            const uint32_t curH = stg_u + ((kkb & 1) ? 0u : 16384u);
            const uint32_t curL = stg_u + ((kkb & 1) ? 8192u : 24576u);
            #pragma unroll
            for (int ks = 0; ks < 4; ++ks) {
                uint32_t kfh[4], kfl[4];
                const int ar = wm * 16 + lrow;
                const uint32_t ao = swz(ar, ks * 2 + lhi);
                ldsm4(kfh, curH + ao);
                ldsm4(kfl, curL + ao);
                #pragma unroll
                for (int nt = 0; nt < 2; ++nt) {
                    mma16816(accS[nt], kfh, ufh[ks] + nt * 2);
                    mma16816(accS[nt], kfh, ufl[ks] + nt * 2);
                    mma16816(accS[nt], kfl, ufh[ks] + nt * 2);
                }
            }
            // S finalize: fp32 RMW + bf16 re-split for this 64-row block
            #pragma unroll
            for (int nt = 0; nt < 2; ++nt) {
                const int sr = kkb * 64 + wm * 16 + erow;
                const int sc = wn * 16 + nt * 8 + ecol;
                const float s0 = SF[sr * 68 + sc]           + accS[nt][0];
                const float s1 = SF[sr * 68 + sc + 1]       + accS[nt][1];
                const float s2 = SF[(sr + 8) * 68 + sc]     + accS[nt][2];
                const float s3 = SF[(sr + 8) * 68 + sc + 1] + accS[nt][3];
                SF[sr * 68 + sc]           = s0;
                SF[sr * 68 + sc + 1]       = s1;
                SF[(sr + 8) * 68 + sc]     = s2;
                SF[(sr + 8) * 68 + sc + 1] = s3;
                uint32_t hi, lo;
                split2(s0, s1, hi, lo);
                *(uint32_t*)(SH + swzb(sr, sc)) = hi;
                *(uint32_t*)(SL + swzb(sr, sc)) = lo;
                split2(s2, s3, hi, lo);
                *(uint32_t*)(SH + swzb(sr + 8, sc)) = hi;
                *(uint32_t*)(SL + swzb(sr + 8, sc)) = lo;
            }
            __syncthreads();
            if (kkb < 3) {
                char* oH = STG + ((kkb & 1) ? 16384 : 0);
                char* oL = STG + ((kkb & 1) ? 24576 : 8192);
                *(uint4*)(oH + sso) = kf[0];
                *(uint4*)(oL + sso) = kf[1];
                __syncthreads();
            }
        }
    }
}

// ---------------------------------------------------------------------------
// 6) per-head RMSNorm on g_o -> bf16 split g_oh/g_ol
// ---------------------------------------------------------------------------
__global__ void __launch_bounds__(256) rmsnorm_kernel(const float* __restrict__ w) {
    const int grp  = blockIdx.x * 8 + (threadIdx.x >> 5);
    const int lane = threadIdx.x & 31;
    const float* base = g_o + (size_t)grp * DV_;
    float4 v[4];
    float ss = 0.f;
    #pragma unroll
    for (int i = 0; i < 4; ++i) {
        v[i] = ((const float4*)base)[lane + 32 * i];
        ss += v[i].x * v[i].x + v[i].y * v[i].y + v[i].z * v[i].z + v[i].w * v[i].w;
    }
    #pragma unroll
    for (int off = 16; off > 0; off >>= 1) ss += __shfl_xor_sync(0xffffffffu, ss, off);
    const float rs = rsqrtf(ss * (1.0f / DV_) + 1e-5f);
    #pragma unroll
    for (int i = 0; i < 4; ++i) {
        const int idx = lane + 32 * i;
        const float4 wv = ((const float4*)w)[idx];
        const float4 o = make_float4(v[i].x * rs * wv.x, v[i].y * rs * wv.y,
                                     v[i].z * rs * wv.z, v[i].w * rs * wv.w);
        split_store4(o, g_oh, g_ol, (size_t)grp * DV_ + (size_t)idx * 4);
    }
}

// ---------------------------------------------------------------------------
// Launch
// ---------------------------------------------------------------------------
extern "C" void kernel_launch(void* const* d_in, const int* in_sizes, int n_in,
                              void* d_out, int out_size) {
    const float* x        = (const float*)d_in[0];
    const float* ln_w     = (const float*)d_in[1];
    const float* ln_b     = (const float*)d_in[2];
    const float* Wq       = (const float*)d_in[3];
    const float* Wk       = (const float*)d_in[4];
    const float* Wv       = (const float*)d_in[5];
    const float* Wb       = (const float*)d_in[6];
    const float* o_norm_w = (const float*)d_in[7];
    const float* Wo       = (const float*)d_in[8];
    float* out = (float*)d_out;

    cudaFuncSetAttribute(mma_gemm, cudaFuncAttributeMaxDynamicSharedMemorySize, MG_SMEM);
    cudaFuncSetAttribute(prep1_kernel, cudaFuncAttributeMaxDynamicSharedMemorySize, P1_BYTES);
    cudaFuncSetAttribute(prep2_kernel, cudaFuncAttributeMaxDynamicSharedMemorySize, P2_BYTES);
    cudaFuncSetAttribute(chunkscan_kernel, cudaFuncAttributeMaxDynamicSharedMemorySize, CS2_BYTES);

    __nv_bfloat16 *nh, *nl, *oh, *ol, *wqh, *wql, *wkh, *wkl, *wvh, *wvl, *woh, *wol;
    cudaGetSymbolAddress((void**)&nh,  g_nh);
    cudaGetSymbolAddress((void**)&nl,  g_nl);
    cudaGetSymbolAddress((void**)&oh,  g_oh);
    cudaGetSymbolAddress((void**)&ol,  g_ol);
    cudaGetSymbolAddress((void**)&wqh, g_Wqt_h);
    cudaGetSymbolAddress((void**)&wql, g_Wqt_l);
    cudaGetSymbolAddress((void**)&wkh, g_Wkt_h);
    cudaGetSymbolAddress((void**)&wkl, g_Wkt_l);
    cudaGetSymbolAddress((void**)&wvh, g_Wvt_h);
    cudaGetSymbolAddress((void**)&wvl, g_Wvt_l);
    cudaGetSymbolAddress((void**)&woh, g_Wot_h);
    cudaGetSymbolAddress((void**)&wol, g_Wot_l);
    float *gq, *gk, *gv;
    cudaGetSymbolAddress((void**)&gq, g_q);
    cudaGetSymbolAddress((void**)&gk, g_k);
    cudaGetSymbolAddress((void**)&gv, g_v);

    // 1) LayerNorm (+ bf16 split of normed, + fused beta)
    ln_kernel<<<M_, 256>>>(x, ln_w, ln_b, Wb);

    // 1b) weight transpose+split
    wtrans_kernel<<<dim3(NKV / 32, D_ / 32), 256>>>(Wq, wqh, wql, D_, NKV);
    wtrans_kernel<<<dim3(NKV / 32, D_ / 32), 256>>>(Wk, wkh, wkl, D_, NKV);
    wtrans_kernel<<<dim3(NV  / 32, D_ / 32), 256>>>(Wv, wvh, wvl, D_, NV);
    wtrans_kernel<<<dim3(D_  / 32, NV / 32), 256>>>(Wo, woh, wol, NV, D_);

    // 2) projections (HMMA, silu fused)
    mma_gemm<<<dim3(NKV / 128, M_ / 128), 256, MG_SMEM>>>(nh, nl, wqh, wql, gq, nullptr, NKV, D_, 1);
    mma_gemm<<<dim3(NKV / 128, M_ / 128), 256, MG_SMEM>>>(nh, nl, wkh, wkl, gk, nullptr, NKV, D_, 1);
    mma_gemm<<<dim3(NV  / 128, M_ / 128), 256, MG_SMEM>>>(nh, nl, wvh, wvl, gv, nullptr, NV,  D_, 1);

    // 5) chunked delta-rule (prep1 includes l2norm of q/k)
    prep1_kernel<<<NCH, 256, P1_BYTES>>>();
    prep2_kernel<<<NCH, 256, P2_BYTES>>>();
    chunkscan_kernel<<<B_ * H_ * 8, CST, CS2_BYTES>>>();

    // 6) RMSNorm (+ bf16 split of o)
    rmsnorm_kernel<<<(M_ * H_) / 8, 256>>>(o_norm_w);

    // 7) output projection + residual (HMMA)
    mma_gemm<<<dim3(D_ / 128, M_ / 128), 256, MG_SMEM>>>(oh, ol, woh, wol, out, x, D_, NV, 0);
}

// round 14
// speedup vs baseline: 1.0729x; 1.0231x over previous
#include <cuda_runtime.h>
#include <cuda_bf16.h>
#include <cstdint>

// Problem constants (fixed shapes)
#define B_  4
#define T_  2048
#define D_  1024
#define H_  4
#define DK_ 256
#define DV_ 512
#define M_  (B_ * T_)        // 8192 rows
#define NKV (H_ * DK_)       // 1024
#define NV  (H_ * DV_)       // 2048
#define NQKV 4096            // q(1024) | k(1024) | v(2048)
#define C_   64              // chunk length
#define NC_  32              // chunks per sequence
#define NCH  (B_ * H_ * NC_) // 512 chunk instances

typedef unsigned long long ull;

// ---------------------------------------------------------------------------
// Scratch (device globals; no dynamic allocation allowed)
// ---------------------------------------------------------------------------
__device__ float g_qkv[(size_t)M_ * NQKV];       // fused q|k|v projections
__device__ float g_beta[(size_t)M_ * H_];
__device__ float g_o[(size_t)M_ * NV];
// chunked-scan intermediates
__device__ float g_mlt[(size_t)NCH * C_ * C_];   // [cIdx][i][j]  strict tril
__device__ float g_Uv [(size_t)NCH * C_ * DV_];  // [cIdx][i][dv] fp32
// split-bf16 chunkscan operands (written by prep1)
__device__ __nv_bfloat16 g_cWh [(size_t)NCH * C_ * DK_];  // [cIdx][i][kk]
__device__ __nv_bfloat16 g_cWl [(size_t)NCH * C_ * DK_];
__device__ __nv_bfloat16 g_cQh [(size_t)NCH * C_ * DK_];  // [cIdx][i][kk]
__device__ __nv_bfloat16 g_cQl [(size_t)NCH * C_ * DK_];
__device__ __nv_bfloat16 g_cKth[(size_t)NCH * DK_ * C_];  // [cIdx][kk][i]
__device__ __nv_bfloat16 g_cKtl[(size_t)NCH * DK_ * C_];
__device__ __nv_bfloat16 g_cPh [(size_t)NCH * C_ * C_];   // [cIdx][i][j]
__device__ __nv_bfloat16 g_cPl [(size_t)NCH * C_ * C_];
// bf16 split operands for projection GEMMs
__device__ __nv_bfloat16 g_nh[(size_t)M_ * D_];
__device__ __nv_bfloat16 g_nl[(size_t)M_ * D_];
__device__ __nv_bfloat16 g_oh[(size_t)M_ * NV];
__device__ __nv_bfloat16 g_ol[(size_t)M_ * NV];
__device__ __nv_bfloat16 g_Wqkvt_h[(size_t)NQKV * D_];    // [q|k|v rows][K]
__device__ __nv_bfloat16 g_Wqkvt_l[(size_t)NQKV * D_];
__device__ __nv_bfloat16 g_Wot_h[(size_t)D_ * NV];
__device__ __nv_bfloat16 g_Wot_l[(size_t)D_ * NV];

// ---------------------------------------------------------------------------
// f32x2 packed-FMA helpers (prep kernels)
// ---------------------------------------------------------------------------
__device__ __forceinline__ ull pack2(float x, float y) {
    ull r; asm("mov.b64 %0, {%1, %2};" : "=l"(r) : "f"(x), "f"(y)); return r;
}
__device__ __forceinline__ void unpack2(ull v, float& x, float& y) {
    asm("mov.b64 {%0, %1}, %2;" : "=f"(x), "=f"(y) : "l"(v));
}
__device__ __forceinline__ void ffma2(ull& d, ull a, ull b) {
    asm("fma.rn.f32x2 %0, %1, %2, %0;" : "+l"(d) : "l"(a), "l"(b));
}
__device__ __forceinline__ void mma4x4p(ull (&acc)[4][2], const float4 a4,
                                        const ull b0, const ull b1) {
    ull a;
    a = pack2(a4.x, a4.x); ffma2(acc[0][0], a, b0); ffma2(acc[0][1], a, b1);
    a = pack2(a4.y, a4.y); ffma2(acc[1][0], a, b0); ffma2(acc[1][1], a, b1);
    a = pack2(a4.z, a4.z); ffma2(acc[2][0], a, b0); ffma2(acc[2][1], a, b1);
    a = pack2(a4.w, a4.w); ffma2(acc[3][0], a, b0); ffma2(acc[3][1], a, b1);
}
__device__ __forceinline__ void unp4x4(const ull (&acc)[4][2], float (&o)[4][4]) {
    #pragma unroll
    for (int r = 0; r < 4; ++r) {
        unpack2(acc[r][0], o[r][0], o[r][1]);
        unpack2(acc[r][1], o[r][2], o[r][3]);
    }
}

__device__ __forceinline__ float sigmoidf_(float x) { return 1.0f / (1.0f + __expf(-x)); }
__device__ __forceinline__ float siluf_(float x)    { return x * sigmoidf_(x); }

// split pair (a,b) fp32 -> hi bf16x2 (as u32) + lo bf16x2 (as u32)
__device__ __forceinline__ void split2(float a, float b, uint32_t& hi, uint32_t& lo) {
    __nv_bfloat162 h, l;
    h.x = __float2bfloat16(a); h.y = __float2bfloat16(b);
    l.x = __float2bfloat16(a - __bfloat162float(h.x));
    l.y = __float2bfloat16(b - __bfloat162float(h.y));
    hi = *(uint32_t*)&h; lo = *(uint32_t*)&l;
}

__device__ __forceinline__ void split_store4(const float4 v,
                                             __nv_bfloat16* __restrict__ hp,
                                             __nv_bfloat16* __restrict__ lp,
                                             size_t idx) {
    uint32_t h0, l0, h1, l1;
    split2(v.x, v.y, h0, l0);
    split2(v.z, v.w, h1, l1);
    *(uint32_t*)(hp + idx)     = h0;
    *(uint32_t*)(hp + idx + 2) = h1;
    *(uint32_t*)(lp + idx)     = l0;
    *(uint32_t*)(lp + idx + 2) = l1;
}

// ---------------------------------------------------------------------------
// mma.sync helpers (arch-portable HMMA)
// ---------------------------------------------------------------------------
__device__ __forceinline__ uint32_t smem_u32(const void* p) {
    uint32_t a;
    asm("{ .reg .u64 t; cvta.to.shared.u64 t, %1; cvt.u32.u64 %0, t; }" : "=r"(a) : "l"(p));
    return a;
}
__device__ __forceinline__ void ldsm4(uint32_t* r, uint32_t addr) {
    asm volatile("ldmatrix.sync.aligned.m8n8.x4.shared.b16 {%0,%1,%2,%3}, [%4];"
        : "=r"(r[0]), "=r"(r[1]), "=r"(r[2]), "=r"(r[3]) : "r"(addr));
}
__device__ __forceinline__ void ldsm4t(uint32_t* r, uint32_t addr) {
    asm volatile("ldmatrix.sync.aligned.m8n8.x4.trans.shared.b16 {%0,%1,%2,%3}, [%4];"
        : "=r"(r[0]), "=r"(r[1]), "=r"(r[2]), "=r"(r[3]) : "r"(addr));
}
__device__ __forceinline__ void mma16816(float* c, const uint32_t* a, const uint32_t* b) {
    asm volatile(
        "mma.sync.aligned.m16n8k16.row.col.f32.bf16.bf16.f32 "
        "{%0,%1,%2,%3}, {%4,%5,%6,%7}, {%8,%9}, {%0,%1,%2,%3};"
        : "+f"(c[0]), "+f"(c[1]), "+f"(c[2]), "+f"(c[3])
        : "r"(a[0]), "r"(a[1]), "r"(a[2]), "r"(a[3]), "r"(b[0]), "r"(b[1]));
}

// 64-col bf16 tile swizzle: rows of 128B, 8 chunks of 16B, chunk ^ (row&7)
__device__ __forceinline__ uint32_t swz(int row, int ch) {
    return (uint32_t)((row << 7) + ((ch ^ (row & 7)) << 4));
}
// byte offset of bf16 element (row, col), col even
__device__ __forceinline__ uint32_t swzb(int row, int col) {
    return (uint32_t)((row << 7) + ((((col >> 3) ^ (row & 7))) << 4) + ((col & 7) << 1));
}

// ---------------------------------------------------------------------------
// 1) LayerNorm -> g_nh/g_nl (bf16 split) + fused beta = sigmoid(normed @ Wb)
// ---------------------------------------------------------------------------
__global__ void __launch_bounds__(256) ln_kernel(const float* __restrict__ x,
                                                 const float* __restrict__ w,
                                                 const float* __restrict__ b,
                                                 const float* __restrict__ Wb) {
    const int row = blockIdx.x;
    const int tid = threadIdx.x;
    const float4 v = ((const float4*)(x + (size_t)row * D_))[tid];

    float s  = v.x + v.y + v.z + v.w;
    float s2 = v.x * v.x + v.y * v.y + v.z * v.z + v.w * v.w;
    #pragma unroll
    for (int off = 16; off > 0; off >>= 1) {
        s  += __shfl_xor_sync(0xffffffffu, s,  off);
        s2 += __shfl_xor_sync(0xffffffffu, s2, off);
    }
    __shared__ float sh[16];
    __shared__ float bsh[32];
    const int wid = tid >> 5, lane = tid & 31;
    if (lane == 0) { sh[wid] = s; sh[8 + wid] = s2; }
    __syncthreads();
    float ts = 0.f, ts2 = 0.f;
    #pragma unroll
    for (int i = 0; i < 8; ++i) { ts += sh[i]; ts2 += sh[8 + i]; }

    const float mean = ts * (1.0f / D_);
    const float var  = ts2 * (1.0f / D_) - mean * mean;
    const float rstd = rsqrtf(var + 1e-5f);

    const float4 wv = ((const float4*)w)[tid];
    const float4 bv = ((const float4*)b)[tid];
    float4 o;
    o.x = (v.x - mean) * rstd * wv.x + bv.x;
    o.y = (v.y - mean) * rstd * wv.y + bv.y;
    o.z = (v.z - mean) * rstd * wv.z + bv.z;
    o.w = (v.w - mean) * rstd * wv.w + bv.w;
    const size_t base = (size_t)row * D_;
    split_store4(o, g_nh, g_nl, base + (size_t)tid * 4);

    // fused beta: partial dot of normed row with Wb[:,0..3]
    float a0, a1, a2, a3;
    {
        const float4 w0 = ((const float4*)Wb)[tid * 4 + 0];
        const float4 w1 = ((const float4*)Wb)[tid * 4 + 1];
        const float4 w2 = ((const float4*)Wb)[tid * 4 + 2];
        const float4 w3 = ((const float4*)Wb)[tid * 4 + 3];
        a0 = o.x * w0.x + o.y * w1.x + o.z * w2.x + o.w * w3.x;
        a1 = o.x * w0.y + o.y * w1.y + o.z * w2.y + o.w * w3.y;
        a2 = o.x * w0.z + o.y * w1.z + o.z * w2.z + o.w * w3.z;
        a3 = o.x * w0.w + o.y * w1.w + o.z * w2.w + o.w * w3.w;
    }
    #pragma unroll
    for (int off = 16; off > 0; off >>= 1) {
        a0 += __shfl_xor_sync(0xffffffffu, a0, off);
        a1 += __shfl_xor_sync(0xffffffffu, a1, off);
        a2 += __shfl_xor_sync(0xffffffffu, a2, off);
        a3 += __shfl_xor_sync(0xffffffffu, a3, off);
    }
    if (lane == 0) {
        bsh[wid * 4 + 0] = a0; bsh[wid * 4 + 1] = a1;
        bsh[wid * 4 + 2] = a2; bsh[wid * 4 + 3] = a3;
    }
    __syncthreads();
    if (tid == 0) {
        float t0 = 0, t1 = 0, t2 = 0, t3 = 0;
        #pragma unroll
        for (int wq = 0; wq < 8; ++wq) {
            t0 += bsh[wq * 4 + 0]; t1 += bsh[wq * 4 + 1];
            t2 += bsh[wq * 4 + 2]; t3 += bsh[wq * 4 + 3];
        }
        *(float4*)&g_beta[(size_t)row * 4] =
            make_float4(sigmoidf_(t0), sigmoidf_(t1), sigmoidf_(t2), sigmoidf_(t3));
    }
}

// ---------------------------------------------------------------------------
// 1b) weight transpose + bf16 split (writes into row-offset of combined array)
// ---------------------------------------------------------------------------
__global__ void __launch_bounds__(256) wtrans_kernel(const float* __restrict__ W,
                                                     __nv_bfloat16* __restrict__ Th,
                                                     __nv_bfloat16* __restrict__ Tl,
                                                     int K, int N) {
    __shared__ float tile[32][33];
    const int tx = threadIdx.x & 31, ty = threadIdx.x >> 5;
    const int k0 = blockIdx.y * 32, n0 = blockIdx.x * 32;
    #pragma unroll
    for (int i = 0; i < 32; i += 8)
        tile[ty + i][tx] = W[(size_t)(k0 + ty + i) * N + n0 + tx];
    __syncthreads();
    #pragma unroll
    for (int i = 0; i < 32; i += 8) {
        const float v = tile[tx][ty + i];
        const size_t oi = (size_t)(n0 + ty + i) * K + k0 + tx;
        const __nv_bfloat16 h = __float2bfloat16(v);
        Th[oi] = h;
        Tl[oi] = __float2bfloat16(v - __bfloat162float(h));
    }
}

// ---------------------------------------------------------------------------
// 2) HMMA GEMM (R6 proven: register-prefetch double-buffer)
// ---------------------------------------------------------------------------
#define MG_STAGE 65536
#define MG_SMEM  (2 * MG_STAGE)

__global__ void __launch_bounds__(256, 1)
mma_gemm(const __nv_bfloat16* __restrict__ Ah, const __nv_bfloat16* __restrict__ Al,
         const __nv_bfloat16* __restrict__ Bh, const __nv_bfloat16* __restrict__ Bl,
         float* __restrict__ C, const float* __restrict__ resid,
         int N, int K, int do_silu) {
    extern __shared__ char smx[];
    const uint32_t sbase = smem_u32(smx);
    const int tid = threadIdx.x;
    const int lane = tid & 31;
    const int wid = tid >> 5;
    const int wm = wid >> 2;
    const int wn = wid & 3;
    const int m0w = wm * 64, n0w = wn * 32;

    const size_t bm = (size_t)blockIdx.y * 128;
    const size_t bn = (size_t)blockIdx.x * 128;
    const __nv_bfloat16* pAh = Ah + bm * K;
    const __nv_bfloat16* pAl = Al + bm * K;
    const __nv_bfloat16* pBh = Bh + bn * K;
    const __nv_bfloat16* pBl = Bl + bn * K;

    {
        char* stg = smx;
        #pragma unroll
        for (int p = 0; p < 4; ++p) {
            const int c = tid + (p << 8);
            const int row = c >> 3, ch = c & 7;
            const size_t gi = (size_t)row * K + (ch << 3);
            const int off = (row << 7) + (((ch ^ (row & 7))) << 4);
            *(uint4*)(stg + off)         = *(const uint4*)(pAh + gi);
            *(uint4*)(stg + 16384 + off) = *(const uint4*)(pAl + gi);
            *(uint4*)(stg + 32768 + off) = *(const uint4*)(pBh + gi);
            *(uint4*)(stg + 49152 + off) = *(const uint4*)(pBl + gi);
        }
    }
    __syncthreads();

    float acc[4][4][4];
    #pragma unroll
    for (int i = 0; i < 4; ++i)
        #pragma unroll
        for (int j = 0; j < 4; ++j)
            #pragma unroll
            for (int q = 0; q < 4; ++q) acc[i][j][q] = 0.f;

    const int a_row = m0w + (lane & 15);
    const int a_chs = lane >> 4;
    const int b_row = n0w + ((lane >> 3) & 2) * 4 + (lane & 7);
    const int b_chs = (lane >> 3) & 1;

    const int KB = K >> 6;
    for (int kb = 0; kb < KB; ++kb) {
        const uint32_t stg = sbase + (uint32_t)(kb & 1) * MG_STAGE;
        const bool hasNext = (kb + 1) < KB;

        uint4 vAh[4], vAl[4], vBh[4], vBl[4];
        if (hasNext) {
            const int k0 = (kb + 1) << 6;
            #pragma unroll
            for (int p = 0; p < 4; ++p) {
                const int c = tid + (p << 8);
                const int row = c >> 3, ch = c & 7;
                const size_t gi = (size_t)row * K + k0 + (ch << 3);
                vAh[p] = *(const uint4*)(pAh + gi);
                vAl[p] = *(const uint4*)(pAl + gi);
                vBh[p] = *(const uint4*)(pBh + gi);
                vBl[p] = *(const uint4*)(pBl + gi);
            }
        }

        #pragma unroll
        for (int ks = 0; ks < 4; ++ks) {
            uint32_t afh[4][4], afl[4][4];
            #pragma unroll
            for (int mt = 0; mt < 4; ++mt) {
                const int row = a_row + mt * 16;
                const int ch  = ks * 2 + a_chs;
                const uint32_t off = (uint32_t)((row << 7) + ((ch ^ (row & 7)) << 4));
                ldsm4(afh[mt], stg + off);
                ldsm4(afl[mt], stg + 16384u + off);
            }
            uint32_t bfh[2][4], bfl[2][4];
            #pragma unroll
            for (int np = 0; np < 2; ++np) {
                const int row = b_row + np * 16;
                const int ch  = ks * 2 + b_chs;
                const uint32_t off = (uint32_t)((row << 7) + ((ch ^ (row & 7)) << 4));
                ldsm4(bfh[np], stg + 32768u + off);
                ldsm4(bfl[np], stg + 49152u + off);
            }
            #pragma unroll
            for (int mt = 0; mt < 4; ++mt) {
                #pragma unroll
                for (int nt = 0; nt < 4; ++nt) {
                    const uint32_t* bh = &bfh[nt >> 1][(nt & 1) * 2];
                    const uint32_t* bl = &bfl[nt >> 1][(nt & 1) * 2];
                    mma16816(acc[mt][nt], afh[mt], bh);
                    mma16816(acc[mt][nt], afh[mt], bl);
                    mma16816(acc[mt][nt], afl[mt], bh);
                }
            }
        }

        if (hasNext) {
            char* nst = smx + ((kb + 1) & 1) * MG_STAGE;
            #pragma unroll
            for (int p = 0; p < 4; ++p) {
                const int c = tid + (p << 8);
                const int row = c >> 3, ch = c & 7;
                const int off = (row << 7) + ((ch ^ (row & 7)) << 4);
                *(uint4*)(nst + off)         = vAh[p];
                *(uint4*)(nst + 16384 + off) = vAl[p];
                *(uint4*)(nst + 32768 + off) = vBh[p];
                *(uint4*)(nst + 49152 + off) = vBl[p];
            }
        }
        __syncthreads();
    }

    const int erow = lane >> 2;
    const int ecol = (lane & 3) * 2;
    #pragma unroll
    for (int mt = 0; mt < 4; ++mt) {
        #pragma unroll
        for (int nt = 0; nt < 4; ++nt) {
            const size_t gr0 = bm + m0w + mt * 16 + erow;
            const size_t gc  = bn + n0w + nt * 8 + ecol;
            float v0 = acc[mt][nt][0], v1 = acc[mt][nt][1];
            float v2 = acc[mt][nt][2], v3 = acc[mt][nt][3];
            if (do_silu) { v0 = siluf_(v0); v1 = siluf_(v1); v2 = siluf_(v2); v3 = siluf_(v3); }
            if (resid != nullptr) {
                const float2 r0 = *(const float2*)&resid[gr0 * N + gc];
                const float2 r1 = *(const float2*)&resid[(gr0 + 8) * N + gc];
                v0 += r0.x; v1 += r0.y; v2 += r1.x; v3 += r1.y;
            }
            float2 w0; w0.x = v0; w0.y = v1;
            float2 w1; w1.x = v2; w1.y = v3;
            *(float2*)&C[gr0 * N + gc]       = w0;
            *(float2*)&C[(gr0 + 8) * N + gc] = w1;
        }
    }
}

// ---------------------------------------------------------------------------
// 5a) prep1 (includes l2norm of k and q, q additionally * DK^-0.5)
//     reads q at g_qkv[.. + hK], k at g_qkv[.. + 1024 + hK]
// ---------------------------------------------------------------------------
#define P1_FLOATS (17408 + 17408 + 4352 + 64 + 64 + 272)
#define P1_BYTES  (P1_FLOATS * 4)

__global__ void __launch_bounds__(256, 1) prep1_kernel() {
    extern __shared__ float sm1[];
    float* Kt  = sm1;            // [256][68]
    float* wb  = sm1 + 17408;    // [64][260]
    float* Qts = sm1 + 17408;    // [256][68]  (aliases wb)
    float* Ms  = sm1 + 34816;    // [64][68]
    float* bsm = sm1 + 39168;    // [64]
    float* rsk = sm1 + 39232;    // [64]
    float* nrm = sm1 + 39296;    // [4][68]

    const int tid  = threadIdx.x;
    const int cIdx = blockIdx.x;
    const int n = cIdx & 31, h = (cIdx >> 5) & 3, b = cIdx >> 7;
    const size_t m0 = (size_t)b * T_ + n * C_;
    const int hK = h * DK_;

    if (tid < 64) bsm[tid] = g_beta[(m0 + tid) * H_ + h];

    #pragma unroll 4
    for (int p = 0; p < 16; ++p) {
        const int idx = tid + p * 256;
        const int i = idx >> 6, c4 = idx & 63;
        const float4 v = *(const float4*)&g_qkv[(m0 + i) * NQKV + 1024 + hK + c4 * 4];
        Kt[(c4 * 4 + 0) * 68 + i] = v.x;
        Kt[(c4 * 4 + 1) * 68 + i] = v.y;
        Kt[(c4 * 4 + 2) * 68 + i] = v.z;
        Kt[(c4 * 4 + 3) * 68 + i] = v.w;
    }
    __syncthreads();

    {
        const int i = tid & 63, part = tid >> 6;
        float ss = 0.f;
        #pragma unroll 4
        for (int kk = part * 64; kk < part * 64 + 64; ++kk) {
            const float vv = Kt[kk * 68 + i];
            ss += vv * vv;
        }
        nrm[part * 68 + i] = ss;
    }
    __syncthreads();
    if (tid < 64)
        rsk[tid] = rsqrtf(nrm[tid] + nrm[68 + tid] + nrm[136 + tid] + nrm[204 + tid] + 1e-6f);
    __syncthreads();
    for (int idx = tid; idx < 4352; idx += 256) {
        const int kk = idx / 17, f4 = idx % 17;
        if (f4 < 16) {
            float4 v = *(float4*)&Kt[kk * 68 + f4 * 4];
            const float4 r = *(const float4*)&rsk[f4 * 4];
            v.x *= r.x; v.y *= r.y; v.z *= r.z; v.w *= r.w;
            *(float4*)&Kt[kk * 68 + f4 * 4] = v;
        }
    }
    __syncthreads();

    const int ty = tid >> 4, tx = tid & 15;
    const int ti4 = ty * 4, tj4 = tx * 4;

    #pragma unroll 4
    for (int p = 0; p < 16; ++p) {
        const int idx = tid + p * 256;
        const int i = idx >> 6, c4 = idx & 63;
        const float bb = bsm[i];
        float4 v;
        v.x = bb * Kt[(c4 * 4 + 0) * 68 + i];
        v.y = bb * Kt[(c4 * 4 + 1) * 68 + i];
        v.z = bb * Kt[(c4 * 4 + 2) * 68 + i];
        v.w = bb * Kt[(c4 * 4 + 3) * 68 + i];
        *(float4*)&wb[i * 260 + c4 * 4] = v;
    }

    {
        ull acc[4][2] = {};
        #pragma unroll 4
        for (int kk = 0; kk < 256; ++kk) {
            const float4 a4 = *(const float4*)&Kt[kk * 68 + ti4];
            const float4 b4 = *(const float4*)&Kt[kk * 68 + tj4];
            mma4x4p(acc, a4, pack2(b4.x, b4.y), pack2(b4.z, b4.w));
        }
        float mo[4][4]; unp4x4(acc, mo);
        #pragma unroll
        for (int r = 0; r < 4; ++r) {
            const int i = ti4 + r;
            const float bi = bsm[i];
            #pragma unroll
            for (int cc = 0; cc < 4; ++cc) {
                const int j = tj4 + cc;
                Ms[i * 68 + j] = (j < i) ? bi * mo[r][cc] : 0.f;
            }
        }
    }

    {
        __nv_bfloat16* kth = g_cKth + (size_t)cIdx * 16384;
        __nv_bfloat16* ktl = g_cKtl + (size_t)cIdx * 16384;
        for (int idx = tid; idx < 8192; idx += 256) {
            const int kk = idx >> 5, i2 = (idx & 31) * 2;
            uint32_t hi, lo;
            split2(Kt[kk * 68 + i2], Kt[kk * 68 + i2 + 1], hi, lo);
            *(uint32_t*)(kth + kk * 64 + i2) = hi;
            *(uint32_t*)(ktl + kk * 64 + i2) = lo;
        }
    }
    __syncthreads();

    for (int i = 1; i < 64; ++i) {
        const float* mr = Ms + i * 68;
        float a0 = 0.f, a1 = 0.f, a2 = 0.f, a3 = 0.f;
        int j = 0;
        for (; j + 4 <= i; j += 4) {
            a0 += mr[j + 0] * wb[(j + 0) * 260 + tid];
            a1 += mr[j + 1] * wb[(j + 1) * 260 + tid];
            a2 += mr[j + 2] * wb[(j + 2) * 260 + tid];
            a3 += mr[j + 3] * wb[(j + 3) * 260 + tid];
        }
        for (; j < i; ++j) a0 += mr[j] * wb[j * 260 + tid];
        wb[i * 260 + tid] -= (a0 + a1) + (a2 + a3);
        __syncthreads();
    }

    {
        __nv_bfloat16* wh = g_cWh + (size_t)cIdx * 16384;
        __nv_bfloat16* wl = g_cWl + (size_t)cIdx * 16384;
        for (int idx = tid; idx < 8192; idx += 256) {
            const int i = idx >> 7, kk2 = (idx & 127) * 2;
            uint32_t hi, lo;
            split2(wb[i * 260 + kk2], wb[i * 260 + kk2 + 1], hi, lo);
            *(uint32_t*)(wh + i * 256 + kk2) = hi;
            *(uint32_t*)(wl + i * 256 + kk2) = lo;
        }
        float* mo = g_mlt + (size_t)cIdx * (C_ * C_);
        for (int idx = tid; idx < C_ * C_; idx += 256)
            mo[idx] = Ms[(idx >> 6) * 68 + (idx & 63)];
    }
    __syncthreads();   // wb dead; Qts may now overwrite

    #pragma unroll 4
    for (int p = 0; p < 16; ++p) {
        const int idx = tid + p * 256;
        const int i = idx >> 6, c4 = idx & 63;
        const float4 v = *(const float4*)&g_qkv[(m0 + i) * NQKV + hK + c4 * 4];
        Qts[(c4 * 4 + 0) * 68 + i] = v.x;
        Qts[(c4 * 4 + 1) * 68 + i] = v.y;
        Qts[(c4 * 4 + 2) * 68 + i] = v.z;
        Qts[(c4 * 4 + 3) * 68 + i] = v.w;
    }
    __syncthreads();

    {
        const int i = tid & 63, part = tid >> 6;
        float ss = 0.f;
        #pragma unroll 4
        for (int kk = part * 64; kk < part * 64 + 64; ++kk) {
            const float vv = Qts[kk * 68 + i];
            ss += vv * vv;
        }
        nrm[part * 68 + i] = ss;
    }
    __syncthreads();
    if (tid < 64)
        rsk[tid] = rsqrtf(nrm[tid] + nrm[68 + tid] + nrm[136 + tid] + nrm[204 + tid] + 1e-6f) * 0.0625f;
    __syncthreads();
    for (int idx = tid; idx < 4352; idx += 256) {
        const int kk = idx / 17, f4 = idx % 17;
        if (f4 < 16) {
            float4 v = *(float4*)&Qts[kk * 68 + f4 * 4];
            const float4 r = *(const float4*)&rsk[f4 * 4];
            v.x *= r.x; v.y *= r.y; v.z *= r.z; v.w *= r.w;
            *(float4*)&Qts[kk * 68 + f4 * 4] = v;
        }
    }
    __syncthreads();

    {
        __nv_bfloat16* qh = g_cQh + (size_t)cIdx * 16384;
        __nv_bfloat16* ql = g_cQl + (size_t)cIdx * 16384;
        for (int idx = tid; idx < 8192; idx += 256) {
            const int i = idx >> 7, kk2 = (idx & 127) * 2;
            uint32_t hi, lo;
            split2(Qts[kk2 * 68 + i], Qts[(kk2 + 1) * 68 + i], hi, lo);
            *(uint32_t*)(qh + i * 256 + kk2) = hi;
            *(uint32_t*)(ql + i * 256 + kk2) = lo;
        }
    }

    {
        ull acc[4][2] = {};
        #pragma unroll 4
        for (int kk = 0; kk < 256; ++kk) {
            const float4 a4 = *(const float4*)&Qts[kk * 68 + ti4];
            const float4 b4 = *(const float4*)&Kt[kk * 68 + tj4];
            mma4x4p(acc, a4, pack2(b4.x, b4.y), pack2(b4.z, b4.w));
        }
        float po[4][4]; unp4x4(acc, po);
        __nv_bfloat16* ph = g_cPh + (size_t)cIdx * 4096;
        __nv_bfloat16* pl = g_cPl + (size_t)cIdx * 4096;
        #pragma unroll
        for (int r = 0; r < 4; ++r) {
            const int i = ti4 + r;
            const float v0 = (tj4 + 0 <= i) ? po[r][0] : 0.f;
            const float v1 = (tj4 + 1 <= i) ? po[r][1] : 0.f;
            const float v2 = (tj4 + 2 <= i) ? po[r][2] : 0.f;
            const float v3 = (tj4 + 3 <= i) ? po[r][3] : 0.f;
            uint32_t hi, lo;
            split2(v0, v1, hi, lo);
            *(uint32_t*)(ph + i * 64 + tj4)     = hi;
            *(uint32_t*)(pl + i * 64 + tj4)     = lo;
            split2(v2, v3, hi, lo);
            *(uint32_t*)(ph + i * 64 + tj4 + 2) = hi;
            *(uint32_t*)(pl + i * 64 + tj4 + 2) = lo;
        }
    }
}

// ---------------------------------------------------------------------------
// 5b) prep2: Uv = (I+M)^{-1} (beta V)  -> g_Uv (v read from g_qkv + 2048)
// ---------------------------------------------------------------------------
#define P2_FLOATS (33280 + 4352 + 64)
#define P2_BYTES  (P2_FLOATS * 4)

__global__ void __launch_bounds__(256, 1) prep2_kernel() {
    extern __shared__ float sm2[];
    float* vb  = sm2;            // [64][520]
    float* Ms  = sm2 + 33280;    // [64][68]
    float* bsm = sm2 + 33280 + 4352;

    const int tid  = threadIdx.x;
    const int cIdx = blockIdx.x;
    const int n = cIdx & 31, h = (cIdx >> 5) & 3, b = cIdx >> 7;
    const size_t m0 = (size_t)b * T_ + n * C_;
    const int hV = h * DV_;

    if (tid < 64) bsm[tid] = g_beta[(m0 + tid) * H_ + h];
    {
        const float* mg = g_mlt + (size_t)cIdx * (C_ * C_);
        for (int idx = tid; idx < C_ * C_; idx += 256)
            Ms[(idx >> 6) * 68 + (idx & 63)] = mg[idx];
    }
    __syncthreads();

    #pragma unroll 4
    for (int p = 0; p < 32; ++p) {
        const int idx = tid + p * 256;
        const int i = idx >> 7, c4 = idx & 127;
        float4 v = *(const float4*)&g_qkv[(m0 + i) * NQKV + 2048 + hV + c4 * 4];
        const float bb = bsm[i];
        v.x *= bb; v.y *= bb; v.z *= bb; v.w *= bb;
        *(float4*)&vb[i * 520 + c4 * 4] = v;
    }
    __syncthreads();

    const int col2 = 2 * tid;
    for (int i = 1; i < 64; ++i) {
        const float* mr = Ms + i * 68;
        ull acc = 0ull;
        for (int j = 0; j < i; ++j) {
            const float m = mr[j];
            const ull v = *(const ull*)&vb[j * 520 + col2];
            ffma2(acc, pack2(m, m), v);
        }
        float ax, ay; unpack2(acc, ax, ay);
        vb[i * 520 + col2]     -= ax;
        vb[i * 520 + col2 + 1] -= ay;
        __syncthreads();
    }

    float* uo = g_Uv + (size_t)cIdx * (C_ * DV_);
    #pragma unroll 4
    for (int p = 0; p < 32; ++p) {
        const int idx = tid + p * 256;
        const int i = idx >> 7, c4 = idx & 127;
        *(float4*)&uo[i * DV_ + c4 * 4] = *(const float4*)&vb[i * 520 + c4 * 4];
    }
}

// ---------------------------------------------------------------------------
// 5c) chunkscan (HMMA, 512 threads / 16 warps, warp grid 4x4 — R9 best)
// ---------------------------------------------------------------------------
#define CST 512
#define CS2_SH   69632
#define CS2_SL   102400
#define CS2_UH   135168
#define CS2_UL   143360
#define CS2_UVS  151552
#define CS2_STG  168960
#define CS2_BYTES 201728

__global__ void __launch_bounds__(CST, 1) chunkscan_kernel() {
    extern __shared__ char sm3[];
    float* SF  = (float*)sm3;                 // [256][68] fp32
    char*  SH  = sm3 + CS2_SH;                // [256][64] bf16 swizzled
    char*  SL  = sm3 + CS2_SL;
    char*  UH  = sm3 + CS2_UH;                // [64][64] bf16 swizzled
    char*  UL  = sm3 + CS2_UL;
    float* UVS = (float*)(sm3 + CS2_UVS);     // [64][68] fp32
    char*  STG = sm3 + CS2_STG;               // 4 x 8192B tiles

    const uint32_t stg_u = smem_u32(STG);
    const uint32_t sh_u  = smem_u32(SH);
    const uint32_t sl_u  = smem_u32(SL);
    const uint32_t uh_u  = smem_u32(UH);
    const uint32_t ul_u  = smem_u32(UL);

    const int tid  = threadIdx.x;
    const int lane = tid & 31, wid = tid >> 5;      // 16 warps
    const int wm = wid >> 2, wn = wid & 3;          // 4 x 4
    const int erow = lane >> 2, ecol = (lane & 3) * 2;
    const int lrow = lane & 15, lhi = lane >> 4;
    const int c = blockIdx.x & 7, h = (blockIdx.x >> 3) & 3, b = blockIdx.x >> 5;
    const int dv0 = c * 64;
    const int srow = tid >> 3, sch = tid & 7;       // staging role (512 = 64 rows x 8 ch)
    const uint32_t sso = swz(srow, sch);

    for (int i = tid; i < 17408; i += CST) SF[i] = 0.f;
    for (int i = tid; i < 8192; i += CST) { ((uint32_t*)SH)[i] = 0u; ((uint32_t*)SL)[i] = 0u; }
    __syncthreads();

    for (int n = 0; n < NC_; ++n) {
        const int cIdx = b * 128 + h * 32 + n;
        const __nv_bfloat16* Wh  = g_cWh  + (size_t)cIdx * 16384;
        const __nv_bfloat16* Wl  = g_cWl  + (size_t)cIdx * 16384;
        const __nv_bfloat16* Qh  = g_cQh  + (size_t)cIdx * 16384;
        const __nv_bfloat16* Ql  = g_cQl  + (size_t)cIdx * 16384;
        const __nv_bfloat16* Kth = g_cKth + (size_t)cIdx * 16384;
        const __nv_bfloat16* Ktl = g_cKtl + (size_t)cIdx * 16384;
        const __nv_bfloat16* Ph  = g_cPh  + (size_t)cIdx * 4096;
        const __nv_bfloat16* Pl  = g_cPl  + (size_t)cIdx * 4096;
        const float* Uvg = g_Uv + (size_t)cIdx * 32768 + dv0;
        const size_t m0  = (size_t)b * T_ + n * 64;

        // stage W/Q block 0 + Uv
        {
            const size_t gi = (size_t)srow * 256 + sch * 8;
            *(uint4*)(STG + sso)         = *(const uint4*)(Wh + gi);
            *(uint4*)(STG + 8192 + sso)  = *(const uint4*)(Wl + gi);
            *(uint4*)(STG + 16384 + sso) = *(const uint4*)(Qh + gi);
            *(uint4*)(STG + 24576 + sso) = *(const uint4*)(Ql + gi);
        }
        #pragma unroll
        for (int j = 0; j < 2; ++j) {
            const int idx = tid + j * CST;
            const int r = idx >> 4, c4 = idx & 15;
            *(float4*)&UVS[r * 68 + c4 * 4] = *(const float4*)&Uvg[(size_t)r * DV_ + c4 * 4];
        }
        __syncthreads();

        float accU[2][4] = {}, accO[2][4] = {};

        // GEMM1+2a: accU = W·S, accO = Q·S over 4 kk-blocks
        for (int kb = 0; kb < 4; ++kb) {
            uint4 pf[4];
            if (kb < 3) {
                const size_t gi = (size_t)srow * 256 + (kb + 1) * 64 + sch * 8;
                pf[0] = *(const uint4*)(Wh + gi);
                pf[1] = *(const uint4*)(Wl + gi);
                pf[2] = *(const uint4*)(Qh + gi);
                pf[3] = *(const uint4*)(Ql + gi);
            }
            #pragma unroll
            for (int ks = 0; ks < 4; ++ks) {
                uint32_t wfh[4], wfl[4], qfh[4], qfl[4];
                const int ar = wm * 16 + lrow;
                const uint32_t ao = swz(ar, ks * 2 + lhi);
                ldsm4(wfh, stg_u + ao);
                ldsm4(wfl, stg_u + 8192u + ao);
                ldsm4(qfh, stg_u + 16384u + ao);
                ldsm4(qfl, stg_u + 24576u + ao);
                uint32_t sfh[4], sfl[4];
                const int br = kb * 64 + ks * 16 + lrow;
                const uint32_t bo = swz(br, wn * 2 + lhi);
                ldsm4t(sfh, sh_u + bo);
                ldsm4t(sfl, sl_u + bo);
                #pragma unroll
                for (int nt = 0; nt < 2; ++nt) {
                    mma16816(accU[nt], wfh, sfh + nt * 2);
                    mma16816(accU[nt], wfh, sfl + nt * 2);
                    mma16816(accU[nt], wfl, sfh + nt * 2);
                    mma16816(accO[nt], qfh, sfh + nt * 2);
                    mma16816(accO[nt], qfh, sfl + nt * 2);
                    mma16816(accO[nt], qfl, sfh + nt * 2);
                }
            }
            __syncthreads();
            if (kb < 3) {
                *(uint4*)(STG + sso)         = pf[0];
                *(uint4*)(STG + 8192 + sso)  = pf[1];
                *(uint4*)(STG + 16384 + sso) = pf[2];
                *(uint4*)(STG + 24576 + sso) = pf[3];
                __syncthreads();
            }
        }

        // U finalize (u = Uv - accU) -> UH/UL
        #pragma unroll
        for (int nt = 0; nt < 2; ++nt) {
            const int r0 = wm * 16 + erow;
            const int cc = wn * 16 + nt * 8 + ecol;
            const float u0 = UVS[r0 * 68 + cc]           - accU[nt][0];
            const float u1 = UVS[r0 * 68 + cc + 1]       - accU[nt][1];
            const float u2 = UVS[(r0 + 8) * 68 + cc]     - accU[nt][2];
            const float u3 = UVS[(r0 + 8) * 68 + cc + 1] - accU[nt][3];
            uint32_t hi, lo;
            split2(u0, u1, hi, lo);
            *(uint32_t*)(UH + swzb(r0, cc)) = hi;
            *(uint32_t*)(UL + swzb(r0, cc)) = lo;
            split2(u2, u3, hi, lo);
            *(uint32_t*)(UH + swzb(r0 + 8, cc)) = hi;
            *(uint32_t*)(UL + swzb(r0 + 8, cc)) = lo;
        }
        // stage P -> T0/T1, Kt block0 -> T2/T3
        {
            const size_t gp = (size_t)srow * 64 + sch * 8;
            *(uint4*)(STG + sso)         = *(const uint4*)(Ph + gp);
            *(uint4*)(STG + 8192 + sso)  = *(const uint4*)(Pl + gp);
            *(uint4*)(STG + 16384 + sso) = *(const uint4*)(Kth + gp);
            *(uint4*)(STG + 24576 + sso) = *(const uint4*)(Ktl + gp);
        }
        __syncthreads();

        // hoist U B-fragments for all 4 k-steps (shared by GEMM2b and GEMM3)
        uint32_t ufh[4][4], ufl[4][4];
        #pragma unroll
        for (int ks = 0; ks < 4; ++ks) {
            const int br = ks * 16 + lrow;
            const uint32_t bo = swz(br, wn * 2 + lhi);
            ldsm4t(ufh[ks], uh_u + bo);
            ldsm4t(ufl[ks], ul_u + bo);
        }

        // GEMM2b: accO += P·U
        #pragma unroll
        for (int ks = 0; ks < 4; ++ks) {
            uint32_t pfh[4], pfl[4];
            const int ar = wm * 16 + lrow;
            const uint32_t ao = swz(ar, ks * 2 + lhi);
            ldsm4(pfh, stg_u + ao);
            ldsm4(pfl, stg_u + 8192u + ao);
            #pragma unroll
            for (int nt = 0; nt < 2; ++nt) {
                mma16816(accO[nt], pfh, ufh[ks] + nt * 2);
                mma16816(accO[nt], pfh, ufl[ks] + nt * 2);
                mma16816(accO[nt], pfl, ufh[ks] + nt * 2);
            }
        }

        // O epilogue -> global
        #pragma unroll
        for (int nt = 0; nt < 2; ++nt) {
            const int r0 = wm * 16 + erow;
            const int cc = wn * 16 + nt * 8 + ecol;
            float2 w0; w0.x = accO[nt][0]; w0.y = accO[nt][1];
            float2 w1; w1.x = accO[nt][2]; w1.y = accO[nt][3];
            *(float2*)&g_o[(m0 + r0) * NV + h * DV_ + dv0 + cc]     = w0;
            *(float2*)&g_o[(m0 + r0 + 8) * NV + h * DV_ + dv0 + cc] = w1;
        }
        __syncthreads();   // retire P reads (T0/T1) before GEMM3 stores there

        // GEMM3: S += K^T · U, 4 kk-blocks, double-buffered halves
        for (int kkb = 0; kkb < 4; ++kkb) {
            float accS[2][4] = {};
            uint4 kf[2];
            if (kkb < 3) {
                const size_t gi = (size_t)((kkb + 1) * 64 + srow) * 64 + sch * 8;
                kf[0] = *(const uint4*)(Kth + gi);
                kf[1] = *(const uint4*)(Ktl + gi);
            }
            const uint32_t curH = stg_u + ((kkb & 1) ? 0u : 16384u);
            const uint32_t curL = stg_u + ((kkb & 1) ? 8192u : 24576u);
            #pragma unroll
            for (int ks = 0; ks < 4; ++ks) {
                uint32_t kfh[4], kfl[4];
                const int ar = wm * 16 + lrow;
                const uint32_t ao = swz(ar, ks * 2 + lhi);
                ldsm4(kfh, curH + ao);
                ldsm4(kfl, curL + ao);
                #pragma unroll
                for (int nt = 0; nt < 2; ++nt) {
                    mma16816(accS[nt], kfh, ufh[ks] + nt * 2);
                    mma16816(accS[nt], kfh, ufl[ks] + nt * 2);
                    mma16816(accS[nt], kfl, ufh[ks] + nt * 2);
                }
            }
            // S finalize: fp32 RMW + bf16 re-split for this 64-row block
            #pragma unroll
            for (int nt = 0; nt < 2; ++nt) {
                const int sr = kkb * 64 + wm * 16 + erow;
                const int sc = wn * 16 + nt * 8 + ecol;
                const float s0 = SF[sr * 68 + sc]           + accS[nt][0];
                const float s1 = SF[sr * 68 + sc + 1]       + accS[nt][1];
                const float s2 = SF[(sr + 8) * 68 + sc]     + accS[nt][2];
                const float s3 = SF[(sr + 8) * 68 + sc + 1] + accS[nt][3];
                SF[sr * 68 + sc]           = s0;
                SF[sr * 68 + sc + 1]       = s1;
                SF[(sr + 8) * 68 + sc]     = s2;
                SF[(sr + 8) * 68 + sc + 1] = s3;
                uint32_t hi, lo;
                split2(s0, s1, hi, lo);
                *(uint32_t*)(SH + swzb(sr, sc)) = hi;
                *(uint32_t*)(SL + swzb(sr, sc)) = lo;
                split2(s2, s3, hi, lo);
                *(uint32_t*)(SH + swzb(sr + 8, sc)) = hi;
                *(uint32_t*)(SL + swzb(sr + 8, sc)) = lo;
            }
            __syncthreads();
            if (kkb < 3) {
                char* oH = STG + ((kkb & 1) ? 16384 : 0);
                char* oL = STG + ((kkb & 1) ? 24576 : 8192);
                *(uint4*)(oH + sso) = kf[0];
                *(uint4*)(oL + sso) = kf[1];
                __syncthreads();
            }
        }
    }
}

// ---------------------------------------------------------------------------
// 6) per-head RMSNorm on g_o -> bf16 split g_oh/g_ol
// ---------------------------------------------------------------------------
__global__ void __launch_bounds__(256) rmsnorm_kernel(const float* __restrict__ w) {
    const int grp  = blockIdx.x * 8 + (threadIdx.x >> 5);
    const int lane = threadIdx.x & 31;
    const float* base = g_o + (size_t)grp * DV_;
    float4 v[4];
    float ss = 0.f;
    #pragma unroll
    for (int i = 0; i < 4; ++i) {
        v[i] = ((const float4*)base)[lane + 32 * i];
        ss += v[i].x * v[i].x + v[i].y * v[i].y + v[i].z * v[i].z + v[i].w * v[i].w;
    }
    #pragma unroll
    for (int off = 16; off > 0; off >>= 1) ss += __shfl_xor_sync(0xffffffffu, ss, off);
    const float rs = rsqrtf(ss * (1.0f / DV_) + 1e-5f);
    #pragma unroll
    for (int i = 0; i < 4; ++i) {
        const int idx = lane + 32 * i;
        const float4 wv = ((const float4*)w)[idx];
        const float4 o = make_float4(v[i].x * rs * wv.x, v[i].y * rs * wv.y,
                                     v[i].z * rs * wv.z, v[i].w * rs * wv.w);
        split_store4(o, g_oh, g_ol, (size_t)grp * DV_ + (size_t)idx * 4);
    }
}

// ---------------------------------------------------------------------------
// Launch
// ---------------------------------------------------------------------------
extern "C" void kernel_launch(void* const* d_in, const int* in_sizes, int n_in,
                              void* d_out, int out_size) {
    const float* x        = (const float*)d_in[0];
    const float* ln_w     = (const float*)d_in[1];
    const float* ln_b     = (const float*)d_in[2];
    const float* Wq       = (const float*)d_in[3];
    const float* Wk       = (const float*)d_in[4];
    const float* Wv       = (const float*)d_in[5];
    const float* Wb       = (const float*)d_in[6];
    const float* o_norm_w = (const float*)d_in[7];
    const float* Wo       = (const float*)d_in[8];
    float* out = (float*)d_out;

    cudaFuncSetAttribute(mma_gemm, cudaFuncAttributeMaxDynamicSharedMemorySize, MG_SMEM);
    cudaFuncSetAttribute(prep1_kernel, cudaFuncAttributeMaxDynamicSharedMemorySize, P1_BYTES);
    cudaFuncSetAttribute(prep2_kernel, cudaFuncAttributeMaxDynamicSharedMemorySize, P2_BYTES);
    cudaFuncSetAttribute(chunkscan_kernel, cudaFuncAttributeMaxDynamicSharedMemorySize, CS2_BYTES);

    __nv_bfloat16 *nh, *nl, *oh, *ol, *wqkvh, *wqkvl, *woh, *wol;
    cudaGetSymbolAddress((void**)&nh,    g_nh);
    cudaGetSymbolAddress((void**)&nl,    g_nl);
    cudaGetSymbolAddress((void**)&oh,    g_oh);
    cudaGetSymbolAddress((void**)&ol,    g_ol);
    cudaGetSymbolAddress((void**)&wqkvh, g_Wqkvt_h);
    cudaGetSymbolAddress((void**)&wqkvl, g_Wqkvt_l);
    cudaGetSymbolAddress((void**)&woh,   g_Wot_h);
    cudaGetSymbolAddress((void**)&wol,   g_Wot_l);
    float* gqkv;
    cudaGetSymbolAddress((void**)&gqkv, g_qkv);

    // 1) LayerNorm (+ bf16 split of normed, + fused beta)
    ln_kernel<<<M_, 256>>>(x, ln_w, ln_b, Wb);

    // 1b) weight transpose+split into combined [q|k|v][K] array + Wo
    wtrans_kernel<<<dim3(NKV / 32, D_ / 32), 256>>>(Wq, wqkvh,                      wqkvl,                      D_, NKV);
    wtrans_kernel<<<dim3(NKV / 32, D_ / 32), 256>>>(Wk, wqkvh + (size_t)1024 * D_,  wqkvl + (size_t)1024 * D_,  D_, NKV);
    wtrans_kernel<<<dim3(NV  / 32, D_ / 32), 256>>>(Wv, wqkvh + (size_t)2048 * D_,  wqkvl + (size_t)2048 * D_,  D_, NV);
    wtrans_kernel<<<dim3(D_  / 32, NV / 32), 256>>>(Wo, woh, wol, NV, D_);

    // 2) fused QKV projection (HMMA, silu fused, single launch N=4096)
    mma_gemm<<<dim3(NQKV / 128, M_ / 128), 256, MG_SMEM>>>(nh, nl, wqkvh, wqkvl, gqkv, nullptr, NQKV, D_, 1);

    // 5) chunked delta-rule (prep1 includes l2norm of q/k)
    prep1_kernel<<<NCH, 256, P1_BYTES>>>();
    prep2_kernel<<<NCH, 256, P2_BYTES>>>();
    chunkscan_kernel<<<B_ * H_ * 8, CST, CS2_BYTES>>>();

    // 6) RMSNorm (+ bf16 split of o)
    rmsnorm_kernel<<<(M_ * H_) / 8, 256>>>(o_norm_w);

    // 7) output projection + residual (HMMA)
    mma_gemm<<<dim3(D_ / 128, M_ / 128), 256, MG_SMEM>>>(oh, ol, woh, wol, out, x, D_, NV, 0);
}

// round 16
// speedup vs baseline: 1.0941x; 1.0198x over previous
#include <cuda_runtime.h>
#include <cuda_bf16.h>
#include <cstdint>

// Problem constants (fixed shapes)
#define B_  4
#define T_  2048
#define D_  1024
#define H_  4
#define DK_ 256
#define DV_ 512
#define M_  (B_ * T_)        // 8192 rows
#define NKV (H_ * DK_)       // 1024
#define NV  (H_ * DV_)       // 2048
#define NQKV 4096            // q(1024) | k(1024) | v(2048)
#define C_   64              // chunk length
#define NC_  32              // chunks per sequence
#define NCH  (B_ * H_ * NC_) // 512 chunk instances

typedef unsigned long long ull;

// ---------------------------------------------------------------------------
// Scratch (device globals; no dynamic allocation allowed)
// ---------------------------------------------------------------------------
__device__ float g_qkv[(size_t)M_ * NQKV];       // fused q|k|v projections
__device__ float g_beta[(size_t)M_ * H_];
__device__ float g_o[(size_t)M_ * NV];
// chunked-scan intermediates
__device__ float g_Uv [(size_t)NCH * C_ * DV_];  // [cIdx][i][dv] fp32
// split-bf16 chunkscan operands (written by prep kernel)
__device__ __nv_bfloat16 g_cWh [(size_t)NCH * C_ * DK_];  // [cIdx][i][kk]
__device__ __nv_bfloat16 g_cWl [(size_t)NCH * C_ * DK_];
__device__ __nv_bfloat16 g_cQh [(size_t)NCH * C_ * DK_];  // [cIdx][i][kk]
__device__ __nv_bfloat16 g_cQl [(size_t)NCH * C_ * DK_];
__device__ __nv_bfloat16 g_cKth[(size_t)NCH * DK_ * C_];  // [cIdx][kk][i]
__device__ __nv_bfloat16 g_cKtl[(size_t)NCH * DK_ * C_];
__device__ __nv_bfloat16 g_cPh [(size_t)NCH * C_ * C_];   // [cIdx][i][j]
__device__ __nv_bfloat16 g_cPl [(size_t)NCH * C_ * C_];
// bf16 split operands for projection GEMMs
__device__ __nv_bfloat16 g_nh[(size_t)M_ * D_];
__device__ __nv_bfloat16 g_nl[(size_t)M_ * D_];
__device__ __nv_bfloat16 g_oh[(size_t)M_ * NV];
__device__ __nv_bfloat16 g_ol[(size_t)M_ * NV];
__device__ __nv_bfloat16 g_Wqkvt_h[(size_t)NQKV * D_];    // [q|k|v rows][K]
__device__ __nv_bfloat16 g_Wqkvt_l[(size_t)NQKV * D_];
__device__ __nv_bfloat16 g_Wot_h[(size_t)D_ * NV];
__device__ __nv_bfloat16 g_Wot_l[(size_t)D_ * NV];

// ---------------------------------------------------------------------------
// f32x2 packed-FMA helpers (prep kernels)
// ---------------------------------------------------------------------------
__device__ __forceinline__ ull pack2(float x, float y) {
    ull r; asm("mov.b64 %0, {%1, %2};" : "=l"(r) : "f"(x), "f"(y)); return r;
}
__device__ __forceinline__ void unpack2(ull v, float& x, float& y) {
    asm("mov.b64 {%0, %1}, %2;" : "=f"(x), "=f"(y) : "l"(v));
}
__device__ __forceinline__ void ffma2(ull& d, ull a, ull b) {
    asm("fma.rn.f32x2 %0, %1, %2, %0;" : "+l"(d) : "l"(a), "l"(b));
}
__device__ __forceinline__ void mma4x4p(ull (&acc)[4][2], const float4 a4,
                                        const ull b0, const ull b1) {
    ull a;
    a = pack2(a4.x, a4.x); ffma2(acc[0][0], a, b0); ffma2(acc[0][1], a, b1);
    a = pack2(a4.y, a4.y); ffma2(acc[1][0], a, b0); ffma2(acc[1][1], a, b1);
    a = pack2(a4.z, a4.z); ffma2(acc[2][0], a, b0); ffma2(acc[2][1], a, b1);
    a = pack2(a4.w, a4.w); ffma2(acc[3][0], a, b0); ffma2(acc[3][1], a, b1);
}
__device__ __forceinline__ void unp4x4(const ull (&acc)[4][2], float (&o)[4][4]) {
    #pragma unroll
    for (int r = 0; r < 4; ++r) {
        unpack2(acc[r][0], o[r][0], o[r][1]);
        unpack2(acc[r][1], o[r][2], o[r][3]);
    }
}

__device__ __forceinline__ float sigmoidf_(float x) { return 1.0f / (1.0f + __expf(-x)); }
__device__ __forceinline__ float siluf_(float x)    { return x * sigmoidf_(x); }

// split pair (a,b) fp32 -> hi bf16x2 (as u32) + lo bf16x2 (as u32)
__device__ __forceinline__ void split2(float a, float b, uint32_t& hi, uint32_t& lo) {
    __nv_bfloat162 h, l;
    h.x = __float2bfloat16(a); h.y = __float2bfloat16(b);
    l.x = __float2bfloat16(a - __bfloat162float(h.x));
    l.y = __float2bfloat16(b - __bfloat162float(h.y));
    hi = *(uint32_t*)&h; lo = *(uint32_t*)&l;
}

__device__ __forceinline__ void split_store4(const float4 v,
                                             __nv_bfloat16* __restrict__ hp,
                                             __nv_bfloat16* __restrict__ lp,
                                             size_t idx) {
    uint32_t h0, l0, h1, l1;
    split2(v.x, v.y, h0, l0);
    split2(v.z, v.w, h1, l1);
    *(uint32_t*)(hp + idx)     = h0;
    *(uint32_t*)(hp + idx + 2) = h1;
    *(uint32_t*)(lp + idx)     = l0;
    *(uint32_t*)(lp + idx + 2) = l1;
}

// ---------------------------------------------------------------------------
// mma.sync helpers (arch-portable HMMA)
// ---------------------------------------------------------------------------
__device__ __forceinline__ uint32_t smem_u32(const void* p) {
    uint32_t a;
    asm("{ .reg .u64 t; cvta.to.shared.u64 t, %1; cvt.u32.u64 %0, t; }" : "=r"(a) : "l"(p));
    return a;
}
__device__ __forceinline__ void ldsm4(uint32_t* r, uint32_t addr) {
    asm volatile("ldmatrix.sync.aligned.m8n8.x4.shared.b16 {%0,%1,%2,%3}, [%4];"
        : "=r"(r[0]), "=r"(r[1]), "=r"(r[2]), "=r"(r[3]) : "r"(addr));
}
__device__ __forceinline__ void ldsm4t(uint32_t* r, uint32_t addr) {
    asm volatile("ldmatrix.sync.aligned.m8n8.x4.trans.shared.b16 {%0,%1,%2,%3}, [%4];"
        : "=r"(r[0]), "=r"(r[1]), "=r"(r[2]), "=r"(r[3]) : "r"(addr));
}
__device__ __forceinline__ void mma16816(float* c, const uint32_t* a, const uint32_t* b) {
    asm volatile(
        "mma.sync.aligned.m16n8k16.row.col.f32.bf16.bf16.f32 "
        "{%0,%1,%2,%3}, {%4,%5,%6,%7}, {%8,%9}, {%0,%1,%2,%3};"
        : "+f"(c[0]), "+f"(c[1]), "+f"(c[2]), "+f"(c[3])
        : "r"(a[0]), "r"(a[1]), "r"(a[2]), "r"(a[3]), "r"(b[0]), "r"(b[1]));
}

// 64-col bf16 tile swizzle: rows of 128B, 8 chunks of 16B, chunk ^ (row&7)
__device__ __forceinline__ uint32_t swz(int row, int ch) {
    return (uint32_t)((row << 7) + ((ch ^ (row & 7)) << 4));
}
// byte offset of bf16 element (row, col), col even
__device__ __forceinline__ uint32_t swzb(int row, int col) {
    return (uint32_t)((row << 7) + ((((col >> 3) ^ (row & 7))) << 4) + ((col & 7) << 1));
}

// ---------------------------------------------------------------------------
// 1) LayerNorm -> g_nh/g_nl (bf16 split) + fused beta = sigmoid(normed @ Wb)
// ---------------------------------------------------------------------------
__global__ void __launch_bounds__(256) ln_kernel(const float* __restrict__ x,
                                                 const float* __restrict__ w,
                                                 const float* __restrict__ b,
                                                 const float* __restrict__ Wb) {
    const int row = blockIdx.x;
    const int tid = threadIdx.x;
    const float4 v = ((const float4*)(x + (size_t)row * D_))[tid];

    float s  = v.x + v.y + v.z + v.w;
    float s2 = v.x * v.x + v.y * v.y + v.z * v.z + v.w * v.w;
    #pragma unroll
    for (int off = 16; off > 0; off >>= 1) {
        s  += __shfl_xor_sync(0xffffffffu, s,  off);
        s2 += __shfl_xor_sync(0xffffffffu, s2, off);
    }
    __shared__ float sh[16];
    __shared__ float bsh[32];
    const int wid = tid >> 5, lane = tid & 31;
    if (lane == 0) { sh[wid] = s; sh[8 + wid] = s2; }
    __syncthreads();
    float ts = 0.f, ts2 = 0.f;
    #pragma unroll
    for (int i = 0; i < 8; ++i) { ts += sh[i]; ts2 += sh[8 + i]; }

    const float mean = ts * (1.0f / D_);
    const float var  = ts2 * (1.0f / D_) - mean * mean;
    const float rstd = rsqrtf(var + 1e-5f);

    const float4 wv = ((const float4*)w)[tid];
    const float4 bv = ((const float4*)b)[tid];
    float4 o;
    o.x = (v.x - mean) * rstd * wv.x + bv.x;
    o.y = (v.y - mean) * rstd * wv.y + bv.y;
    o.z = (v.z - mean) * rstd * wv.z + bv.z;
    o.w = (v.w - mean) * rstd * wv.w + bv.w;
    const size_t base = (size_t)row * D_;
    split_store4(o, g_nh, g_nl, base + (size_t)tid * 4);

    // fused beta: partial dot of normed row with Wb[:,0..3]
    float a0, a1, a2, a3;
    {
        const float4 w0 = ((const float4*)Wb)[tid * 4 + 0];
        const float4 w1 = ((const float4*)Wb)[tid * 4 + 1];
        const float4 w2 = ((const float4*)Wb)[tid * 4 + 2];
        const float4 w3 = ((const float4*)Wb)[tid * 4 + 3];
        a0 = o.x * w0.x + o.y * w1.x + o.z * w2.x + o.w * w3.x;
        a1 = o.x * w0.y + o.y * w1.y + o.z * w2.y + o.w * w3.y;
        a2 = o.x * w0.z + o.y * w1.z + o.z * w2.z + o.w * w3.z;
        a3 = o.x * w0.w + o.y * w1.w + o.z * w2.w + o.w * w3.w;
    }
    #pragma unroll
    for (int off = 16; off > 0; off >>= 1) {
        a0 += __shfl_xor_sync(0xffffffffu, a0, off);
        a1 += __shfl_xor_sync(0xffffffffu, a1, off);
        a2 += __shfl_xor_sync(0xffffffffu, a2, off);
        a3 += __shfl_xor_sync(0xffffffffu, a3, off);
    }
    if (lane == 0) {
        bsh[wid * 4 + 0] = a0; bsh[wid * 4 + 1] = a1;
        bsh[wid * 4 + 2] = a2; bsh[wid * 4 + 3] = a3;
    }
    __syncthreads();
    if (tid == 0) {
        float t0 = 0, t1 = 0, t2 = 0, t3 = 0;
        #pragma unroll
        for (int wq = 0; wq < 8; ++wq) {
            t0 += bsh[wq * 4 + 0]; t1 += bsh[wq * 4 + 1];
            t2 += bsh[wq * 4 + 2]; t3 += bsh[wq * 4 + 3];
        }
        *(float4*)&g_beta[(size_t)row * 4] =
            make_float4(sigmoidf_(t0), sigmoidf_(t1), sigmoidf_(t2), sigmoidf_(t3));
    }
}

// ---------------------------------------------------------------------------
// 1b) all-weights transpose + bf16 split in ONE launch.
//     Segments: 0: Wq (K=1024,N=1024, 1024 tiles) -> g_Wqkvt + 0
//               1: Wk (K=1024,N=1024, 1024 tiles) -> g_Wqkvt + 1024*D
//               2: Wv (K=1024,N=2048, 2048 tiles) -> g_Wqkvt + 2048*D
//               3: Wo (K=2048,N=1024, 2048 tiles) -> g_Wot
// ---------------------------------------------------------------------------
__global__ void __launch_bounds__(256) wtrans_all(const float* __restrict__ Wq,
                                                  const float* __restrict__ Wk,
                                                  const float* __restrict__ Wv,
                                                  const float* __restrict__ Wo) {
    __shared__ float tile[32][33];
    int t = blockIdx.x;
    const float* W;
    __nv_bfloat16 *Th, *Tl;
    int K, N;
    if (t < 1024) {
        W = Wq; Th = g_Wqkvt_h; Tl = g_Wqkvt_l; K = D_; N = NKV;
    } else if (t < 2048) {
        t -= 1024;
        W = Wk; Th = g_Wqkvt_h + (size_t)1024 * D_; Tl = g_Wqkvt_l + (size_t)1024 * D_;
        K = D_; N = NKV;
    } else if (t < 4096) {
        t -= 2048;
        W = Wv; Th = g_Wqkvt_h + (size_t)2048 * D_; Tl = g_Wqkvt_l + (size_t)2048 * D_;
        K = D_; N = NV;
    } else {
        t -= 4096;
        W = Wo; Th = g_Wot_h; Tl = g_Wot_l; K = NV; N = D_;
    }
    const int nbx = N >> 5;
    const int bx = t % nbx, by = t / nbx;
    const int tx = threadIdx.x & 31, ty = threadIdx.x >> 5;
    const int k0 = by * 32, n0 = bx * 32;
    #pragma unroll
    for (int i = 0; i < 32; i += 8)
        tile[ty + i][tx] = W[(size_t)(k0 + ty + i) * N + n0 + tx];
    __syncthreads();
    #pragma unroll
    for (int i = 0; i < 32; i += 8) {
        const float v = tile[tx][ty + i];
        const size_t oi = (size_t)(n0 + ty + i) * K + k0 + tx;
        const __nv_bfloat16 h = __float2bfloat16(v);
        Th[oi] = h;
        Tl[oi] = __float2bfloat16(v - __bfloat162float(h));
    }
}

// ---------------------------------------------------------------------------
// 2) HMMA GEMM (R6 proven: register-prefetch double-buffer)
// ---------------------------------------------------------------------------
#define MG_STAGE 65536
#define MG_SMEM  (2 * MG_STAGE)

__global__ void __launch_bounds__(256, 1)
mma_gemm(const __nv_bfloat16* __restrict__ Ah, const __nv_bfloat16* __restrict__ Al,
         const __nv_bfloat16* __restrict__ Bh, const __nv_bfloat16* __restrict__ Bl,
         float* __restrict__ C, const float* __restrict__ resid,
         int N, int K, int do_silu) {
    extern __shared__ char smx[];
    const uint32_t sbase = smem_u32(smx);
    const int tid = threadIdx.x;
    const int lane = tid & 31;
    const int wid = tid >> 5;
    const int wm = wid >> 2;
    const int wn = wid & 3;
    const int m0w = wm * 64, n0w = wn * 32;

    const size_t bm = (size_t)blockIdx.y * 128;
    const size_t bn = (size_t)blockIdx.x * 128;
    const __nv_bfloat16* pAh = Ah + bm * K;
    const __nv_bfloat16* pAl = Al + bm * K;
    const __nv_bfloat16* pBh = Bh + bn * K;
    const __nv_bfloat16* pBl = Bl + bn * K;

    {
        char* stg = smx;
        #pragma unroll
        for (int p = 0; p < 4; ++p) {
            const int c = tid + (p << 8);
            const int row = c >> 3, ch = c & 7;
            const size_t gi = (size_t)row * K + (ch << 3);
            const int off = (row << 7) + (((ch ^ (row & 7))) << 4);
            *(uint4*)(stg + off)         = *(const uint4*)(pAh + gi);
            *(uint4*)(stg + 16384 + off) = *(const uint4*)(pAl + gi);
            *(uint4*)(stg + 32768 + off) = *(const uint4*)(pBh + gi);
            *(uint4*)(stg + 49152 + off) = *(const uint4*)(pBl + gi);
        }
    }
    __syncthreads();

    float acc[4][4][4];
    #pragma unroll
    for (int i = 0; i < 4; ++i)
        #pragma unroll
        for (int j = 0; j < 4; ++j)
            #pragma unroll
            for (int q = 0; q < 4; ++q) acc[i][j][q] = 0.f;

    const int a_row = m0w + (lane & 15);
    const int a_chs = lane >> 4;
    const int b_row = n0w + ((lane >> 3) & 2) * 4 + (lane & 7);
    const int b_chs = (lane >> 3) & 1;

    const int KB = K >> 6;
    for (int kb = 0; kb < KB; ++kb) {
        const uint32_t stg = sbase + (uint32_t)(kb & 1) * MG_STAGE;
        const bool hasNext = (kb + 1) < KB;

        uint4 vAh[4], vAl[4], vBh[4], vBl[4];
        if (hasNext) {
            const int k0 = (kb + 1) << 6;
            #pragma unroll
            for (int p = 0; p < 4; ++p) {
                const int c = tid + (p << 8);
                const int row = c >> 3, ch = c & 7;
                const size_t gi = (size_t)row * K + k0 + (ch << 3);
                vAh[p] = *(const uint4*)(pAh + gi);
                vAl[p] = *(const uint4*)(pAl + gi);
                vBh[p] = *(const uint4*)(pBh + gi);
                vBl[p] = *(const uint4*)(pBl + gi);
            }
        }

        #pragma unroll
        for (int ks = 0; ks < 4; ++ks) {
            uint32_t afh[4][4], afl[4][4];
            #pragma unroll
            for (int mt = 0; mt < 4; ++mt) {
                const int row = a_row + mt * 16;
                const int ch  = ks * 2 + a_chs;
                const uint32_t off = (uint32_t)((row << 7) + ((ch ^ (row & 7)) << 4));
                ldsm4(afh[mt], stg + off);
                ldsm4(afl[mt], stg + 16384u + off);
            }
            uint32_t bfh[2][4], bfl[2][4];
            #pragma unroll
            for (int np = 0; np < 2; ++np) {
                const int row = b_row + np * 16;
                const int ch  = ks * 2 + b_chs;
                const uint32_t off = (uint32_t)((row << 7) + ((ch ^ (row & 7)) << 4));
                ldsm4(bfh[np], stg + 32768u + off);
                ldsm4(bfl[np], stg + 49152u + off);
            }
            #pragma unroll
            for (int mt = 0; mt < 4; ++mt) {
                #pragma unroll
                for (int nt = 0; nt < 4; ++nt) {
                    const uint32_t* bh = &bfh[nt >> 1][(nt & 1) * 2];
                    const uint32_t* bl = &bfl[nt >> 1][(nt & 1) * 2];
                    mma16816(acc[mt][nt], afh[mt], bh);
                    mma16816(acc[mt][nt], afh[mt], bl);
                    mma16816(acc[mt][nt], afl[mt], bh);
                }
            }
        }

        if (hasNext) {
            char* nst = smx + ((kb + 1) & 1) * MG_STAGE;
            #pragma unroll
            for (int p = 0; p < 4; ++p) {
                const int c = tid + (p << 8);
                const int row = c >> 3, ch = c & 7;
                const int off = (row << 7) + ((ch ^ (row & 7)) << 4);
                *(uint4*)(nst + off)         = vAh[p];
                *(uint4*)(nst + 16384 + off) = vAl[p];
                *(uint4*)(nst + 32768 + off) = vBh[p];
                *(uint4*)(nst + 49152 + off) = vBl[p];
            }
        }
        __syncthreads();
    }

    const int erow = lane >> 2;
    const int ecol = (lane & 3) * 2;
    #pragma unroll
    for (int mt = 0; mt < 4; ++mt) {
        #pragma unroll
        for (int nt = 0; nt < 4; ++nt) {
            const size_t gr0 = bm + m0w + mt * 16 + erow;
            const size_t gc  = bn + n0w + nt * 8 + ecol;
            float v0 = acc[mt][nt][0], v1 = acc[mt][nt][1];
            float v2 = acc[mt][nt][2], v3 = acc[mt][nt][3];
            if (do_silu) { v0 = siluf_(v0); v1 = siluf_(v1); v2 = siluf_(v2); v3 = siluf_(v3); }
            if (resid != nullptr) {
                const float2 r0 = *(const float2*)&resid[gr0 * N + gc];
                const float2 r1 = *(const float2*)&resid[(gr0 + 8) * N + gc];
                v0 += r0.x; v1 += r0.y; v2 += r1.x; v3 += r1.y;
            }
            float2 w0; w0.x = v0; w0.y = v1;
            float2 w1; w1.x = v2; w1.y = v3;
            *(float2*)&C[gr0 * N + gc]       = w0;
            *(float2*)&C[(gr0 + 8) * N + gc] = w1;
        }
    }
}

// ---------------------------------------------------------------------------
// 5a) fused prep: prep1 (l2norm q/k, M, W, Kt, Q, P) + prep2 (Uv) in one kernel
// ---------------------------------------------------------------------------
#define P1_FLOATS (17408 + 17408 + 4352 + 64 + 64 + 272)
#define P1_BYTES  (P1_FLOATS * 4)

__global__ void __launch_bounds__(256, 1) prep_kernel() {
    extern __shared__ float sm1[];
    float* Kt  = sm1;            // [256][68]
    float* wb  = sm1 + 17408;    // [64][260]
    float* Qts = sm1 + 17408;    // [256][68]  (aliases wb)
    float* vb  = sm1;            // [64][520]  (aliases Kt+wb, used after P)
    float* Ms  = sm1 + 34816;    // [64][68]
    float* bsm = sm1 + 39168;    // [64]
    float* rsk = sm1 + 39232;    // [64]
    float* nrm = sm1 + 39296;    // [4][68]

    const int tid  = threadIdx.x;
    const int cIdx = blockIdx.x;
    const int n = cIdx & 31, h = (cIdx >> 5) & 3, b = cIdx >> 7;
    const size_t m0 = (size_t)b * T_ + n * C_;
    const int hK = h * DK_;
    const int hV = h * DV_;

    if (tid < 64) bsm[tid] = g_beta[(m0 + tid) * H_ + h];

    #pragma unroll 4
    for (int p = 0; p < 16; ++p) {
        const int idx = tid + p * 256;
        const int i = idx >> 6, c4 = idx & 63;
        const float4 v = *(const float4*)&g_qkv[(m0 + i) * NQKV + 1024 + hK + c4 * 4];
        Kt[(c4 * 4 + 0) * 68 + i] = v.x;
        Kt[(c4 * 4 + 1) * 68 + i] = v.y;
        Kt[(c4 * 4 + 2) * 68 + i] = v.z;
        Kt[(c4 * 4 + 3) * 68 + i] = v.w;
    }
    __syncthreads();

    {
        const int i = tid & 63, part = tid >> 6;
        float ss = 0.f;
        #pragma unroll 4
        for (int kk = part * 64; kk < part * 64 + 64; ++kk) {
            const float vv = Kt[kk * 68 + i];
            ss += vv * vv;
        }
        nrm[part * 68 + i] = ss;
    }
    __syncthreads();
    if (tid < 64)
        rsk[tid] = rsqrtf(nrm[tid] + nrm[68 + tid] + nrm[136 + tid] + nrm[204 + tid] + 1e-6f);
    __syncthreads();
    for (int idx = tid; idx < 4352; idx += 256) {
        const int kk = idx / 17, f4 = idx % 17;
        if (f4 < 16) {
            float4 v = *(float4*)&Kt[kk * 68 + f4 * 4];
            const float4 r = *(const float4*)&rsk[f4 * 4];
            v.x *= r.x; v.y *= r.y; v.z *= r.z; v.w *= r.w;
            *(float4*)&Kt[kk * 68 + f4 * 4] = v;
        }
    }
    __syncthreads();

    const int ty = tid >> 4, tx = tid & 15;
    const int ti4 = ty * 4, tj4 = tx * 4;

    #pragma unroll 4
    for (int p = 0; p < 16; ++p) {
        const int idx = tid + p * 256;
        const int i = idx >> 6, c4 = idx & 63;
        const float bb = bsm[i];
        float4 v;
        v.x = bb * Kt[(c4 * 4 + 0) * 68 + i];
        v.y = bb * Kt[(c4 * 4 + 1) * 68 + i];
        v.z = bb * Kt[(c4 * 4 + 2) * 68 + i];
        v.w = bb * Kt[(c4 * 4 + 3) * 68 + i];
        *(float4*)&wb[i * 260 + c4 * 4] = v;
    }

    {
        ull acc[4][2] = {};
        #pragma unroll 4
        for (int kk = 0; kk < 256; ++kk) {
            const float4 a4 = *(const float4*)&Kt[kk * 68 + ti4];
            const float4 b4 = *(const float4*)&Kt[kk * 68 + tj4];
            mma4x4p(acc, a4, pack2(b4.x, b4.y), pack2(b4.z, b4.w));
        }
        float mo[4][4]; unp4x4(acc, mo);
        #pragma unroll
        for (int r = 0; r < 4; ++r) {
            const int i = ti4 + r;
            const float bi = bsm[i];
            #pragma unroll
            for (int cc = 0; cc < 4; ++cc) {
                const int j = tj4 + cc;
                Ms[i * 68 + j] = (j < i) ? bi * mo[r][cc] : 0.f;
            }
        }
    }

    {
        __nv_bfloat16* kth = g_cKth + (size_t)cIdx * 16384;
        __nv_bfloat16* ktl = g_cKtl + (size_t)cIdx * 16384;
        for (int idx = tid; idx < 8192; idx += 256) {
            const int kk = idx >> 5, i2 = (idx & 31) * 2;
            uint32_t hi, lo;
            split2(Kt[kk * 68 + i2], Kt[kk * 68 + i2 + 1], hi, lo);
            *(uint32_t*)(kth + kk * 64 + i2) = hi;
            *(uint32_t*)(ktl + kk * 64 + i2) = lo;
        }
    }
    __syncthreads();

    for (int i = 1; i < 64; ++i) {
        const float* mr = Ms + i * 68;
        float a0 = 0.f, a1 = 0.f, a2 = 0.f, a3 = 0.f;
        int j = 0;
        for (; j + 4 <= i; j += 4) {
            a0 += mr[j + 0] * wb[(j + 0) * 260 + tid];
            a1 += mr[j + 1] * wb[(j + 1) * 260 + tid];
            a2 += mr[j + 2] * wb[(j + 2) * 260 + tid];
            a3 += mr[j + 3] * wb[(j + 3) * 260 + tid];
        }
        for (; j < i; ++j) a0 += mr[j] * wb[j * 260 + tid];
        wb[i * 260 + tid] -= (a0 + a1) + (a2 + a3);
        __syncthreads();
    }

    {
        __nv_bfloat16* wh = g_cWh + (size_t)cIdx * 16384;
        __nv_bfloat16* wl = g_cWl + (size_t)cIdx * 16384;
        for (int idx = tid; idx < 8192; idx += 256) {
            const int i = idx >> 7, kk2 = (idx & 127) * 2;
            uint32_t hi, lo;
            split2(wb[i * 260 + kk2], wb[i * 260 + kk2 + 1], hi, lo);
            *(uint32_t*)(wh + i * 256 + kk2) = hi;
            *(uint32_t*)(wl + i * 256 + kk2) = lo;
        }
    }
    __syncthreads();   // wb dead; Qts may now overwrite

    #pragma unroll 4
    for (int p = 0; p < 16; ++p) {
        const int idx = tid + p * 256;
        const int i = idx >> 6, c4 = idx & 63;
        const float4 v = *(const float4*)&g_qkv[(m0 + i) * NQKV + hK + c4 * 4];
        Qts[(c4 * 4 + 0) * 68 + i] = v.x;
        Qts[(c4 * 4 + 1) * 68 + i] = v.y;
        Qts[(c4 * 4 + 2) * 68 + i] = v.z;
        Qts[(c4 * 4 + 3) * 68 + i] = v.w;
    }
    __syncthreads();

    {
        const int i = tid & 63, part = tid >> 6;
        float ss = 0.f;
        #pragma unroll 4
        for (int kk = part * 64; kk < part * 64 + 64; ++kk) {
            const float vv = Qts[kk * 68 + i];
            ss += vv * vv;
        }
        nrm[part * 68 + i] = ss;
    }
    __syncthreads();
    if (tid < 64)
        rsk[tid] = rsqrtf(nrm[tid] + nrm[68 + tid] + nrm[136 + tid] + nrm[204 + tid] + 1e-6f) * 0.0625f;
    __syncthreads();
    for (int idx = tid; idx < 4352; idx += 256) {
        const int kk = idx / 17, f4 = idx % 17;
        if (f4 < 16) {
            float4 v = *(float4*)&Qts[kk * 68 + f4 * 4];
            const float4 r = *(const float4*)&rsk[f4 * 4];
            v.x *= r.x; v.y *= r.y; v.z *= r.z; v.w *= r.w;
            *(float4*)&Qts[kk * 68 + f4 * 4] = v;
        }
    }
    __syncthreads();

    {
        __nv_bfloat16* qh = g_cQh + (size_t)cIdx * 16384;
        __nv_bfloat16* ql = g_cQl + (size_t)cIdx * 16384;
        for (int idx = tid; idx < 8192; idx += 256) {
            const int i = idx >> 7, kk2 = (idx & 127) * 2;
            uint32_t hi, lo;
            split2(Qts[kk2 * 68 + i], Qts[(kk2 + 1) * 68 + i], hi, lo);
            *(uint32_t*)(qh + i * 256 + kk2) = hi;
            *(uint32_t*)(ql + i * 256 + kk2) = lo;
        }
    }

    {
        ull acc[4][2] = {};
        #pragma unroll 4
        for (int kk = 0; kk < 256; ++kk) {
            const float4 a4 = *(const float4*)&Qts[kk * 68 + ti4];
            const float4 b4 = *(const float4*)&Kt[kk * 68 + tj4];
            mma4x4p(acc, a4, pack2(b4.x, b4.y), pack2(b4.z, b4.w));
        }
        float po[4][4]; unp4x4(acc, po);
        __nv_bfloat16* ph = g_cPh + (size_t)cIdx * 4096;
        __nv_bfloat16* pl = g_cPl + (size_t)cIdx * 4096;
        #pragma unroll
        for (int r = 0; r < 4; ++r) {
            const int i = ti4 + r;
            const float v0 = (tj4 + 0 <= i) ? po[r][0] : 0.f;
            const float v1 = (tj4 + 1 <= i) ? po[r][1] : 0.f;
            const float v2 = (tj4 + 2 <= i) ? po[r][2] : 0.f;
            const float v3 = (tj4 + 3 <= i) ? po[r][3] : 0.f;
            uint32_t hi, lo;
            split2(v0, v1, hi, lo);
            *(uint32_t*)(ph + i * 64 + tj4)     = hi;
            *(uint32_t*)(pl + i * 64 + tj4)     = lo;
            split2(v2, v3, hi, lo);
            *(uint32_t*)(ph + i * 64 + tj4 + 2) = hi;
            *(uint32_t*)(pl + i * 64 + tj4 + 2) = lo;
        }
    }
    __syncthreads();   // Kt & Qts dead; vb may now overwrite

    // ---- fused prep2: Uv = (I+M)^{-1} (beta V), Ms still resident ----
    #pragma unroll 4
    for (int p = 0; p < 32; ++p) {
        const int idx = tid + p * 256;
        const int i = idx >> 7, c4 = idx & 127;
        float4 v = *(const float4*)&g_qkv[(m0 + i) * NQKV + 2048 + hV + c4 * 4];
        const float bb = bsm[i];
        v.x *= bb; v.y *= bb; v.z *= bb; v.w *= bb;
        *(float4*)&vb[i * 520 + c4 * 4] = v;
    }
    __syncthreads();

    const int col2 = 2 * tid;
    for (int i = 1; i < 64; ++i) {
        const float* mr = Ms + i * 68;
        ull acc = 0ull;
        for (int j = 0; j < i; ++j) {
            const float m = mr[j];
            const ull v = *(const ull*)&vb[j * 520 + col2];
            ffma2(acc, pack2(m, m), v);
        }
        float ax, ay; unpack2(acc, ax, ay);
        vb[i * 520 + col2]     -= ax;
        vb[i * 520 + col2 + 1] -= ay;
        __syncthreads();
    }

    float* uo = g_Uv + (size_t)cIdx * (C_ * DV_);
    #pragma unroll 4
    for (int p = 0; p < 32; ++p) {
        const int idx = tid + p * 256;
        const int i = idx >> 7, c4 = idx & 127;
        *(float4*)&uo[i * DV_ + c4 * 4] = *(const float4*)&vb[i * 520 + c4 * 4];
    }
}

// ---------------------------------------------------------------------------
// 5c) chunkscan (HMMA, 512 threads / 16 warps, warp grid 4x4 — R9 best)
// ---------------------------------------------------------------------------
#define CST 512
#define CS2_SH   69632
#define CS2_SL   102400
#define CS2_UH   135168
#define CS2_UL   143360
#define CS2_UVS  151552
#define CS2_STG  168960
#define CS2_BYTES 201728

__global__ void __launch_bounds__(CST, 1) chunkscan_kernel() {
    extern __shared__ char sm3[];
    float* SF  = (float*)sm3;                 // [256][68] fp32
    char*  SH  = sm3 + CS2_SH;                // [256][64] bf16 swizzled
    char*  SL  = sm3 + CS2_SL;
    char*  UH  = sm3 + CS2_UH;                // [64][64] bf16 swizzled
    char*  UL  = sm3 + CS2_UL;
    float* UVS = (float*)(sm3 + CS2_UVS);     // [64][68] fp32
    char*  STG = sm3 + CS2_STG;               // 4 x 8192B tiles

    const uint32_t stg_u = smem_u32(STG);
    const uint32_t sh_u  = smem_u32(SH);
    const uint32_t sl_u  = smem_u32(SL);
    const uint32_t uh_u  = smem_u32(UH);
    const uint32_t ul_u  = smem_u32(UL);

    const int tid  = threadIdx.x;
    const int lane = tid & 31, wid = tid >> 5;      // 16 warps
    const int wm = wid >> 2, wn = wid & 3;          // 4 x 4
    const int erow = lane >> 2, ecol = (lane & 3) * 2;
    const int lrow = lane & 15, lhi = lane >> 4;
    const int c = blockIdx.x & 7, h = (blockIdx.x >> 3) & 3, b = blockIdx.x >> 5;
    const int dv0 = c * 64;
    const int srow = tid >> 3, sch = tid & 7;       // staging role (512 = 64 rows x 8 ch)
    const uint32_t sso = swz(srow, sch);

    for (int i = tid; i < 17408; i += CST) SF[i] = 0.f;
    for (int i = tid; i < 8192; i += CST) { ((uint32_t*)SH)[i] = 0u; ((uint32_t*)SL)[i] = 0u; }
    __syncthreads();

    for (int n = 0; n < NC_; ++n) {
        const int cIdx = b * 128 + h * 32 + n;
        const __nv_bfloat16* Wh  = g_cWh  + (size_t)cIdx * 16384;
        const __nv_bfloat16* Wl  = g_cWl  + (size_t)cIdx * 16384;
        const __nv_bfloat16* Qh  = g_cQh  + (size_t)cIdx * 16384;
        const __nv_bfloat16* Ql  = g_cQl  + (size_t)cIdx * 16384;
        const __nv_bfloat16* Kth = g_cKth + (size_t)cIdx * 16384;
        const __nv_bfloat16* Ktl = g_cKtl + (size_t)cIdx * 16384;
        const __nv_bfloat16* Ph  = g_cPh  + (size_t)cIdx * 4096;
        const __nv_bfloat16* Pl  = g_cPl  + (size_t)cIdx * 4096;
        const float* Uvg = g_Uv + (size_t)cIdx * 32768 + dv0;
        const size_t m0  = (size_t)b * T_ + n * 64;

        // stage W/Q block 0 + Uv
        {
            const size_t gi = (size_t)srow * 256 + sch * 8;
            *(uint4*)(STG + sso)         = *(const uint4*)(Wh + gi);
            *(uint4*)(STG + 8192 + sso)  = *(const uint4*)(Wl + gi);
            *(uint4*)(STG + 16384 + sso) = *(const uint4*)(Qh + gi);
            *(uint4*)(STG + 24576 + sso) = *(const uint4*)(Ql + gi);
        }
        #pragma unroll
        for (int j = 0; j < 2; ++j) {
            const int idx = tid + j * CST;
            const int r = idx >> 4, c4 = idx & 15;
            *(float4*)&UVS[r * 68 + c4 * 4] = *(const float4*)&Uvg[(size_t)r * DV_ + c4 * 4];
        }
        __syncthreads();

        float accU[2][4] = {}, accO[2][4] = {};

        // GEMM1+2a: accU = W·S, accO = Q·S over 4 kk-blocks
        for (int kb = 0; kb < 4; ++kb) {
            uint4 pf[4];
            if (kb < 3) {
                const size_t gi = (size_t)srow * 256 + (kb + 1) * 64 + sch * 8;
                pf[0] = *(const uint4*)(Wh + gi);
                pf[1] = *(const uint4*)(Wl + gi);
                pf[2] = *(const uint4*)(Qh + gi);
                pf[3] = *(const uint4*)(Ql + gi);
            }
            #pragma unroll
            for (int ks = 0; ks < 4; ++ks) {
                uint32_t wfh[4], wfl[4], qfh[4], qfl[4];
                const int ar = wm * 16 + lrow;
                const uint32_t ao = swz(ar, ks * 2 + lhi);
                ldsm4(wfh, stg_u + ao);
                ldsm4(wfl, stg_u + 8192u + ao);
                ldsm4(qfh, stg_u + 16384u + ao);
                ldsm4(qfl, stg_u + 24576u + ao);
                uint32_t sfh[4], sfl[4];
                const int br = kb * 64 + ks * 16 + lrow;
                const uint32_t bo = swz(br, wn * 2 + lhi);
                ldsm4t(sfh, sh_u + bo);
                ldsm4t(sfl, sl_u + bo);
                #pragma unroll
                for (int nt = 0; nt < 2; ++nt) {
                    mma16816(accU[nt], wfh, sfh + nt * 2);
                    mma16816(accU[nt], wfh, sfl + nt * 2);
                    mma16816(accU[nt], wfl, sfh + nt * 2);
                    mma16816(accO[nt], qfh, sfh + nt * 2);
                    mma16816(accO[nt], qfh, sfl + nt * 2);
                    mma16816(accO[nt], qfl, sfh + nt * 2);
                }
            }
            __syncthreads();
            if (kb < 3) {
                *(uint4*)(STG + sso)         = pf[0];
                *(uint4*)(STG + 8192 + sso)  = pf[1];
                *(uint4*)(STG + 16384 + sso) = pf[2];
                *(uint4*)(STG + 24576 + sso) = pf[3];
                __syncthreads();
            }
        }

        // U finalize (u = Uv - accU) -> UH/UL
        #pragma unroll
        for (int nt = 0; nt < 2; ++nt) {
            const int r0 = wm * 16 + erow;
            const int cc = wn * 16 + nt * 8 + ecol;
            const float u0 = UVS[r0 * 68 + cc]           - accU[nt][0];
            const float u1 = UVS[r0 * 68 + cc + 1]       - accU[nt][1];
            const float u2 = UVS[(r0 + 8) * 68 + cc]     - accU[nt][2];
            const float u3 = UVS[(r0 + 8) * 68 + cc + 1] - accU[nt][3];
            uint32_t hi, lo;
            split2(u0, u1, hi, lo);
            *(uint32_t*)(UH + swzb(r0, cc)) = hi;
            *(uint32_t*)(UL + swzb(r0, cc)) = lo;
            split2(u2, u3, hi, lo);
            *(uint32_t*)(UH + swzb(r0 + 8, cc)) = hi;
            *(uint32_t*)(UL + swzb(r0 + 8, cc)) = lo;
        }
        // stage P -> T0/T1, Kt block0 -> T2/T3
        {
            const size_t gp = (size_t)srow * 64 + sch * 8;
            *(uint4*)(STG + sso)         = *(const uint4*)(Ph + gp);
            *(uint4*)(STG + 8192 + sso)  = *(const uint4*)(Pl + gp);
            *(uint4*)(STG + 16384 + sso) = *(const uint4*)(Kth + gp);
            *(uint4*)(STG + 24576 + sso) = *(const uint4*)(Ktl + gp);
        }
        __syncthreads();

        // hoist U B-fragments for all 4 k-steps (shared by GEMM2b and GEMM3)
        uint32_t ufh[4][4], ufl[4][4];
        #pragma unroll
        for (int ks = 0; ks < 4; ++ks) {
            const int br = ks * 16 + lrow;
            const uint32_t bo = swz(br, wn * 2 + lhi);
            ldsm4t(ufh[ks], uh_u + bo);
            ldsm4t(ufl[ks], ul_u + bo);
        }

        // GEMM2b: accO += P·U
        #pragma unroll
        for (int ks = 0; ks < 4; ++ks) {
            uint32_t pfh[4], pfl[4];
            const int ar = wm * 16 + lrow;
            const uint32_t ao = swz(ar, ks * 2 + lhi);
            ldsm4(pfh, stg_u + ao);
            ldsm4(pfl, stg_u + 8192u + ao);
            #pragma unroll
            for (int nt = 0; nt < 2; ++nt) {
                mma16816(accO[nt], pfh, ufh[ks] + nt * 2);
                mma16816(accO[nt], pfh, ufl[ks] + nt * 2);
                mma16816(accO[nt], pfl, ufh[ks] + nt * 2);
            }
        }

        // O epilogue -> global
        #pragma unroll
        for (int nt = 0; nt < 2; ++nt) {
            const int r0 = wm * 16 + erow;
            const int cc = wn * 16 + nt * 8 + ecol;
            float2 w0; w0.x = accO[nt][0]; w0.y = accO[nt][1];
            float2 w1; w1.x = accO[nt][2]; w1.y = accO[nt][3];
            *(float2*)&g_o[(m0 + r0) * NV + h * DV_ + dv0 + cc]     = w0;
            *(float2*)&g_o[(m0 + r0 + 8) * NV + h * DV_ + dv0 + cc] = w1;
        }
        __syncthreads();   // retire P reads (T0/T1) before GEMM3 stores there

        // GEMM3: S += K^T · U, 4 kk-blocks, double-buffered halves
        for (int kkb = 0; kkb < 4; ++kkb) {
            float accS[2][4] = {};
            uint4 kf[2];
            if (kkb < 3) {
                const size_t gi = (size_t)((kkb + 1) * 64 + srow) * 64 + sch * 8;
                kf[0] = *(const uint4*)(Kth + gi);
                kf[1] = *(const uint4*)(Ktl + gi);
            }
            const uint32_t curH = stg_u + ((kkb & 1) ? 0u : 16384u);
            const uint32_t curL = stg_u + ((kkb & 1) ? 8192u : 24576u);
            #pragma unroll
            for (int ks = 0; ks < 4; ++ks) {
                uint32_t kfh[4], kfl[4];
                const int ar = wm * 16 + lrow;
                const uint32_t ao = swz(ar, ks * 2 + lhi);
                ldsm4(kfh, curH + ao);
                ldsm4(kfl, curL + ao);
                #pragma unroll
                for (int nt = 0; nt < 2; ++nt) {
                    mma16816(accS[nt], kfh, ufh[ks] + nt * 2);
                    mma16816(accS[nt], kfh, ufl[ks] + nt * 2);
                    mma16816(accS[nt], kfl, ufh[ks] + nt * 2);
                }
            }
            // S finalize: fp32 RMW + bf16 re-split for this 64-row block
            #pragma unroll
            for (int nt = 0; nt < 2; ++nt) {
                const int sr = kkb * 64 + wm * 16 + erow;
                const int sc = wn * 16 + nt * 8 + ecol;
                const float s0 = SF[sr * 68 + sc]           + accS[nt][0];
                const float s1 = SF[sr * 68 + sc + 1]       + accS[nt][1];
                const float s2 = SF[(sr + 8) * 68 + sc]     + accS[nt][2];
                const float s3 = SF[(sr + 8) * 68 + sc + 1] + accS[nt][3];
                SF[sr * 68 + sc]           = s0;
                SF[sr * 68 + sc + 1]       = s1;
                SF[(sr + 8) * 68 + sc]     = s2;
                SF[(sr + 8) * 68 + sc + 1] = s3;
                uint32_t hi, lo;
                split2(s0, s1, hi, lo);
                *(uint32_t*)(SH + swzb(sr, sc)) = hi;
                *(uint32_t*)(SL + swzb(sr, sc)) = lo;
                split2(s2, s3, hi, lo);
                *(uint32_t*)(SH + swzb(sr + 8, sc)) = hi;
                *(uint32_t*)(SL + swzb(sr + 8, sc)) = lo;
            }
            __syncthreads();
            if (kkb < 3) {
                char* oH = STG + ((kkb & 1) ? 16384 : 0);
                char* oL = STG + ((kkb & 1) ? 24576 : 8192);
                *(uint4*)(oH + sso) = kf[0];
                *(uint4*)(oL + sso) = kf[1];
                __syncthreads();
            }
        }
    }
}

// ---------------------------------------------------------------------------
// 6) per-head RMSNorm on g_o -> bf16 split g_oh/g_ol
// ---------------------------------------------------------------------------
__global__ void __launch_bounds__(256) rmsnorm_kernel(const float* __restrict__ w) {
    const int grp  = blockIdx.x * 8 + (threadIdx.x >> 5);
    const int lane = threadIdx.x & 31;
    const float* base = g_o + (size_t)grp * DV_;
    float4 v[4];
    float ss = 0.f;
    #pragma unroll
    for (int i = 0; i < 4; ++i) {
        v[i] = ((const float4*)base)[lane + 32 * i];
        ss += v[i].x * v[i].x + v[i].y * v[i].y + v[i].z * v[i].z + v[i].w * v[i].w;
    }
    #pragma unroll
    for (int off = 16; off > 0; off >>= 1) ss += __shfl_xor_sync(0xffffffffu, ss, off);
    const float rs = rsqrtf(ss * (1.0f / DV_) + 1e-5f);
    #pragma unroll
    for (int i = 0; i < 4; ++i) {
        const int idx = lane + 32 * i;
        const float4 wv = ((const float4*)w)[idx];
        const float4 o = make_float4(v[i].x * rs * wv.x, v[i].y * rs * wv.y,
                                     v[i].z * rs * wv.z, v[i].w * rs * wv.w);
        split_store4(o, g_oh, g_ol, (size_t)grp * DV_ + (size_t)idx * 4);
    }
}

// ---------------------------------------------------------------------------
// Launch
// ---------------------------------------------------------------------------
extern "C" void kernel_launch(void* const* d_in, const int* in_sizes, int n_in,
                              void* d_out, int out_size) {
    const float* x        = (const float*)d_in[0];
    const float* ln_w     = (const float*)d_in[1];
    const float* ln_b     = (const float*)d_in[2];
    const float* Wq       = (const float*)d_in[3];
    const float* Wk       = (const float*)d_in[4];
    const float* Wv       = (const float*)d_in[5];
    const float* Wb       = (const float*)d_in[6];
    const float* o_norm_w = (const float*)d_in[7];
    const float* Wo       = (const float*)d_in[8];
    float* out = (float*)d_out;

    cudaFuncSetAttribute(mma_gemm, cudaFuncAttributeMaxDynamicSharedMemorySize, MG_SMEM);
    cudaFuncSetAttribute(prep_kernel, cudaFuncAttributeMaxDynamicSharedMemorySize, P1_BYTES);
    cudaFuncSetAttribute(chunkscan_kernel, cudaFuncAttributeMaxDynamicSharedMemorySize, CS2_BYTES);

    __nv_bfloat16 *nh, *nl, *oh, *ol, *wqkvh, *wqkvl, *woh, *wol;
    cudaGetSymbolAddress((void**)&nh,    g_nh);
    cudaGetSymbolAddress((void**)&nl,    g_nl);
    cudaGetSymbolAddress((void**)&oh,    g_oh);
    cudaGetSymbolAddress((void**)&ol,    g_ol);
    cudaGetSymbolAddress((void**)&wqkvh, g_Wqkvt_h);
    cudaGetSymbolAddress((void**)&wqkvl, g_Wqkvt_l);
    cudaGetSymbolAddress((void**)&woh,   g_Wot_h);
    cudaGetSymbolAddress((void**)&wol,   g_Wot_l);
    float* gqkv;
    cudaGetSymbolAddress((void**)&gqkv, g_qkv);

    // 1) LayerNorm (+ bf16 split of normed, + fused beta)
    ln_kernel<<<M_, 256>>>(x, ln_w, ln_b, Wb);

    // 1b) all weight transposes+splits in one launch (6144 tiles)
    wtrans_all<<<6144, 256>>>(Wq, Wk, Wv, Wo);

    // 2) fused QKV projection (HMMA, silu fused, single launch N=4096)
    mma_gemm<<<dim3(NQKV / 128, M_ / 128), 256, MG_SMEM>>>(nh, nl, wqkvh, wqkvl, gqkv, nullptr, NQKV, D_, 1);

    // 5) chunked delta-rule (fused prep: l2norm q/k + W/Kt/Q/P + Uv)
    prep_kernel<<<NCH, 256, P1_BYTES>>>();
    chunkscan_kernel<<<B_ * H_ * 8, CST, CS2_BYTES>>>();

    // 6) RMSNorm (+ bf16 split of o)
    rmsnorm_kernel<<<(M_ * H_) / 8, 256>>>(o_norm_w);

    // 7) output projection + residual (HMMA)
    mma_gemm<<<dim3(D_ / 128, M_ / 128), 256, MG_SMEM>>>(oh, ol, woh, wol, out, x, D_, NV, 0);
}

// round 17
// speedup vs baseline: 1.1176x; 1.0214x over previous
#include <cuda_runtime.h>
#include <cuda_bf16.h>
#include <cstdint>

// Problem constants (fixed shapes)
#define B_  4
#define T_  2048
#define D_  1024
#define H_  4
#define DK_ 256
#define DV_ 512
#define M_  (B_ * T_)        // 8192 rows
#define NKV (H_ * DK_)       // 1024
#define NV  (H_ * DV_)       // 2048
#define NQKV 4096            // q(1024) | k(1024) | v(2048)
#define C_   64              // chunk length
#define NC_  32              // chunks per sequence
#define NCH  (B_ * H_ * NC_) // 512 chunk instances

typedef unsigned long long ull;

// ---------------------------------------------------------------------------
// Scratch (device globals; no dynamic allocation allowed)
// ---------------------------------------------------------------------------
__device__ float g_qkv[(size_t)M_ * NQKV];       // fused q|k|v projections
__device__ float g_beta[(size_t)M_ * H_];
__device__ float g_o[(size_t)M_ * NV];
// chunked-scan intermediates
__device__ float g_Uv [(size_t)NCH * C_ * DV_];  // [cIdx][i][dv] fp32
// split-bf16 chunkscan operands (written by prep kernel)
__device__ __nv_bfloat16 g_cWh [(size_t)NCH * C_ * DK_];  // [cIdx][i][kk]
__device__ __nv_bfloat16 g_cWl [(size_t)NCH * C_ * DK_];
__device__ __nv_bfloat16 g_cQh [(size_t)NCH * C_ * DK_];  // [cIdx][i][kk]
__device__ __nv_bfloat16 g_cQl [(size_t)NCH * C_ * DK_];
__device__ __nv_bfloat16 g_cKth[(size_t)NCH * DK_ * C_];  // [cIdx][kk][i]
__device__ __nv_bfloat16 g_cKtl[(size_t)NCH * DK_ * C_];
__device__ __nv_bfloat16 g_cPh [(size_t)NCH * C_ * C_];   // [cIdx][i][j]
__device__ __nv_bfloat16 g_cPl [(size_t)NCH * C_ * C_];
// bf16 split operands for projection GEMMs
__device__ __nv_bfloat16 g_nh[(size_t)M_ * D_];
__device__ __nv_bfloat16 g_nl[(size_t)M_ * D_];
__device__ __nv_bfloat16 g_oh[(size_t)M_ * NV];
__device__ __nv_bfloat16 g_ol[(size_t)M_ * NV];
__device__ __nv_bfloat16 g_Wqkvt_h[(size_t)NQKV * D_];    // [q|k|v rows][K]
__device__ __nv_bfloat16 g_Wqkvt_l[(size_t)NQKV * D_];
__device__ __nv_bfloat16 g_Wot_h[(size_t)D_ * NV];
__device__ __nv_bfloat16 g_Wot_l[(size_t)D_ * NV];

// ---------------------------------------------------------------------------
// f32x2 packed-FMA helpers (prep kernels)
// ---------------------------------------------------------------------------
__device__ __forceinline__ ull pack2(float x, float y) {
    ull r; asm("mov.b64 %0, {%1, %2};" : "=l"(r) : "f"(x), "f"(y)); return r;
}
__device__ __forceinline__ void unpack2(ull v, float& x, float& y) {
    asm("mov.b64 {%0, %1}, %2;" : "=f"(x), "=f"(y) : "l"(v));
}
__device__ __forceinline__ void ffma2(ull& d, ull a, ull b) {
    asm("fma.rn.f32x2 %0, %1, %2, %0;" : "+l"(d) : "l"(a), "l"(b));
}
__device__ __forceinline__ void mma4x4p(ull (&acc)[4][2], const float4 a4,
                                        const ull b0, const ull b1) {
    ull a;
    a = pack2(a4.x, a4.x); ffma2(acc[0][0], a, b0); ffma2(acc[0][1], a, b1);
    a = pack2(a4.y, a4.y); ffma2(acc[1][0], a, b0); ffma2(acc[1][1], a, b1);
    a = pack2(a4.z, a4.z); ffma2(acc[2][0], a, b0); ffma2(acc[2][1], a, b1);
    a = pack2(a4.w, a4.w); ffma2(acc[3][0], a, b0); ffma2(acc[3][1], a, b1);
}
__device__ __forceinline__ void unp4x4(const ull (&acc)[4][2], float (&o)[4][4]) {
    #pragma unroll
    for (int r = 0; r < 4; ++r) {
        unpack2(acc[r][0], o[r][0], o[r][1]);
        unpack2(acc[r][1], o[r][2], o[r][3]);
    }
}

__device__ __forceinline__ float sigmoidf_(float x) { return 1.0f / (1.0f + __expf(-x)); }
__device__ __forceinline__ float siluf_(float x)    { return x * sigmoidf_(x); }

// split pair (a,b) fp32 -> hi bf16x2 (as u32) + lo bf16x2 (as u32)
__device__ __forceinline__ void split2(float a, float b, uint32_t& hi, uint32_t& lo) {
    __nv_bfloat162 h, l;
    h.x = __float2bfloat16(a); h.y = __float2bfloat16(b);
    l.x = __float2bfloat16(a - __bfloat162float(h.x));
    l.y = __float2bfloat16(b - __bfloat162float(h.y));
    hi = *(uint32_t*)&h; lo = *(uint32_t*)&l;
}

__device__ __forceinline__ void split_store4(const float4 v,
                                             __nv_bfloat16* __restrict__ hp,
                                             __nv_bfloat16* __restrict__ lp,
                                             size_t idx) {
    uint32_t h0, l0, h1, l1;
    split2(v.x, v.y, h0, l0);
    split2(v.z, v.w, h1, l1);
    *(uint32_t*)(hp + idx)     = h0;
    *(uint32_t*)(hp + idx + 2) = h1;
    *(uint32_t*)(lp + idx)     = l0;
    *(uint32_t*)(lp + idx + 2) = l1;
}

// ---------------------------------------------------------------------------
// mma.sync helpers (arch-portable HMMA)
// ---------------------------------------------------------------------------
__device__ __forceinline__ uint32_t smem_u32(const void* p) {
    uint32_t a;
    asm("{ .reg .u64 t; cvta.to.shared.u64 t, %1; cvt.u32.u64 %0, t; }" : "=r"(a) : "l"(p));
    return a;
}
__device__ __forceinline__ void ldsm4(uint32_t* r, uint32_t addr) {
    asm volatile("ldmatrix.sync.aligned.m8n8.x4.shared.b16 {%0,%1,%2,%3}, [%4];"
        : "=r"(r[0]), "=r"(r[1]), "=r"(r[2]), "=r"(r[3]) : "r"(addr));
}
__device__ __forceinline__ void ldsm4t(uint32_t* r, uint32_t addr) {
    asm volatile("ldmatrix.sync.aligned.m8n8.x4.trans.shared.b16 {%0,%1,%2,%3}, [%4];"
        : "=r"(r[0]), "=r"(r[1]), "=r"(r[2]), "=r"(r[3]) : "r"(addr));
}
__device__ __forceinline__ void mma16816(float* c, const uint32_t* a, const uint32_t* b) {
    asm volatile(
        "mma.sync.aligned.m16n8k16.row.col.f32.bf16.bf16.f32 "
        "{%0,%1,%2,%3}, {%4,%5,%6,%7}, {%8,%9}, {%0,%1,%2,%3};"
        : "+f"(c[0]), "+f"(c[1]), "+f"(c[2]), "+f"(c[3])
        : "r"(a[0]), "r"(a[1]), "r"(a[2]), "r"(a[3]), "r"(b[0]), "r"(b[1]));
}

// 64-col bf16 tile swizzle: rows of 128B, 8 chunks of 16B, chunk ^ (row&7)
__device__ __forceinline__ uint32_t swz(int row, int ch) {
    return (uint32_t)((row << 7) + ((ch ^ (row & 7)) << 4));
}
// byte offset of bf16 element (row, col), col even
__device__ __forceinline__ uint32_t swzb(int row, int col) {
    return (uint32_t)((row << 7) + ((((col >> 3) ^ (row & 7))) << 4) + ((col & 7) << 1));
}

// ---------------------------------------------------------------------------
// 1) LayerNorm -> g_nh/g_nl (bf16 split) + fused beta = sigmoid(normed @ Wb)
// ---------------------------------------------------------------------------
__global__ void __launch_bounds__(256) ln_kernel(const float* __restrict__ x,
                                                 const float* __restrict__ w,
                                                 const float* __restrict__ b,
                                                 const float* __restrict__ Wb) {
    const int row = blockIdx.x;
    const int tid = threadIdx.x;
    const float4 v = ((const float4*)(x + (size_t)row * D_))[tid];

    float s  = v.x + v.y + v.z + v.w;
    float s2 = v.x * v.x + v.y * v.y + v.z * v.z + v.w * v.w;
    #pragma unroll
    for (int off = 16; off > 0; off >>= 1) {
        s  += __shfl_xor_sync(0xffffffffu, s,  off);
        s2 += __shfl_xor_sync(0xffffffffu, s2, off);
    }
    __shared__ float sh[16];
    __shared__ float bsh[32];
    const int wid = tid >> 5, lane = tid & 31;
    if (lane == 0) { sh[wid] = s; sh[8 + wid] = s2; }
    __syncthreads();
    float ts = 0.f, ts2 = 0.f;
    #pragma unroll
    for (int i = 0; i < 8; ++i) { ts += sh[i]; ts2 += sh[8 + i]; }

    const float mean = ts * (1.0f / D_);
    const float var  = ts2 * (1.0f / D_) - mean * mean;
    const float rstd = rsqrtf(var + 1e-5f);

    const float4 wv = ((const float4*)w)[tid];
    const float4 bv = ((const float4*)b)[tid];
    float4 o;
    o.x = (v.x - mean) * rstd * wv.x + bv.x;
    o.y = (v.y - mean) * rstd * wv.y + bv.y;
    o.z = (v.z - mean) * rstd * wv.z + bv.z;
    o.w = (v.w - mean) * rstd * wv.w + bv.w;
    const size_t base = (size_t)row * D_;
    split_store4(o, g_nh, g_nl, base + (size_t)tid * 4);

    // fused beta: partial dot of normed row with Wb[:,0..3]
    float a0, a1, a2, a3;
    {
        const float4 w0 = ((const float4*)Wb)[tid * 4 + 0];
        const float4 w1 = ((const float4*)Wb)[tid * 4 + 1];
        const float4 w2 = ((const float4*)Wb)[tid * 4 + 2];
        const float4 w3 = ((const float4*)Wb)[tid * 4 + 3];
        a0 = o.x * w0.x + o.y * w1.x + o.z * w2.x + o.w * w3.x;
        a1 = o.x * w0.y + o.y * w1.y + o.z * w2.y + o.w * w3.y;
        a2 = o.x * w0.z + o.y * w1.z + o.z * w2.z + o.w * w3.z;
        a3 = o.x * w0.w + o.y * w1.w + o.z * w2.w + o.w * w3.w;
    }
    #pragma unroll
    for (int off = 16; off > 0; off >>= 1) {
        a0 += __shfl_xor_sync(0xffffffffu, a0, off);
        a1 += __shfl_xor_sync(0xffffffffu, a1, off);
        a2 += __shfl_xor_sync(0xffffffffu, a2, off);
        a3 += __shfl_xor_sync(0xffffffffu, a3, off);
    }
    if (lane == 0) {
        bsh[wid * 4 + 0] = a0; bsh[wid * 4 + 1] = a1;
        bsh[wid * 4 + 2] = a2; bsh[wid * 4 + 3] = a3;
    }
    __syncthreads();
    if (tid == 0) {
        float t0 = 0, t1 = 0, t2 = 0, t3 = 0;
        #pragma unroll
        for (int wq = 0; wq < 8; ++wq) {
            t0 += bsh[wq * 4 + 0]; t1 += bsh[wq * 4 + 1];
            t2 += bsh[wq * 4 + 2]; t3 += bsh[wq * 4 + 3];
        }
        *(float4*)&g_beta[(size_t)row * 4] =
            make_float4(sigmoidf_(t0), sigmoidf_(t1), sigmoidf_(t2), sigmoidf_(t3));
    }
}

// ---------------------------------------------------------------------------
// 1b) all-weights transpose + bf16 split in ONE launch.
// ---------------------------------------------------------------------------
__global__ void __launch_bounds__(256) wtrans_all(const float* __restrict__ Wq,
                                                  const float* __restrict__ Wk,
                                                  const float* __restrict__ Wv,
                                                  const float* __restrict__ Wo) {
    __shared__ float tile[32][33];
    int t = blockIdx.x;
    const float* W;
    __nv_bfloat16 *Th, *Tl;
    int K, N;
    if (t < 1024) {
        W = Wq; Th = g_Wqkvt_h; Tl = g_Wqkvt_l; K = D_; N = NKV;
    } else if (t < 2048) {
        t -= 1024;
        W = Wk; Th = g_Wqkvt_h + (size_t)1024 * D_; Tl = g_Wqkvt_l + (size_t)1024 * D_;
        K = D_; N = NKV;
    } else if (t < 4096) {
        t -= 2048;
        W = Wv; Th = g_Wqkvt_h + (size_t)2048 * D_; Tl = g_Wqkvt_l + (size_t)2048 * D_;
        K = D_; N = NV;
    } else {
        t -= 4096;
        W = Wo; Th = g_Wot_h; Tl = g_Wot_l; K = NV; N = D_;
    }
    const int nbx = N >> 5;
    const int bx = t % nbx, by = t / nbx;
    const int tx = threadIdx.x & 31, ty = threadIdx.x >> 5;
    const int k0 = by * 32, n0 = bx * 32;
    #pragma unroll
    for (int i = 0; i < 32; i += 8)
        tile[ty + i][tx] = W[(size_t)(k0 + ty + i) * N + n0 + tx];
    __syncthreads();
    #pragma unroll
    for (int i = 0; i < 32; i += 8) {
        const float v = tile[tx][ty + i];
        const size_t oi = (size_t)(n0 + ty + i) * K + k0 + tx;
        const __nv_bfloat16 h = __float2bfloat16(v);
        Th[oi] = h;
        Tl[oi] = __float2bfloat16(v - __bfloat162float(h));
    }
}

// ---------------------------------------------------------------------------
// 2) HMMA GEMM (R6 proven: register-prefetch double-buffer)
// ---------------------------------------------------------------------------
#define MG_STAGE 65536
#define MG_SMEM  (2 * MG_STAGE)

__global__ void __launch_bounds__(256, 1)
mma_gemm(const __nv_bfloat16* __restrict__ Ah, const __nv_bfloat16* __restrict__ Al,
         const __nv_bfloat16* __restrict__ Bh, const __nv_bfloat16* __restrict__ Bl,
         float* __restrict__ C, const float* __restrict__ resid,
         int N, int K, int do_silu) {
    extern __shared__ char smx[];
    const uint32_t sbase = smem_u32(smx);
    const int tid = threadIdx.x;
    const int lane = tid & 31;
    const int wid = tid >> 5;
    const int wm = wid >> 2;
    const int wn = wid & 3;
    const int m0w = wm * 64, n0w = wn * 32;

    const size_t bm = (size_t)blockIdx.y * 128;
    const size_t bn = (size_t)blockIdx.x * 128;
    const __nv_bfloat16* pAh = Ah + bm * K;
    const __nv_bfloat16* pAl = Al + bm * K;
    const __nv_bfloat16* pBh = Bh + bn * K;
    const __nv_bfloat16* pBl = Bl + bn * K;

    {
        char* stg = smx;
        #pragma unroll
        for (int p = 0; p < 4; ++p) {
            const int c = tid + (p << 8);
            const int row = c >> 3, ch = c & 7;
            const size_t gi = (size_t)row * K + (ch << 3);
            const int off = (row << 7) + (((ch ^ (row & 7))) << 4);
            *(uint4*)(stg + off)         = *(const uint4*)(pAh + gi);
            *(uint4*)(stg + 16384 + off) = *(const uint4*)(pAl + gi);
            *(uint4*)(stg + 32768 + off) = *(const uint4*)(pBh + gi);
            *(uint4*)(stg + 49152 + off) = *(const uint4*)(pBl + gi);
        }
    }
    __syncthreads();

    float acc[4][4][4];
    #pragma unroll
    for (int i = 0; i < 4; ++i)
        #pragma unroll
        for (int j = 0; j < 4; ++j)
            #pragma unroll
            for (int q = 0; q < 4; ++q) acc[i][j][q] = 0.f;

    const int a_row = m0w + (lane & 15);
    const int a_chs = lane >> 4;
    const int b_row = n0w + ((lane >> 3) & 2) * 4 + (lane & 7);
    const int b_chs = (lane >> 3) & 1;

    const int KB = K >> 6;
    for (int kb = 0; kb < KB; ++kb) {
        const uint32_t stg = sbase + (uint32_t)(kb & 1) * MG_STAGE;
        const bool hasNext = (kb + 1) < KB;

        uint4 vAh[4], vAl[4], vBh[4], vBl[4];
        if (hasNext) {
            const int k0 = (kb + 1) << 6;
            #pragma unroll
            for (int p = 0; p < 4; ++p) {
                const int c = tid + (p << 8);
                const int row = c >> 3, ch = c & 7;
                const size_t gi = (size_t)row * K + k0 + (ch << 3);
                vAh[p] = *(const uint4*)(pAh + gi);
                vAl[p] = *(const uint4*)(pAl + gi);
                vBh[p] = *(const uint4*)(pBh + gi);
                vBl[p] = *(const uint4*)(pBl + gi);
            }
        }

        #pragma unroll
        for (int ks = 0; ks < 4; ++ks) {
            uint32_t afh[4][4], afl[4][4];
            #pragma unroll
            for (int mt = 0; mt < 4; ++mt) {
                const int row = a_row + mt * 16;
                const int ch  = ks * 2 + a_chs;
                const uint32_t off = (uint32_t)((row << 7) + ((ch ^ (row & 7)) << 4));
                ldsm4(afh[mt], stg + off);
                ldsm4(afl[mt], stg + 16384u + off);
            }
            uint32_t bfh[2][4], bfl[2][4];
            #pragma unroll
            for (int np = 0; np < 2; ++np) {
                const int row = b_row + np * 16;
                const int ch  = ks * 2 + b_chs;
                const uint32_t off = (uint32_t)((row << 7) + ((ch ^ (row & 7)) << 4));
                ldsm4(bfh[np], stg + 32768u + off);
                ldsm4(bfl[np], stg + 49152u + off);
            }
            #pragma unroll
            for (int mt = 0; mt < 4; ++mt) {
                #pragma unroll
                for (int nt = 0; nt < 4; ++nt) {
                    const uint32_t* bh = &bfh[nt >> 1][(nt & 1) * 2];
                    const uint32_t* bl = &bfl[nt >> 1][(nt & 1) * 2];
                    mma16816(acc[mt][nt], afh[mt], bh);
                    mma16816(acc[mt][nt], afh[mt], bl);
                    mma16816(acc[mt][nt], afl[mt], bh);
                }
            }
        }

        if (hasNext) {
            char* nst = smx + ((kb + 1) & 1) * MG_STAGE;
            #pragma unroll
            for (int p = 0; p < 4; ++p) {
                const int c = tid + (p << 8);
                const int row = c >> 3, ch = c & 7;
                const int off = (row << 7) + ((ch ^ (row & 7)) << 4);
                *(uint4*)(nst + off)         = vAh[p];
                *(uint4*)(nst + 16384 + off) = vAl[p];
                *(uint4*)(nst + 32768 + off) = vBh[p];
                *(uint4*)(nst + 49152 + off) = vBl[p];
            }
        }
        __syncthreads();
    }

    const int erow = lane >> 2;
    const int ecol = (lane & 3) * 2;
    #pragma unroll
    for (int mt = 0; mt < 4; ++mt) {
        #pragma unroll
        for (int nt = 0; nt < 4; ++nt) {
            const size_t gr0 = bm + m0w + mt * 16 + erow;
            const size_t gc  = bn + n0w + nt * 8 + ecol;
            float v0 = acc[mt][nt][0], v1 = acc[mt][nt][1];
            float v2 = acc[mt][nt][2], v3 = acc[mt][nt][3];
            if (do_silu) { v0 = siluf_(v0); v1 = siluf_(v1); v2 = siluf_(v2); v3 = siluf_(v3); }
            if (resid != nullptr) {
                const float2 r0 = *(const float2*)&resid[gr0 * N + gc];
                const float2 r1 = *(const float2*)&resid[(gr0 + 8) * N + gc];
                v0 += r0.x; v1 += r0.y; v2 += r1.x; v3 += r1.y;
            }
            float2 w0; w0.x = v0; w0.y = v1;
            float2 w1; w1.x = v2; w1.y = v3;
            *(float2*)&C[gr0 * N + gc]       = w0;
            *(float2*)&C[(gr0 + 8) * N + gc] = w1;
        }
    }
}

// ---------------------------------------------------------------------------
// 5a) fused prep: prep1 (l2norm q/k, M, W, Kt, Q, P) + prep2 (Uv) in one kernel
//     Substitution loops are barrier-free (per-thread-column independence).
// ---------------------------------------------------------------------------
#define P1_FLOATS (17408 + 17408 + 4352 + 64 + 64 + 272)
#define P1_BYTES  (P1_FLOATS * 4)

__global__ void __launch_bounds__(256, 1) prep_kernel() {
    extern __shared__ float sm1[];
    float* Kt  = sm1;            // [256][68]
    float* wb  = sm1 + 17408;    // [64][260]
    float* Qts = sm1 + 17408;    // [256][68]  (aliases wb)
    float* vb  = sm1;            // [64][520]  (aliases Kt+wb, used after P)
    float* Ms  = sm1 + 34816;    // [64][68]
    float* bsm = sm1 + 39168;    // [64]
    float* rsk = sm1 + 39232;    // [64]
    float* nrm = sm1 + 39296;    // [4][68]

    const int tid  = threadIdx.x;
    const int cIdx = blockIdx.x;
    const int n = cIdx & 31, h = (cIdx >> 5) & 3, b = cIdx >> 7;
    const size_t m0 = (size_t)b * T_ + n * C_;
    const int hK = h * DK_;
    const int hV = h * DV_;

    if (tid < 64) bsm[tid] = g_beta[(m0 + tid) * H_ + h];

    #pragma unroll 4
    for (int p = 0; p < 16; ++p) {
        const int idx = tid + p * 256;
        const int i = idx >> 6, c4 = idx & 63;
        const float4 v = *(const float4*)&g_qkv[(m0 + i) * NQKV + 1024 + hK + c4 * 4];
        Kt[(c4 * 4 + 0) * 68 + i] = v.x;
        Kt[(c4 * 4 + 1) * 68 + i] = v.y;
        Kt[(c4 * 4 + 2) * 68 + i] = v.z;
        Kt[(c4 * 4 + 3) * 68 + i] = v.w;
    }
    __syncthreads();

    {
        const int i = tid & 63, part = tid >> 6;
        float ss = 0.f;
        #pragma unroll 4
        for (int kk = part * 64; kk < part * 64 + 64; ++kk) {
            const float vv = Kt[kk * 68 + i];
            ss += vv * vv;
        }
        nrm[part * 68 + i] = ss;
    }
    __syncthreads();
    if (tid < 64)
        rsk[tid] = rsqrtf(nrm[tid] + nrm[68 + tid] + nrm[136 + tid] + nrm[204 + tid] + 1e-6f);
    __syncthreads();
    for (int idx = tid; idx < 4352; idx += 256) {
        const int kk = idx / 17, f4 = idx % 17;
        if (f4 < 16) {
            float4 v = *(float4*)&Kt[kk * 68 + f4 * 4];
            const float4 r = *(const float4*)&rsk[f4 * 4];
            v.x *= r.x; v.y *= r.y; v.z *= r.z; v.w *= r.w;
            *(float4*)&Kt[kk * 68 + f4 * 4] = v;
        }
    }
    __syncthreads();

    const int ty = tid >> 4, tx = tid & 15;
    const int ti4 = ty * 4, tj4 = tx * 4;

    #pragma unroll 4
    for (int p = 0; p < 16; ++p) {
        const int idx = tid + p * 256;
        const int i = idx >> 6, c4 = idx & 63;
        const float bb = bsm[i];
        float4 v;
        v.x = bb * Kt[(c4 * 4 + 0) * 68 + i];
        v.y = bb * Kt[(c4 * 4 + 1) * 68 + i];
        v.z = bb * Kt[(c4 * 4 + 2) * 68 + i];
        v.w = bb * Kt[(c4 * 4 + 3) * 68 + i];
        *(float4*)&wb[i * 260 + c4 * 4] = v;
    }

    {
        ull acc[4][2] = {};
        #pragma unroll 4
        for (int kk = 0; kk < 256; ++kk) {
            const float4 a4 = *(const float4*)&Kt[kk * 68 + ti4];
            const float4 b4 = *(const float4*)&Kt[kk * 68 + tj4];
            mma4x4p(acc, a4, pack2(b4.x, b4.y), pack2(b4.z, b4.w));
        }
        float mo[4][4]; unp4x4(acc, mo);
        #pragma unroll
        for (int r = 0; r < 4; ++r) {
            const int i = ti4 + r;
            const float bi = bsm[i];
            #pragma unroll
            for (int cc = 0; cc < 4; ++cc) {
                const int j = tj4 + cc;
                Ms[i * 68 + j] = (j < i) ? bi * mo[r][cc] : 0.f;
            }
        }
    }

    {
        __nv_bfloat16* kth = g_cKth + (size_t)cIdx * 16384;
        __nv_bfloat16* ktl = g_cKtl + (size_t)cIdx * 16384;
        for (int idx = tid; idx < 8192; idx += 256) {
            const int kk = idx >> 5, i2 = (idx & 31) * 2;
            uint32_t hi, lo;
            split2(Kt[kk * 68 + i2], Kt[kk * 68 + i2 + 1], hi, lo);
            *(uint32_t*)(kth + kk * 64 + i2) = hi;
            *(uint32_t*)(ktl + kk * 64 + i2) = lo;
        }
    }
    __syncthreads();

    // barrier-free forward substitution: thread owns column tid
    for (int i = 1; i < 64; ++i) {
        const float* mr = Ms + i * 68;
        float a0 = 0.f, a1 = 0.f, a2 = 0.f, a3 = 0.f;
        int j = 0;
        for (; j + 4 <= i; j += 4) {
            a0 += mr[j + 0] * wb[(j + 0) * 260 + tid];
            a1 += mr[j + 1] * wb[(j + 1) * 260 + tid];
            a2 += mr[j + 2] * wb[(j + 2) * 260 + tid];
            a3 += mr[j + 3] * wb[(j + 3) * 260 + tid];
        }
        for (; j < i; ++j) a0 += mr[j] * wb[j * 260 + tid];
        wb[i * 260 + tid] -= (a0 + a1) + (a2 + a3);
    }
    __syncthreads();   // all columns final before cross-column split store

    {
        __nv_bfloat16* wh = g_cWh + (size_t)cIdx * 16384;
        __nv_bfloat16* wl = g_cWl + (size_t)cIdx * 16384;
        for (int idx = tid; idx < 8192; idx += 256) {
            const int i = idx >> 7, kk2 = (idx & 127) * 2;
            uint32_t hi, lo;
            split2(wb[i * 260 + kk2], wb[i * 260 + kk2 + 1], hi, lo);
            *(uint32_t*)(wh + i * 256 + kk2) = hi;
            *(uint32_t*)(wl + i * 256 + kk2) = lo;
        }
    }
    __syncthreads();   // wb dead; Qts may now overwrite

    #pragma unroll 4
    for (int p = 0; p < 16; ++p) {
        const int idx = tid + p * 256;
        const int i = idx >> 6, c4 = idx & 63;
        const float4 v = *(const float4*)&g_qkv[(m0 + i) * NQKV + hK + c4 * 4];
        Qts[(c4 * 4 + 0) * 68 + i] = v.x;
        Qts[(c4 * 4 + 1) * 68 + i] = v.y;
        Qts[(c4 * 4 + 2) * 68 + i] = v.z;
        Qts[(c4 * 4 + 3) * 68 + i] = v.w;
    }
    __syncthreads();

    {
        const int i = tid & 63, part = tid >> 6;
        float ss = 0.f;
        #pragma unroll 4
        for (int kk = part * 64; kk < part * 64 + 64; ++kk) {
            const float vv = Qts[kk * 68 + i];
            ss += vv * vv;
        }
        nrm[part * 68 + i] = ss;
    }
    __syncthreads();
    if (tid < 64)
        rsk[tid] = rsqrtf(nrm[tid] + nrm[68 + tid] + nrm[136 + tid] + nrm[204 + tid] + 1e-6f) * 0.0625f;
    __syncthreads();
    for (int idx = tid; idx < 4352; idx += 256) {
        const int kk = idx / 17, f4 = idx % 17;
        if (f4 < 16) {
            float4 v = *(float4*)&Qts[kk * 68 + f4 * 4];
            const float4 r = *(const float4*)&rsk[f4 * 4];
            v.x *= r.x; v.y *= r.y; v.z *= r.z; v.w *= r.w;
            *(float4*)&Qts[kk * 68 + f4 * 4] = v;
        }
    }
    __syncthreads();

    {
        __nv_bfloat16* qh = g_cQh + (size_t)cIdx * 16384;
        __nv_bfloat16* ql = g_cQl + (size_t)cIdx * 16384;
        for (int idx = tid; idx < 8192; idx += 256) {
            const int i = idx >> 7, kk2 = (idx & 127) * 2;
            uint32_t hi, lo;
            split2(Qts[kk2 * 68 + i], Qts[(kk2 + 1) * 68 + i], hi, lo);
            *(uint32_t*)(qh + i * 256 + kk2) = hi;
            *(uint32_t*)(ql + i * 256 + kk2) = lo;
        }
    }

    {
        ull acc[4][2] = {};
        #pragma unroll 4
        for (int kk = 0; kk < 256; ++kk) {
            const float4 a4 = *(const float4*)&Qts[kk * 68 + ti4];
            const float4 b4 = *(const float4*)&Kt[kk * 68 + tj4];
            mma4x4p(acc, a4, pack2(b4.x, b4.y), pack2(b4.z, b4.w));
        }
        float po[4][4]; unp4x4(acc, po);
        __nv_bfloat16* ph = g_cPh + (size_t)cIdx * 4096;
        __nv_bfloat16* pl = g_cPl + (size_t)cIdx * 4096;
        #pragma unroll
        for (int r = 0; r < 4; ++r) {
            const int i = ti4 + r;
            const float v0 = (tj4 + 0 <= i) ? po[r][0] : 0.f;
            const float v1 = (tj4 + 1 <= i) ? po[r][1] : 0.f;
            const float v2 = (tj4 + 2 <= i) ? po[r][2] : 0.f;
            const float v3 = (tj4 + 3 <= i) ? po[r][3] : 0.f;
            uint32_t hi, lo;
            split2(v0, v1, hi, lo);
            *(uint32_t*)(ph + i * 64 + tj4)     = hi;
            *(uint32_t*)(pl + i * 64 + tj4)     = lo;
            split2(v2, v3, hi, lo);
            *(uint32_t*)(ph + i * 64 + tj4 + 2) = hi;
            *(uint32_t*)(pl + i * 64 + tj4 + 2) = lo;
        }
    }
    __syncthreads();   // Kt & Qts dead; vb may now overwrite

    // ---- fused prep2: Uv = (I+M)^{-1} (beta V), Ms still resident ----
    #pragma unroll 4
    for (int p = 0; p < 32; ++p) {
        const int idx = tid + p * 256;
        const int i = idx >> 7, c4 = idx & 127;
        float4 v = *(const float4*)&g_qkv[(m0 + i) * NQKV + 2048 + hV + c4 * 4];
        const float bb = bsm[i];
        v.x *= bb; v.y *= bb; v.z *= bb; v.w *= bb;
        *(float4*)&vb[i * 520 + c4 * 4] = v;
    }
    __syncthreads();

    // barrier-free forward substitution: thread owns packed columns 2*tid, 2*tid+1
    const int col2 = 2 * tid;
    for (int i = 1; i < 64; ++i) {
        const float* mr = Ms + i * 68;
        ull acc = 0ull;
        for (int j = 0; j < i; ++j) {
            const float m = mr[j];
            const ull v = *(const ull*)&vb[j * 520 + col2];
            ffma2(acc, pack2(m, m), v);
        }
        float ax, ay; unpack2(acc, ax, ay);
        vb[i * 520 + col2]     -= ax;
        vb[i * 520 + col2 + 1] -= ay;
    }
    __syncthreads();   // all columns final before cross-column store

    float* uo = g_Uv + (size_t)cIdx * (C_ * DV_);
    #pragma unroll 4
    for (int p = 0; p < 32; ++p) {
        const int idx = tid + p * 256;
        const int i = idx >> 7, c4 = idx & 127;
        *(float4*)&uo[i * DV_ + c4 * 4] = *(const float4*)&vb[i * 520 + c4 * 4];
    }
}

// ---------------------------------------------------------------------------
// 5c) chunkscan (HMMA, 512 threads / 16 warps, warp grid 4x4 — R9 best)
// ---------------------------------------------------------------------------
#define CST 512
#define CS2_SH   69632
#define CS2_SL   102400
#define CS2_UH   135168
#define CS2_UL   143360
#define CS2_UVS  151552
#define CS2_STG  168960
#define CS2_BYTES 201728

__global__ void __launch_bounds__(CST, 1) chunkscan_kernel() {
    extern __shared__ char sm3[];
    float* SF  = (float*)sm3;                 // [256][68] fp32
    char*  SH  = sm3 + CS2_SH;                // [256][64] bf16 swizzled
    char*  SL  = sm3 + CS2_SL;
    char*  UH  = sm3 + CS2_UH;                // [64][64] bf16 swizzled
    char*  UL  = sm3 + CS2_UL;
    float* UVS = (float*)(sm3 + CS2_UVS);     // [64][68] fp32
    char*  STG = sm3 + CS2_STG;               // 4 x 8192B tiles

    const uint32_t stg_u = smem_u32(STG);
    const uint32_t sh_u  = smem_u32(SH);
    const uint32_t sl_u  = smem_u32(SL);
    const uint32_t uh_u  = smem_u32(UH);
    const uint32_t ul_u  = smem_u32(UL);

    const int tid  = threadIdx.x;
    const int lane = tid & 31, wid = tid >> 5;      // 16 warps
    const int wm = wid >> 2, wn = wid & 3;          // 4 x 4
    const int erow = lane >> 2, ecol = (lane & 3) * 2;
    const int lrow = lane & 15, lhi = lane >> 4;
    const int c = blockIdx.x & 7, h = (blockIdx.x >> 3) & 3, b = blockIdx.x >> 5;
    const int dv0 = c * 64;
    const int srow = tid >> 3, sch = tid & 7;       // staging role (512 = 64 rows x 8 ch)
    const uint32_t sso = swz(srow, sch);

    for (int i = tid; i < 17408; i += CST) SF[i] = 0.f;
    for (int i = tid; i < 8192; i += CST) { ((uint32_t*)SH)[i] = 0u; ((uint32_t*)SL)[i] = 0u; }
    __syncthreads();

    for (int n = 0; n < NC_; ++n) {
        const int cIdx = b * 128 + h * 32 + n;
        const __nv_bfloat16* Wh  = g_cWh  + (size_t)cIdx * 16384;
        const __nv_bfloat16* Wl  = g_cWl  + (size_t)cIdx * 16384;
        const __nv_bfloat16* Qh  = g_cQh  + (size_t)cIdx * 16384;
        const __nv_bfloat16* Ql  = g_cQl  + (size_t)cIdx * 16384;
        const __nv_bfloat16* Kth = g_cKth + (size_t)cIdx * 16384;
        const __nv_bfloat16* Ktl = g_cKtl + (size_t)cIdx * 16384;
        const __nv_bfloat16* Ph  = g_cPh  + (size_t)cIdx * 4096;
        const __nv_bfloat16* Pl  = g_cPl  + (size_t)cIdx * 4096;
        const float* Uvg = g_Uv + (size_t)cIdx * 32768 + dv0;
        const size_t m0  = (size_t)b * T_ + n * 64;

        // stage W/Q block 0 + Uv
        {
            const size_t gi = (size_t)srow * 256 + sch * 8;
            *(uint4*)(STG + sso)         = *(const uint4*)(Wh + gi);
            *(uint4*)(STG + 8192 + sso)  = *(const uint4*)(Wl + gi);
            *(uint4*)(STG + 16384 + sso) = *(const uint4*)(Qh + gi);
            *(uint4*)(STG + 24576 + sso) = *(const uint4*)(Ql + gi);
        }
        #pragma unroll
        for (int j = 0; j < 2; ++j) {
            const int idx = tid + j * CST;
            const int r = idx >> 4, c4 = idx & 15;
            *(float4*)&UVS[r * 68 + c4 * 4] = *(const float4*)&Uvg[(size_t)r * DV_ + c4 * 4];
        }
        __syncthreads();

        float accU[2][4] = {}, accO[2][4] = {};

        // GEMM1+2a: accU = W·S, accO = Q·S over 4 kk-blocks
        for (int kb = 0; kb < 4; ++kb) {
            uint4 pf[4];
            if (kb < 3) {
                const size_t gi = (size_t)srow * 256 + (kb + 1) * 64 + sch * 8;
                pf[0] = *(const uint4*)(Wh + gi);
                pf[1] = *(const uint4*)(Wl + gi);
                pf[2] = *(const uint4*)(Qh + gi);
                pf[3] = *(const uint4*)(Ql + gi);
            }
            #pragma unroll
            for (int ks = 0; ks < 4; ++ks) {
                uint32_t wfh[4], wfl[4], qfh[4], qfl[4];
                const int ar = wm * 16 + lrow;
                const uint32_t ao = swz(ar, ks * 2 + lhi);
                ldsm4(wfh, stg_u + ao);
                ldsm4(wfl, stg_u + 8192u + ao);
                ldsm4(qfh, stg_u + 16384u + ao);
                ldsm4(qfl, stg_u + 24576u + ao);
                uint32_t sfh[4], sfl[4];
                const int br = kb * 64 + ks * 16 + lrow;
                const uint32_t bo = swz(br, wn * 2 + lhi);
                ldsm4t(sfh, sh_u + bo);
                ldsm4t(sfl, sl_u + bo);
                #pragma unroll
                for (int nt = 0; nt < 2; ++nt) {
                    mma16816(accU[nt], wfh, sfh + nt * 2);
                    mma16816(accU[nt], wfh, sfl + nt * 2);
                    mma16816(accU[nt], wfl, sfh + nt * 2);
                    mma16816(accO[nt], qfh, sfh + nt * 2);
                    mma16816(accO[nt], qfh, sfl + nt * 2);
                    mma16816(accO[nt], qfl, sfh + nt * 2);
                }
            }
            __syncthreads();
            if (kb < 3) {
                *(uint4*)(STG + sso)         = pf[0];
                *(uint4*)(STG + 8192 + sso)  = pf[1];
                *(uint4*)(STG + 16384 + sso) = pf[2];
                *(uint4*)(STG + 24576 + sso) = pf[3];
                __syncthreads();
            }
        }

        // U finalize (u = Uv - accU) -> UH/UL
        #pragma unroll
        for (int nt = 0; nt < 2; ++nt) {
            const int r0 = wm * 16 + erow;
            const int cc = wn * 16 + nt * 8 + ecol;
            const float u0 = UVS[r0 * 68 + cc]           - accU[nt][0];
            const float u1 = UVS[r0 * 68 + cc + 1]       - accU[nt][1];
            const float u2 = UVS[(r0 + 8) * 68 + cc]     - accU[nt][2];
            const float u3 = UVS[(r0 + 8) * 68 + cc + 1] - accU[nt][3];
            uint32_t hi, lo;
            split2(u0, u1, hi, lo);
            *(uint32_t*)(UH + swzb(r0, cc)) = hi;
            *(uint32_t*)(UL + swzb(r0, cc)) = lo;
            split2(u2, u3, hi, lo);
            *(uint32_t*)(UH + swzb(r0 + 8, cc)) = hi;
            *(uint32_t*)(UL + swzb(r0 + 8, cc)) = lo;
        }
        // stage P -> T0/T1, Kt block0 -> T2/T3
        {
            const size_t gp = (size_t)srow * 64 + sch * 8;
            *(uint4*)(STG + sso)         = *(const uint4*)(Ph + gp);
            *(uint4*)(STG + 8192 + sso)  = *(const uint4*)(Pl + gp);
            *(uint4*)(STG + 16384 + sso) = *(const uint4*)(Kth + gp);
            *(uint4*)(STG + 24576 + sso) = *(const uint4*)(Ktl + gp);
        }
        __syncthreads();

        // hoist U B-fragments for all 4 k-steps (shared by GEMM2b and GEMM3)
        uint32_t ufh[4][4], ufl[4][4];
        #pragma unroll
        for (int ks = 0; ks < 4; ++ks) {
            const int br = ks * 16 + lrow;
            const uint32_t bo = swz(br, wn * 2 + lhi);
            ldsm4t(ufh[ks], uh_u + bo);
            ldsm4t(ufl[ks], ul_u + bo);
        }

        // GEMM2b: accO += P·U
        #pragma unroll
        for (int ks = 0; ks < 4; ++ks) {
            uint32_t pfh[4], pfl[4];
            const int ar = wm * 16 + lrow;
            const uint32_t ao = swz(ar, ks * 2 + lhi);
            ldsm4(pfh, stg_u + ao);
            ldsm4(pfl, stg_u + 8192u + ao);
            #pragma unroll
            for (int nt = 0; nt < 2; ++nt) {
                mma16816(accO[nt], pfh, ufh[ks] + nt * 2);
                mma16816(accO[nt], pfh, ufl[ks] + nt * 2);
                mma16816(accO[nt], pfl, ufh[ks] + nt * 2);
            }
        }

        // O epilogue -> global
        #pragma unroll
        for (int nt = 0; nt < 2; ++nt) {
            const int r0 = wm * 16 + erow;
            const int cc = wn * 16 + nt * 8 + ecol;
            float2 w0; w0.x = accO[nt][0]; w0.y = accO[nt][1];
            float2 w1; w1.x = accO[nt][2]; w1.y = accO[nt][3];
            *(float2*)&g_o[(m0 + r0) * NV + h * DV_ + dv0 + cc]     = w0;
            *(float2*)&g_o[(m0 + r0 + 8) * NV + h * DV_ + dv0 + cc] = w1;
        }
        __syncthreads();   // retire P reads (T0/T1) before GEMM3 stores there

        // GEMM3: S += K^T · U, 4 kk-blocks, double-buffered halves
        for (int kkb = 0; kkb < 4; ++kkb) {
            float accS[2][4] = {};
            uint4 kf[2];
            if (kkb < 3) {
                const size_t gi = (size_t)((kkb + 1) * 64 + srow) * 64 + sch * 8;
                kf[0] = *(const uint4*)(Kth + gi);
                kf[1] = *(const uint4*)(Ktl + gi);
            }
            const uint32_t curH = stg_u + ((kkb & 1) ? 0u : 16384u);
            const uint32_t curL = stg_u + ((kkb & 1) ? 8192u : 24576u);
            #pragma unroll
            for (int ks = 0; ks < 4; ++ks) {
                uint32_t kfh[4], kfl[4];
                const int ar = wm * 16 + lrow;
                const uint32_t ao = swz(ar, ks * 2 + lhi);
                ldsm4(kfh, curH + ao);
                ldsm4(kfl, curL + ao);
                #pragma unroll
                for (int nt = 0; nt < 2; ++nt) {
                    mma16816(accS[nt], kfh, ufh[ks] + nt * 2);
                    mma16816(accS[nt], kfh, ufl[ks] + nt * 2);
                    mma16816(accS[nt], kfl, ufh[ks] + nt * 2);
                }
            }
            // S finalize: fp32 RMW + bf16 re-split for this 64-row block
            #pragma unroll
            for (int nt = 0; nt < 2; ++nt) {
                const int sr = kkb * 64 + wm * 16 + erow;
                const int sc = wn * 16 + nt * 8 + ecol;
                const float s0 = SF[sr * 68 + sc]           + accS[nt][0];
                const float s1 = SF[sr * 68 + sc + 1]       + accS[nt][1];
                const float s2 = SF[(sr + 8) * 68 + sc]     + accS[nt][2];
                const float s3 = SF[(sr + 8) * 68 + sc + 1] + accS[nt][3];
                SF[sr * 68 + sc]           = s0;
                SF[sr * 68 + sc + 1]       = s1;
                SF[(sr + 8) * 68 + sc]     = s2;
                SF[(sr + 8) * 68 + sc + 1] = s3;
                uint32_t hi, lo;
                split2(s0, s1, hi, lo);
                *(uint32_t*)(SH + swzb(sr, sc)) = hi;
                *(uint32_t*)(SL + swzb(sr, sc)) = lo;
                split2(s2, s3, hi, lo);
                *(uint32_t*)(SH + swzb(sr + 8, sc)) = hi;
                *(uint32_t*)(SL + swzb(sr + 8, sc)) = lo;
            }
            __syncthreads();
            if (kkb < 3) {
                char* oH = STG + ((kkb & 1) ? 16384 : 0);
                char* oL = STG + ((kkb & 1) ? 24576 : 8192);
                *(uint4*)(oH + sso) = kf[0];
                *(uint4*)(oL + sso) = kf[1];
                __syncthreads();
            }
        }
    }
}

// ---------------------------------------------------------------------------
// 6) per-head RMSNorm on g_o -> bf16 split g_oh/g_ol
// ---------------------------------------------------------------------------
__global__ void __launch_bounds__(256) rmsnorm_kernel(const float* __restrict__ w) {
    const int grp  = blockIdx.x * 8 + (threadIdx.x >> 5);
    const int lane = threadIdx.x & 31;
    const float* base = g_o + (size_t)grp * DV_;
    float4 v[4];
    float ss = 0.f;
    #pragma unroll
    for (int i = 0; i < 4; ++i) {
        v[i] = ((const float4*)base)[lane + 32 * i];
        ss += v[i].x * v[i].x + v[i].y * v[i].y + v[i].z * v[i].z + v[i].w * v[i].w;
    }
    #pragma unroll
    for (int off = 16; off > 0; off >>= 1) ss += __shfl_xor_sync(0xffffffffu, ss, off);
    const float rs = rsqrtf(ss * (1.0f / DV_) + 1e-5f);
    #pragma unroll
    for (int i = 0; i < 4; ++i) {
        const int idx = lane + 32 * i;
        const float4 wv = ((const float4*)w)[idx];
        const float4 o = make_float4(v[i].x * rs * wv.x, v[i].y * rs * wv.y,
                                     v[i].z * rs * wv.z, v[i].w * rs * wv.w);
        split_store4(o, g_oh, g_ol, (size_t)grp * DV_ + (size_t)idx * 4);
    }
}

// ---------------------------------------------------------------------------
// Launch
// ---------------------------------------------------------------------------
extern "C" void kernel_launch(void* const* d_in, const int* in_sizes, int n_in,
                              void* d_out, int out_size) {
    const float* x        = (const float*)d_in[0];
    const float* ln_w     = (const float*)d_in[1];
    const float* ln_b     = (const float*)d_in[2];
    const float* Wq       = (const float*)d_in[3];
    const float* Wk       = (const float*)d_in[4];
    const float* Wv       = (const float*)d_in[5];
    const float* Wb       = (const float*)d_in[6];
    const float* o_norm_w = (const float*)d_in[7];
    const float* Wo       = (const float*)d_in[8];
    float* out = (float*)d_out;

    cudaFuncSetAttribute(mma_gemm, cudaFuncAttributeMaxDynamicSharedMemorySize, MG_SMEM);
    cudaFuncSetAttribute(prep_kernel, cudaFuncAttributeMaxDynamicSharedMemorySize, P1_BYTES);
    cudaFuncSetAttribute(chunkscan_kernel, cudaFuncAttributeMaxDynamicSharedMemorySize, CS2_BYTES);

    __nv_bfloat16 *nh, *nl, *oh, *ol, *wqkvh, *wqkvl, *woh, *wol;
    cudaGetSymbolAddress((void**)&nh,    g_nh);
    cudaGetSymbolAddress((void**)&nl,    g_nl);
    cudaGetSymbolAddress((void**)&oh,    g_oh);
    cudaGetSymbolAddress((void**)&ol,    g_ol);
    cudaGetSymbolAddress((void**)&wqkvh, g_Wqkvt_h);
    cudaGetSymbolAddress((void**)&wqkvl, g_Wqkvt_l);
    cudaGetSymbolAddress((void**)&woh,   g_Wot_h);
    cudaGetSymbolAddress((void**)&wol,   g_Wot_l);
    float* gqkv;
    cudaGetSymbolAddress((void**)&gqkv, g_qkv);

    // 1) LayerNorm (+ bf16 split of normed, + fused beta)
    ln_kernel<<<M_, 256>>>(x, ln_w, ln_b, Wb);

    // 1b) all weight transposes+splits in one launch (6144 tiles)
    wtrans_all<<<6144, 256>>>(Wq, Wk, Wv, Wo);

    // 2) fused QKV projection (HMMA, silu fused, single launch N=4096)
    mma_gemm<<<dim3(NQKV / 128, M_ / 128), 256, MG_SMEM>>>(nh, nl, wqkvh, wqkvl, gqkv, nullptr, NQKV, D_, 1);

    // 5) chunked delta-rule (fused prep: l2norm q/k + W/Kt/Q/P + Uv)
    prep_kernel<<<NCH, 256, P1_BYTES>>>();
    chunkscan_kernel<<<B_ * H_ * 8, CST, CS2_BYTES>>>();

    // 6) RMSNorm (+ bf16 split of o)
    rmsnorm_kernel<<<(M_ * H_) / 8, 256>>>(o_norm_w);

    // 7) output projection + residual (HMMA)
    mma_gemm<<<dim3(D_ / 128, M_ / 128), 256, MG_SMEM>>>(oh, ol, woh, wol, out, x, D_, NV, 0);
}